// round 3
// baseline (speedup 1.0000x reference)
#include <cuda_runtime.h>
#include <cstdint>
#include <cstddef>

#define BB 8
#define SS 2048
#define DD 1024
// DC == DD == 1024, scale = 1/sqrt(1024) = 1/32

// ---------------- scratch (static device globals; no allocation) ----------------
__device__ int   g_labels[BB * SS];
__device__ int   g_chunk_start[BB * SS];
__device__ int   g_chunk_len[BB * SS];
__device__ int   g_nchunks[BB];
__device__ float g_chunk_emb[(size_t)BB * SS * DD];   // 64 MB
__device__ float g_q[(size_t)BB * SS * DD];           // 64 MB
__device__ float g_k[(size_t)BB * SS * DD];           // 64 MB
__device__ float g_v[(size_t)BB * SS * DD];           // 64 MB
__device__ float g_att[(size_t)BB * SS * DD];         // 64 MB
__device__ float g_scores[(size_t)BB * SS * SS];      // 128 MB

// ---------------- 1) labels = argmax(h @ W_lab + b_lab) ----------------
// one warp per token; W_lab is (D,4) row-major -> row k is a float4
__global__ void label_kernel(const float* __restrict__ h,
                             const float* __restrict__ Wlab,
                             const float* __restrict__ blab) {
    int tok  = blockIdx.x * (blockDim.x >> 5) + (threadIdx.x >> 5);
    int lane = threadIdx.x & 31;
    const float* hr = h + (size_t)tok * DD;
    float a0 = 0.f, a1 = 0.f, a2 = 0.f, a3 = 0.f;
    for (int k = lane; k < DD; k += 32) {
        float hv = hr[k];
        float4 w = *(const float4*)(Wlab + k * 4);
        a0 += hv * w.x; a1 += hv * w.y; a2 += hv * w.z; a3 += hv * w.w;
    }
    #pragma unroll
    for (int o = 16; o; o >>= 1) {
        a0 += __shfl_down_sync(0xffffffffu, a0, o);
        a1 += __shfl_down_sync(0xffffffffu, a1, o);
        a2 += __shfl_down_sync(0xffffffffu, a2, o);
        a3 += __shfl_down_sync(0xffffffffu, a3, o);
    }
    if (lane == 0) {
        float lg[4] = { a0 + blab[0], a1 + blab[1], a2 + blab[2], a3 + blab[3] };
        int best = 0; float bv = lg[0];
        #pragma unroll
        for (int j = 1; j < 4; j++) if (lg[j] > bv) { bv = lg[j]; best = j; }  // first-max tie-break
        g_labels[tok] = best;
    }
}

// ---------------- 2) sequential BIOS chunk scan (per batch row) ----------------
__global__ void scan_kernel() {
    __shared__ int lab[SS];
    int b = blockIdx.x;
    for (int s = threadIdx.x; s < SS; s += blockDim.x) lab[s] = g_labels[b * SS + s];
    __syncthreads();
    if (threadIdx.x == 0) {
        int* cs = g_chunk_start + b * SS;
        int* cl = g_chunk_len   + b * SS;
        bool open = false; int c = -1;
        for (int s = 0; s < SS; s++) {
            int l = lab[s];
            bool cont = (l == 1) && open;
            open = (l == 0) || cont;
            if (!cont) {
                if (c >= 0) cl[c] = s - cs[c];
                c++; cs[c] = s;
            }
        }
        cl[c] = SS - cs[c];
        g_nchunks[b] = c + 1;
    }
}

// ---------------- 3) per-chunk mean over contiguous token ranges ----------------
// grid (S, B); block 256; each thread owns 4 contiguous d-columns (float4)
__global__ void chunk_mean_kernel(const float* __restrict__ h) {
    int b = blockIdx.y, c = blockIdx.x;
    float* out = g_chunk_emb + ((size_t)b * SS + c) * DD;
    int d = threadIdx.x * 4;
    int nc = g_nchunks[b];
    if (c >= nc) {  // padded chunk rows must be deterministically zero
        *(float4*)(out + d) = make_float4(0.f, 0.f, 0.f, 0.f);
        return;
    }
    int st  = g_chunk_start[b * SS + c];
    int len = g_chunk_len[b * SS + c];
    const float* base = h + ((size_t)b * SS + st) * DD + d;
    float4 acc = make_float4(0.f, 0.f, 0.f, 0.f);
    for (int t = 0; t < len; t++) {
        float4 v = *(const float4*)(base + (size_t)t * DD);
        acc.x += v.x; acc.y += v.y; acc.z += v.z; acc.w += v.w;
    }
    float lf = (float)len;
    acc.x /= lf; acc.y /= lf; acc.z /= lf; acc.w /= lf;
    *(float4*)(out + d) = acc;
}

// ---------------- 4) tiled SGEMM: C = alpha * A @ op(B) + bias ----------------
// A: (M,K) row-major. TRANSB ? B:(N,K) row-major : B:(K,N) row-major. C:(M,N).
// BM=BN=128, BK=16, 256 threads, 8x8 microtile. All dims multiples of 128/16.
template <bool TRANSB>
__global__ __launch_bounds__(256)
void gemm_kernel(const float* __restrict__ A, const float* __restrict__ Bm,
                 const float* __restrict__ bias, float* __restrict__ C,
                 int M, int N, int K,
                 long long sA, long long sB, long long sC, float alpha) {
    constexpr int BM = 128, BN = 128, BK = 16;
    __shared__ float As[BK][BM];
    __shared__ float Bs[BK][BN];

    int bz = blockIdx.z;
    A  += (size_t)bz * sA;
    Bm += (size_t)bz * sB;
    C  += (size_t)bz * sC;

    int bm = blockIdx.y * BM, bn = blockIdx.x * BN;
    int tid = threadIdx.x;
    int tx = tid & 15, ty = tid >> 4;   // 16x16 thread grid

    float acc[8][8];
    #pragma unroll
    for (int i = 0; i < 8; i++)
        #pragma unroll
        for (int j = 0; j < 8; j++) acc[i][j] = 0.f;

    for (int k0 = 0; k0 < K; k0 += BK) {
        // load A tile (BM x BK) -> As transposed [BK][BM]
        #pragma unroll
        for (int i = 0; i < 2; i++) {
            int r  = (tid >> 2) + 64 * i;
            int c4 = (tid & 3);
            float4 v = *(const float4*)(A + (size_t)(bm + r) * K + k0 + c4 * 4);
            As[c4 * 4 + 0][r] = v.x; As[c4 * 4 + 1][r] = v.y;
            As[c4 * 4 + 2][r] = v.z; As[c4 * 4 + 3][r] = v.w;
        }
        // load B tile
        if (TRANSB) {
            #pragma unroll
            for (int i = 0; i < 2; i++) {
                int r  = (tid >> 2) + 64 * i;
                int c4 = (tid & 3);
                float4 v = *(const float4*)(Bm + (size_t)(bn + r) * K + k0 + c4 * 4);
                Bs[c4 * 4 + 0][r] = v.x; Bs[c4 * 4 + 1][r] = v.y;
                Bs[c4 * 4 + 2][r] = v.z; Bs[c4 * 4 + 3][r] = v.w;
            }
        } else {
            #pragma unroll
            for (int i = 0; i < 2; i++) {
                int r  = (tid >> 5) + 8 * i;
                int c4 = (tid & 31);
                float4 v = *(const float4*)(Bm + (size_t)(k0 + r) * N + bn + c4 * 4);
                *(float4*)&Bs[r][c4 * 4] = v;
            }
        }
        __syncthreads();

        #pragma unroll
        for (int kk = 0; kk < BK; kk++) {
            float ar[8], br[8];
            #pragma unroll
            for (int i = 0; i < 8; i++) ar[i] = As[kk][ty * 8 + i];
            #pragma unroll
            for (int j = 0; j < 8; j++) br[j] = Bs[kk][tx * 8 + j];
            #pragma unroll
            for (int i = 0; i < 8; i++)
                #pragma unroll
                for (int j = 0; j < 8; j++) acc[i][j] += ar[i] * br[j];
        }
        __syncthreads();
    }

    #pragma unroll
    for (int i = 0; i < 8; i++) {
        size_t row = (size_t)(bm + ty * 8 + i);
        #pragma unroll
        for (int j4 = 0; j4 < 2; j4++) {
            int col = bn + tx * 8 + j4 * 4;
            float4 o;
            o.x = acc[i][j4 * 4 + 0] * alpha;
            o.y = acc[i][j4 * 4 + 1] * alpha;
            o.z = acc[i][j4 * 4 + 2] * alpha;
            o.w = acc[i][j4 * 4 + 3] * alpha;
            if (bias) {
                float4 bv = *(const float4*)(bias + col);
                o.x += bv.x; o.y += bv.y; o.z += bv.z; o.w += bv.w;
            }
            *(float4*)(C + row * N + col) = o;
        }
    }
}

// ---------------- 5) masked row softmax over chunk axis ----------------
// one block (256 thr) per (b,s) row of g_scores; 2048 cols -> 8 per thread
__global__ void softmax_kernel() {
    __shared__ float red[8];
    int row = blockIdx.x;
    int b = row >> 11;               // / SS
    int nc = g_nchunks[b];
    float* sc = g_scores + (size_t)row * SS;

    const float NEG_INF = __int_as_float(0xff800000);
    float x[8];
    float m = NEG_INF;
    #pragma unroll
    for (int i = 0; i < 8; i++) {
        int c = threadIdx.x + i * 256;
        x[i] = (c < nc) ? sc[c] : NEG_INF;
        m = fmaxf(m, x[i]);
    }
    #pragma unroll
    for (int o = 16; o; o >>= 1) m = fmaxf(m, __shfl_xor_sync(0xffffffffu, m, o));
    if ((threadIdx.x & 31) == 0) red[threadIdx.x >> 5] = m;
    __syncthreads();
    m = red[0];
    #pragma unroll
    for (int i = 1; i < 8; i++) m = fmaxf(m, red[i]);
    __syncthreads();

    float s = 0.f;
    #pragma unroll
    for (int i = 0; i < 8; i++) {
        int c = threadIdx.x + i * 256;
        x[i] = (c < nc) ? expf(x[i] - m) : 0.f;
        s += x[i];
    }
    #pragma unroll
    for (int o = 16; o; o >>= 1) s += __shfl_xor_sync(0xffffffffu, s, o);
    if ((threadIdx.x & 31) == 0) red[threadIdx.x >> 5] = s;
    __syncthreads();
    s = 0.f;
    #pragma unroll
    for (int i = 0; i < 8; i++) s += red[i];
    float inv = 1.f / s;

    #pragma unroll
    for (int i = 0; i < 8; i++) {
        int c = threadIdx.x + i * 256;
        sc[c] = x[i] * inv;
    }
}

// ---------------- host side ----------------
static void launch_gemm(bool transB, const float* A, const float* Bm, const float* bias,
                        float* C, int M, int N, int K,
                        long long sA, long long sB, long long sC, int batch, float alpha) {
    dim3 grid(N / 128, M / 128, batch), block(256);
    if (transB)
        gemm_kernel<true><<<grid, block>>>(A, Bm, bias, C, M, N, K, sA, sB, sC, alpha);
    else
        gemm_kernel<false><<<grid, block>>>(A, Bm, bias, C, M, N, K, sA, sB, sC, alpha);
}

extern "C" void kernel_launch(void* const* d_in, const int* in_sizes, int n_in,
                              void* d_out, int out_size) {
    (void)in_sizes; (void)n_in; (void)out_size;
    const float* h    = (const float*)d_in[0];
    const float* Wlab = (const float*)d_in[1];
    const float* blab = (const float*)d_in[2];
    const float* Wq   = (const float*)d_in[3];
    const float* bq   = (const float*)d_in[4];
    const float* Wk   = (const float*)d_in[5];
    const float* bk   = (const float*)d_in[6];
    const float* Wv   = (const float*)d_in[7];
    const float* bv   = (const float*)d_in[8];
    const float* Wo   = (const float*)d_in[9];
    const float* bo   = (const float*)d_in[10];
    float* out = (float*)d_out;

    float *ce, *q, *k, *v, *att, *sc;
    cudaGetSymbolAddress((void**)&ce,  g_chunk_emb);
    cudaGetSymbolAddress((void**)&q,   g_q);
    cudaGetSymbolAddress((void**)&k,   g_k);
    cudaGetSymbolAddress((void**)&v,   g_v);
    cudaGetSymbolAddress((void**)&att, g_att);
    cudaGetSymbolAddress((void**)&sc,  g_scores);

    const int M = BB * SS;                      // 16384
    const long long sQ = (long long)SS * DD;    // per-batch q/k/v stride
    const long long sS = (long long)SS * SS;    // per-batch scores stride

    label_kernel<<<M / 8, 256>>>(h, Wlab, blab);
    scan_kernel<<<BB, 256>>>();
    chunk_mean_kernel<<<dim3(SS, BB), 256>>>(h);

    launch_gemm(false, h,  Wq, bq, q, M, DD, DD, 0, 0, 0, 1, 1.f);   // q = h@Wq + bq
    launch_gemm(false, ce, Wk, bk, k, M, DD, DD, 0, 0, 0, 1, 1.f);   // k = ce@Wk + bk
    launch_gemm(false, ce, Wv, bv, v, M, DD, DD, 0, 0, 0, 1, 1.f);   // v = ce@Wv + bv

    // scores[b] = (q[b] @ k[b]^T) / 32   (NT, batched)
    launch_gemm(true, q, k, nullptr, sc, SS, SS, DD, sQ, sQ, sS, BB, 0.03125f);

    softmax_kernel<<<M, 256>>>();

    // attended[b] = attn[b] @ v[b]       (NN, batched; masked cols are exactly 0)
    launch_gemm(false, sc, v, nullptr, att, SS, DD, SS, sS, sQ, sQ, BB, 1.f);

    launch_gemm(false, att, Wo, bo, out, M, DD, DD, 0, 0, 0, 1, 1.f); // out = att@Wo + bo
}

// round 4
// speedup vs baseline: 1.7224x; 1.7224x over previous
#include <cuda_runtime.h>
#include <cuda_bf16.h>
#include <cstdint>
#include <cstddef>

#define BB 8
#define SS 2048
#define DD 1024
// DC == DD == 1024, scale = 1/sqrt(1024) = 1/32

// ---------------- scratch (static device globals; no allocation) ----------------
__device__ int   g_labels[BB * SS];
__device__ int   g_chunk_start[BB * SS];
__device__ int   g_chunk_len[BB * SS];
__device__ int   g_nchunks[BB];
__device__ float g_chunk_emb[(size_t)BB * SS * DD];   // 64 MB
__device__ float g_q[(size_t)BB * SS * DD];           // 64 MB
__device__ float g_k[(size_t)BB * SS * DD];           // 64 MB
__device__ float g_v[(size_t)BB * SS * DD];           // 64 MB
__device__ float g_att[(size_t)BB * SS * DD];         // 64 MB
__device__ float g_scores[(size_t)BB * SS * SS];      // 128 MB

// ---------------- 1) labels = argmax(h @ W_lab + b_lab) ---------------- (fp32: argmax cliff)
__global__ void label_kernel(const float* __restrict__ h,
                             const float* __restrict__ Wlab,
                             const float* __restrict__ blab) {
    int tok  = blockIdx.x * (blockDim.x >> 5) + (threadIdx.x >> 5);
    int lane = threadIdx.x & 31;
    const float* hr = h + (size_t)tok * DD;
    float a0 = 0.f, a1 = 0.f, a2 = 0.f, a3 = 0.f;
    for (int k = lane; k < DD; k += 32) {
        float hv = hr[k];
        float4 w = *(const float4*)(Wlab + k * 4);
        a0 += hv * w.x; a1 += hv * w.y; a2 += hv * w.z; a3 += hv * w.w;
    }
    #pragma unroll
    for (int o = 16; o; o >>= 1) {
        a0 += __shfl_down_sync(0xffffffffu, a0, o);
        a1 += __shfl_down_sync(0xffffffffu, a1, o);
        a2 += __shfl_down_sync(0xffffffffu, a2, o);
        a3 += __shfl_down_sync(0xffffffffu, a3, o);
    }
    if (lane == 0) {
        float lg[4] = { a0 + blab[0], a1 + blab[1], a2 + blab[2], a3 + blab[3] };
        int best = 0; float bv = lg[0];
        #pragma unroll
        for (int j = 1; j < 4; j++) if (lg[j] > bv) { bv = lg[j]; best = j; }
        g_labels[tok] = best;
    }
}

// ---------------- 2) sequential BIOS chunk scan ----------------
__global__ void scan_kernel() {
    __shared__ int lab[SS];
    int b = blockIdx.x;
    for (int s = threadIdx.x; s < SS; s += blockDim.x) lab[s] = g_labels[b * SS + s];
    __syncthreads();
    if (threadIdx.x == 0) {
        int* cs = g_chunk_start + b * SS;
        int* cl = g_chunk_len   + b * SS;
        bool open = false; int c = -1;
        for (int s = 0; s < SS; s++) {
            int l = lab[s];
            bool cont = (l == 1) && open;
            open = (l == 0) || cont;
            if (!cont) {
                if (c >= 0) cl[c] = s - cs[c];
                c++; cs[c] = s;
            }
        }
        cl[c] = SS - cs[c];
        g_nchunks[b] = c + 1;
    }
}

// ---------------- 3) per-chunk mean over contiguous token ranges ----------------
__global__ void chunk_mean_kernel(const float* __restrict__ h) {
    int b = blockIdx.y, c = blockIdx.x;
    float* out = g_chunk_emb + ((size_t)b * SS + c) * DD;
    int d = threadIdx.x * 4;
    int nc = g_nchunks[b];
    if (c >= nc) {
        *(float4*)(out + d) = make_float4(0.f, 0.f, 0.f, 0.f);
        return;
    }
    int st  = g_chunk_start[b * SS + c];
    int len = g_chunk_len[b * SS + c];
    const float* base = h + ((size_t)b * SS + st) * DD + d;
    float4 acc = make_float4(0.f, 0.f, 0.f, 0.f);
    for (int t = 0; t < len; t++) {
        float4 v = *(const float4*)(base + (size_t)t * DD);
        acc.x += v.x; acc.y += v.y; acc.z += v.z; acc.w += v.w;
    }
    float lf = (float)len;
    acc.x /= lf; acc.y /= lf; acc.z /= lf; acc.w /= lf;
    *(float4*)(out + d) = acc;
}

// ---------------- 4) tensor-core GEMM: bf16x3 error-compensated ----------------
// C = alpha * A @ op(B) + bias. fp32 in/out; on-the-fly split x = hi + lo (bf16),
// accumulate hi*hi + hi*lo + lo*hi in fp32 via mma.sync.m16n8k16.
// Tiles: BM=BN=128, BK=32. 256 threads = 8 warps (2 x 4), warp tile 64x32.
#define MMA_BF16(d, a, b0v, b1v) \
    asm volatile("mma.sync.aligned.m16n8k16.row.col.f32.bf16.bf16.f32 " \
                 "{%0,%1,%2,%3}, {%4,%5,%6,%7}, {%8,%9}, {%0,%1,%2,%3};" \
                 : "+f"(d[0]), "+f"(d[1]), "+f"(d[2]), "+f"(d[3]) \
                 : "r"(a[0]), "r"(a[1]), "r"(a[2]), "r"(a[3]), "r"(b0v), "r"(b1v))

__device__ __forceinline__ void split_bf16(float x, __nv_bfloat16& hi, __nv_bfloat16& lo) {
    hi = __float2bfloat16(x);
    lo = __float2bfloat16(x - __bfloat162float(hi));
}

template <bool TRANSB>
__global__ __launch_bounds__(256)
void gemm_tc(const float* __restrict__ A, const float* __restrict__ Bm,
             const float* __restrict__ bias, float* __restrict__ C,
             int M, int N, int K,
             long long sA, long long sB, long long sC, float alpha) {
    constexpr int BM = 128, BN = 128, BK = 32;
    constexpr int LDA  = 40;   // padded k-stride for [m][k] tiles (conflict-free frags)
    constexpr int LDKN = 136;  // padded n-stride for [k][n] tile (NN path)

    __shared__ __nv_bfloat16 Ah[BM][LDA];
    __shared__ __nv_bfloat16 Al[BM][LDA];
    __shared__ __nv_bfloat16 Bh[TRANSB ? (BN * LDA) : (BK * LDKN)];
    __shared__ __nv_bfloat16 Bl[TRANSB ? (BN * LDA) : (BK * LDKN)];

    int bz = blockIdx.z;
    A  += (size_t)bz * sA;
    Bm += (size_t)bz * sB;
    C  += (size_t)bz * sC;

    const int bm = blockIdx.y * BM, bn = blockIdx.x * BN;
    const int tid  = threadIdx.x;
    const int wid  = tid >> 5;
    const int lane = tid & 31;
    const int lr = lane >> 2, lc = lane & 3;
    const int mw = (wid & 1) * 64;   // warp m-offset
    const int nw = (wid >> 1) * 32;  // warp n-offset

    float acc[4][4][4];
    #pragma unroll
    for (int mi = 0; mi < 4; mi++)
        #pragma unroll
        for (int ni = 0; ni < 4; ni++)
            #pragma unroll
            for (int r = 0; r < 4; r++) acc[mi][ni][r] = 0.f;

    for (int k0 = 0; k0 < K; k0 += BK) {
        __syncthreads();  // prior compute done before overwrite
        // ---- load A tile (BM x BK), split, store [m][k] ----
        #pragma unroll
        for (int i = 0; i < 4; i++) {
            int f = tid + 256 * i;            // 1024 float4s
            int r = f >> 3, c4 = f & 7;
            float4 v = *(const float4*)(A + (size_t)(bm + r) * K + k0 + c4 * 4);
            __nv_bfloat16 h0, h1, h2, h3, l0, l1, l2, l3;
            split_bf16(v.x, h0, l0); split_bf16(v.y, h1, l1);
            split_bf16(v.z, h2, l2); split_bf16(v.w, h3, l3);
            *(__nv_bfloat162*)&Ah[r][c4 * 4 + 0] = __nv_bfloat162(h0, h1);
            *(__nv_bfloat162*)&Ah[r][c4 * 4 + 2] = __nv_bfloat162(h2, h3);
            *(__nv_bfloat162*)&Al[r][c4 * 4 + 0] = __nv_bfloat162(l0, l1);
            *(__nv_bfloat162*)&Al[r][c4 * 4 + 2] = __nv_bfloat162(l2, l3);
        }
        // ---- load B tile ----
        if (TRANSB) {
            // B is (N,K) row-major: tile (BN x BK) -> [n][k], same as A
            #pragma unroll
            for (int i = 0; i < 4; i++) {
                int f = tid + 256 * i;
                int r = f >> 3, c4 = f & 7;
                float4 v = *(const float4*)(Bm + (size_t)(bn + r) * K + k0 + c4 * 4);
                __nv_bfloat16 h0, h1, h2, h3, l0, l1, l2, l3;
                split_bf16(v.x, h0, l0); split_bf16(v.y, h1, l1);
                split_bf16(v.z, h2, l2); split_bf16(v.w, h3, l3);
                *(__nv_bfloat162*)&Bh[r * LDA + c4 * 4 + 0] = __nv_bfloat162(h0, h1);
                *(__nv_bfloat162*)&Bh[r * LDA + c4 * 4 + 2] = __nv_bfloat162(h2, h3);
                *(__nv_bfloat162*)&Bl[r * LDA + c4 * 4 + 0] = __nv_bfloat162(l0, l1);
                *(__nv_bfloat162*)&Bl[r * LDA + c4 * 4 + 2] = __nv_bfloat162(l2, l3);
            }
        } else {
            // B is (K,N) row-major: tile (BK x BN) -> [k][n] (coalesced, no transpose)
            #pragma unroll
            for (int i = 0; i < 4; i++) {
                int f = tid + 256 * i;
                int kr = f >> 5, c4 = f & 31;
                float4 v = *(const float4*)(Bm + (size_t)(k0 + kr) * N + bn + c4 * 4);
                __nv_bfloat16 h0, h1, h2, h3, l0, l1, l2, l3;
                split_bf16(v.x, h0, l0); split_bf16(v.y, h1, l1);
                split_bf16(v.z, h2, l2); split_bf16(v.w, h3, l3);
                *(__nv_bfloat162*)&Bh[kr * LDKN + c4 * 4 + 0] = __nv_bfloat162(h0, h1);
                *(__nv_bfloat162*)&Bh[kr * LDKN + c4 * 4 + 2] = __nv_bfloat162(h2, h3);
                *(__nv_bfloat162*)&Bl[kr * LDKN + c4 * 4 + 0] = __nv_bfloat162(l0, l1);
                *(__nv_bfloat162*)&Bl[kr * LDKN + c4 * 4 + 2] = __nv_bfloat162(l2, l3);
            }
        }
        __syncthreads();

        // ---- compute: 2 k-steps of m16n8k16 ----
        #pragma unroll
        for (int ks = 0; ks < 2; ks++) {
            const int kk = ks * 16;
            uint32_t ah[4][4], al[4][4], bhf[4][2], blf[4][2];
            #pragma unroll
            for (int mi = 0; mi < 4; mi++) {
                int r0 = mw + mi * 16 + lr;
                int c0 = kk + lc * 2;
                ah[mi][0] = *(const uint32_t*)&Ah[r0][c0];
                ah[mi][1] = *(const uint32_t*)&Ah[r0 + 8][c0];
                ah[mi][2] = *(const uint32_t*)&Ah[r0][c0 + 8];
                ah[mi][3] = *(const uint32_t*)&Ah[r0 + 8][c0 + 8];
                al[mi][0] = *(const uint32_t*)&Al[r0][c0];
                al[mi][1] = *(const uint32_t*)&Al[r0 + 8][c0];
                al[mi][2] = *(const uint32_t*)&Al[r0][c0 + 8];
                al[mi][3] = *(const uint32_t*)&Al[r0 + 8][c0 + 8];
            }
            #pragma unroll
            for (int ni = 0; ni < 4; ni++) {
                int n0 = nw + ni * 8 + lr;
                if (TRANSB) {
                    int c0 = kk + lc * 2;
                    bhf[ni][0] = *(const uint32_t*)&Bh[n0 * LDA + c0];
                    bhf[ni][1] = *(const uint32_t*)&Bh[n0 * LDA + c0 + 8];
                    blf[ni][0] = *(const uint32_t*)&Bl[n0 * LDA + c0];
                    blf[ni][1] = *(const uint32_t*)&Bl[n0 * LDA + c0 + 8];
                } else {
                    int kb = kk + lc * 2;
                    uint32_t x0 = *(const unsigned short*)&Bh[kb * LDKN + n0];
                    uint32_t x1 = *(const unsigned short*)&Bh[(kb + 1) * LDKN + n0];
                    uint32_t x2 = *(const unsigned short*)&Bh[(kb + 8) * LDKN + n0];
                    uint32_t x3 = *(const unsigned short*)&Bh[(kb + 9) * LDKN + n0];
                    bhf[ni][0] = x0 | (x1 << 16);
                    bhf[ni][1] = x2 | (x3 << 16);
                    uint32_t y0 = *(const unsigned short*)&Bl[kb * LDKN + n0];
                    uint32_t y1 = *(const unsigned short*)&Bl[(kb + 1) * LDKN + n0];
                    uint32_t y2 = *(const unsigned short*)&Bl[(kb + 8) * LDKN + n0];
                    uint32_t y3 = *(const unsigned short*)&Bl[(kb + 9) * LDKN + n0];
                    blf[ni][0] = y0 | (y1 << 16);
                    blf[ni][1] = y2 | (y3 << 16);
                }
            }
            #pragma unroll
            for (int mi = 0; mi < 4; mi++)
                #pragma unroll
                for (int ni = 0; ni < 4; ni++) {
                    MMA_BF16(acc[mi][ni], ah[mi], bhf[ni][0], bhf[ni][1]);  // hi*hi
                    MMA_BF16(acc[mi][ni], ah[mi], blf[ni][0], blf[ni][1]);  // hi*lo
                    MMA_BF16(acc[mi][ni], al[mi], bhf[ni][0], bhf[ni][1]);  // lo*hi
                }
        }
    }

    // ---- epilogue: alpha + bias, fp32 stores ----
    #pragma unroll
    for (int mi = 0; mi < 4; mi++) {
        int row = bm + mw + mi * 16 + lr;
        #pragma unroll
        for (int ni = 0; ni < 4; ni++) {
            int col = bn + nw + ni * 8 + lc * 2;
            float o0 = acc[mi][ni][0] * alpha;
            float o1 = acc[mi][ni][1] * alpha;
            float o2 = acc[mi][ni][2] * alpha;
            float o3 = acc[mi][ni][3] * alpha;
            if (bias) {
                float b0 = bias[col], b1 = bias[col + 1];
                o0 += b0; o1 += b1; o2 += b0; o3 += b1;
            }
            *(float2*)(C + (size_t)row * N + col)       = make_float2(o0, o1);
            *(float2*)(C + (size_t)(row + 8) * N + col) = make_float2(o2, o3);
        }
    }
}

// ---------------- 5) masked row softmax over chunk axis ----------------
__global__ void softmax_kernel() {
    __shared__ float red[8];
    int row = blockIdx.x;
    int b = row >> 11;
    int nc = g_nchunks[b];
    float* sc = g_scores + (size_t)row * SS;

    const float NEG_INF = __int_as_float(0xff800000);
    float x[8];
    float m = NEG_INF;
    #pragma unroll
    for (int i = 0; i < 8; i++) {
        int c = threadIdx.x + i * 256;
        x[i] = (c < nc) ? sc[c] : NEG_INF;
        m = fmaxf(m, x[i]);
    }
    #pragma unroll
    for (int o = 16; o; o >>= 1) m = fmaxf(m, __shfl_xor_sync(0xffffffffu, m, o));
    if ((threadIdx.x & 31) == 0) red[threadIdx.x >> 5] = m;
    __syncthreads();
    m = red[0];
    #pragma unroll
    for (int i = 1; i < 8; i++) m = fmaxf(m, red[i]);
    __syncthreads();

    float s = 0.f;
    #pragma unroll
    for (int i = 0; i < 8; i++) {
        int c = threadIdx.x + i * 256;
        x[i] = (c < nc) ? expf(x[i] - m) : 0.f;
        s += x[i];
    }
    #pragma unroll
    for (int o = 16; o; o >>= 1) s += __shfl_xor_sync(0xffffffffu, s, o);
    if ((threadIdx.x & 31) == 0) red[threadIdx.x >> 5] = s;
    __syncthreads();
    s = 0.f;
    #pragma unroll
    for (int i = 0; i < 8; i++) s += red[i];
    float inv = 1.f / s;

    #pragma unroll
    for (int i = 0; i < 8; i++) {
        int c = threadIdx.x + i * 256;
        sc[c] = x[i] * inv;
    }
}

// ---------------- host side ----------------
static void launch_gemm(bool transB, const float* A, const float* Bm, const float* bias,
                        float* C, int M, int N, int K,
                        long long sA, long long sB, long long sC, int batch, float alpha) {
    dim3 grid(N / 128, M / 128, batch), block(256);
    if (transB)
        gemm_tc<true><<<grid, block>>>(A, Bm, bias, C, M, N, K, sA, sB, sC, alpha);
    else
        gemm_tc<false><<<grid, block>>>(A, Bm, bias, C, M, N, K, sA, sB, sC, alpha);
}

extern "C" void kernel_launch(void* const* d_in, const int* in_sizes, int n_in,
                              void* d_out, int out_size) {
    (void)in_sizes; (void)n_in; (void)out_size;
    const float* h    = (const float*)d_in[0];
    const float* Wlab = (const float*)d_in[1];
    const float* blab = (const float*)d_in[2];
    const float* Wq   = (const float*)d_in[3];
    const float* bq   = (const float*)d_in[4];
    const float* Wk   = (const float*)d_in[5];
    const float* bk   = (const float*)d_in[6];
    const float* Wv   = (const float*)d_in[7];
    const float* bv   = (const float*)d_in[8];
    const float* Wo   = (const float*)d_in[9];
    const float* bo   = (const float*)d_in[10];
    float* out = (float*)d_out;

    float *ce, *q, *k, *v, *att, *sc;
    cudaGetSymbolAddress((void**)&ce,  g_chunk_emb);
    cudaGetSymbolAddress((void**)&q,   g_q);
    cudaGetSymbolAddress((void**)&k,   g_k);
    cudaGetSymbolAddress((void**)&v,   g_v);
    cudaGetSymbolAddress((void**)&att, g_att);
    cudaGetSymbolAddress((void**)&sc,  g_scores);

    const int M = BB * SS;                      // 16384
    const long long sQ = (long long)SS * DD;
    const long long sS = (long long)SS * SS;

    label_kernel<<<M / 8, 256>>>(h, Wlab, blab);
    scan_kernel<<<BB, 256>>>();
    chunk_mean_kernel<<<dim3(SS, BB), 256>>>(h);

    launch_gemm(false, h,  Wq, bq, q, M, DD, DD, 0, 0, 0, 1, 1.f);   // q = h@Wq + bq
    launch_gemm(false, ce, Wk, bk, k, M, DD, DD, 0, 0, 0, 1, 1.f);   // k = ce@Wk + bk
    launch_gemm(false, ce, Wv, bv, v, M, DD, DD, 0, 0, 0, 1, 1.f);   // v = ce@Wv + bv

    // scores[b] = (q[b] @ k[b]^T) / 32   (NT, batched)
    launch_gemm(true, q, k, nullptr, sc, SS, SS, DD, sQ, sQ, sS, BB, 0.03125f);

    softmax_kernel<<<M, 256>>>();

    // attended[b] = attn[b] @ v[b]       (NN, batched; masked cols exactly 0)
    launch_gemm(false, sc, v, nullptr, att, SS, DD, SS, sS, sQ, sQ, BB, 1.f);

    launch_gemm(false, att, Wo, bo, out, M, DD, DD, 0, 0, 0, 1, 1.f); // out = att@Wo + bo
}

// round 5
// speedup vs baseline: 2.2589x; 1.3115x over previous
#include <cuda_runtime.h>
#include <cuda_bf16.h>
#include <cstdint>
#include <cstddef>

#define BB 8
#define SS 2048
#define DD 1024
// DC == DD == 1024, scale = 1/sqrt(1024) = 1/32

typedef __nv_bfloat16 bf16;
typedef __nv_bfloat162 bf162;

// ---------------- scratch (static device globals; no allocation) ----------------
__device__ int   g_labels[BB * SS];
__device__ int   g_chunk_start[BB * SS];
__device__ int   g_chunk_len[BB * SS];
__device__ int   g_nchunks[BB];

__device__ bf16  g_h_hi[(size_t)BB * SS * DD],  g_h_lo[(size_t)BB * SS * DD];
__device__ bf16  g_ce_hi[(size_t)BB * SS * DD], g_ce_lo[(size_t)BB * SS * DD];
__device__ bf16  g_wqT_hi[DD * DD], g_wqT_lo[DD * DD];
__device__ bf16  g_wkT_hi[DD * DD], g_wkT_lo[DD * DD];
__device__ bf16  g_wvT_hi[DD * DD], g_wvT_lo[DD * DD];
__device__ bf16  g_woT_hi[DD * DD], g_woT_lo[DD * DD];
__device__ bf16  g_q_hi[(size_t)BB * SS * DD],  g_q_lo[(size_t)BB * SS * DD];
__device__ bf16  g_k_hi[(size_t)BB * SS * DD],  g_k_lo[(size_t)BB * SS * DD];
__device__ bf16  g_v_hi[(size_t)BB * SS * DD],  g_v_lo[(size_t)BB * SS * DD];
__device__ bf16  g_vT_hi[(size_t)BB * DD * SS], g_vT_lo[(size_t)BB * DD * SS];
__device__ bf16  g_p_hi[(size_t)BB * SS * SS],  g_p_lo[(size_t)BB * SS * SS];
__device__ bf16  g_att_hi[(size_t)BB * SS * DD], g_att_lo[(size_t)BB * SS * DD];
__device__ float g_scores[(size_t)BB * SS * SS];      // 128 MB

__device__ __forceinline__ void split_bf16(float x, bf16& hi, bf16& lo) {
    hi = __float2bfloat16(x);
    lo = __float2bfloat16(x - __bfloat162float(hi));
}

// ---------------- 0) fp32 -> hi/lo split (for h) ----------------
__global__ void split4_kernel(const float* __restrict__ src,
                              bf16* __restrict__ hi, bf16* __restrict__ lo) {
    size_t i = (size_t)blockIdx.x * blockDim.x + threadIdx.x;  // float4 index
    float4 v = ((const float4*)src)[i];
    bf16 h0,h1,h2,h3,l0,l1,l2,l3;
    split_bf16(v.x,h0,l0); split_bf16(v.y,h1,l1);
    split_bf16(v.z,h2,l2); split_bf16(v.w,h3,l3);
    ((bf162*)hi)[i*2+0] = bf162(h0,h1); ((bf162*)hi)[i*2+1] = bf162(h2,h3);
    ((bf162*)lo)[i*2+0] = bf162(l0,l1); ((bf162*)lo)[i*2+1] = bf162(l2,l3);
}

// ---------------- 0b) weight transpose + split: W(K,N) -> WT(N,K) hi/lo ----------------
__global__ void wtrans_kernel(const float* __restrict__ W,
                              bf16* __restrict__ Th, bf16* __restrict__ Tl) {
    __shared__ float t[32][33];
    int tx = threadIdx.x, ty = threadIdx.y;          // (32, 8)
    int x = blockIdx.x * 32 + tx, y = blockIdx.y * 32 + ty;
    #pragma unroll
    for (int k = 0; k < 4; k++) t[ty + 8*k][tx] = W[(size_t)(y + 8*k) * DD + x];
    __syncthreads();
    int x2 = blockIdx.y * 32 + tx, y2 = blockIdx.x * 32 + ty;
    #pragma unroll
    for (int k = 0; k < 4; k++) {
        float v = t[tx][ty + 8*k];
        bf16 h, l; split_bf16(v, h, l);
        Th[(size_t)(y2 + 8*k) * DD + x2] = h;
        Tl[(size_t)(y2 + 8*k) * DD + x2] = l;
    }
}

// ---------------- 0c) bf16 pair transpose: v(S,D) -> vT(D,S), per batch ----------------
__global__ void vtrans_kernel() {
    __shared__ bf16 th[32][34], tl[32][34];
    int b = blockIdx.z;
    int tx = threadIdx.x, ty = threadIdx.y;          // (32, 8)
    const bf16* vh = g_v_hi + (size_t)b * SS * DD;
    const bf16* vl = g_v_lo + (size_t)b * SS * DD;
    bf16* oh = g_vT_hi + (size_t)b * DD * SS;
    bf16* ol = g_vT_lo + (size_t)b * DD * SS;
    int d0 = blockIdx.x * 32, s0 = blockIdx.y * 32;
    #pragma unroll
    for (int k = 0; k < 4; k++) {
        th[ty + 8*k][tx] = vh[(size_t)(s0 + ty + 8*k) * DD + d0 + tx];
        tl[ty + 8*k][tx] = vl[(size_t)(s0 + ty + 8*k) * DD + d0 + tx];
    }
    __syncthreads();
    #pragma unroll
    for (int k = 0; k < 4; k++) {
        oh[(size_t)(d0 + ty + 8*k) * SS + s0 + tx] = th[tx][ty + 8*k];
        ol[(size_t)(d0 + ty + 8*k) * SS + s0 + tx] = tl[tx][ty + 8*k];
    }
}

// ---------------- 1) labels = argmax(h @ W_lab + b_lab) (fp32: argmax cliff) ----------------
__global__ void label_kernel(const float* __restrict__ h,
                             const float* __restrict__ Wlab,
                             const float* __restrict__ blab) {
    int tok  = blockIdx.x * (blockDim.x >> 5) + (threadIdx.x >> 5);
    int lane = threadIdx.x & 31;
    const float* hr = h + (size_t)tok * DD;
    float a0 = 0.f, a1 = 0.f, a2 = 0.f, a3 = 0.f;
    for (int k = lane; k < DD; k += 32) {
        float hv = hr[k];
        float4 w = *(const float4*)(Wlab + k * 4);
        a0 += hv * w.x; a1 += hv * w.y; a2 += hv * w.z; a3 += hv * w.w;
    }
    #pragma unroll
    for (int o = 16; o; o >>= 1) {
        a0 += __shfl_down_sync(0xffffffffu, a0, o);
        a1 += __shfl_down_sync(0xffffffffu, a1, o);
        a2 += __shfl_down_sync(0xffffffffu, a2, o);
        a3 += __shfl_down_sync(0xffffffffu, a3, o);
    }
    if (lane == 0) {
        float lg[4] = { a0 + blab[0], a1 + blab[1], a2 + blab[2], a3 + blab[3] };
        int best = 0; float bv = lg[0];
        #pragma unroll
        for (int j = 1; j < 4; j++) if (lg[j] > bv) { bv = lg[j]; best = j; }
        g_labels[tok] = best;
    }
}

// ---------------- 2) sequential BIOS chunk scan ----------------
__global__ void scan_kernel() {
    __shared__ int lab[SS];
    int b = blockIdx.x;
    for (int s = threadIdx.x; s < SS; s += blockDim.x) lab[s] = g_labels[b * SS + s];
    __syncthreads();
    if (threadIdx.x == 0) {
        int* cs = g_chunk_start + b * SS;
        int* cl = g_chunk_len   + b * SS;
        bool open = false; int c = -1;
        for (int s = 0; s < SS; s++) {
            int l = lab[s];
            bool cont = (l == 1) && open;
            open = (l == 0) || cont;
            if (!cont) {
                if (c >= 0) cl[c] = s - cs[c];
                c++; cs[c] = s;
            }
        }
        cl[c] = SS - cs[c];
        g_nchunks[b] = c + 1;
    }
}

// ---------------- 3) per-chunk mean (contiguous ranges) -> split hi/lo ----------------
__global__ void chunk_mean_kernel(const float* __restrict__ h) {
    int b = blockIdx.y, c = blockIdx.x;
    size_t base_o = ((size_t)b * SS + c) * DD;
    int d = threadIdx.x * 4;
    int nc = g_nchunks[b];
    float4 acc = make_float4(0.f, 0.f, 0.f, 0.f);
    if (c < nc) {
        int st  = g_chunk_start[b * SS + c];
        int len = g_chunk_len[b * SS + c];
        const float* base = h + ((size_t)b * SS + st) * DD + d;
        for (int t = 0; t < len; t++) {
            float4 v = *(const float4*)(base + (size_t)t * DD);
            acc.x += v.x; acc.y += v.y; acc.z += v.z; acc.w += v.w;
        }
        float inv = 1.f / (float)len;
        acc.x *= inv; acc.y *= inv; acc.z *= inv; acc.w *= inv;
    }
    bf16 h0,h1,h2,h3,l0,l1,l2,l3;
    split_bf16(acc.x,h0,l0); split_bf16(acc.y,h1,l1);
    split_bf16(acc.z,h2,l2); split_bf16(acc.w,h3,l3);
    *(bf162*)(g_ce_hi + base_o + d)     = bf162(h0,h1);
    *(bf162*)(g_ce_hi + base_o + d + 2) = bf162(h2,h3);
    *(bf162*)(g_ce_lo + base_o + d)     = bf162(l0,l1);
    *(bf162*)(g_ce_lo + base_o + d + 2) = bf162(l2,l3);
}

// ---------------- 4) NT tensor-core GEMM, bf16x3, cp.async 3-stage pipeline ----------------
// C(M,N) = alpha * A(M,K) @ B(N,K)^T [+ bias]; A,B pre-split hi/lo bf16 row-major.
// MODE 0: write fp32 to Cf.  MODE 1: split and write bf16 hi/lo to Ch/Cl.
// BM=BN=128, BK=32, 256 thr = 8 warps (2m x 4n), warp tile 64x32.
// smem per stage 32KB: A[128 rows][64 halves] (hi 0..31 | lo 32..63), B same.
// 128B rows, XOR-16B swizzle: chunk' = chunk ^ (row & 7)  -> conflict-free lds.32.

#define MMA_BF16(d, a, b0v, b1v) \
    asm volatile("mma.sync.aligned.m16n8k16.row.col.f32.bf16.bf16.f32 " \
                 "{%0,%1,%2,%3}, {%4,%5,%6,%7}, {%8,%9}, {%0,%1,%2,%3};" \
                 : "+f"(d[0]), "+f"(d[1]), "+f"(d[2]), "+f"(d[3]) \
                 : "r"(a[0]), "r"(a[1]), "r"(a[2]), "r"(a[3]), "r"(b0v), "r"(b1v))

#define CP_ASYNC16(dst, src) \
    asm volatile("cp.async.cg.shared.global [%0], [%1], 16;" :: "r"(dst), "l"(src))
#define CP_COMMIT() asm volatile("cp.async.commit_group;")
#define CP_WAIT(n)  asm volatile("cp.async.wait_group %0;" :: "n"(n))

__device__ __forceinline__ uint32_t lds32(uint32_t base, int r, int ch) {
    uint32_t addr = base + r * 128 + ((ch * 2) ^ ((r & 7) << 4));
    uint32_t v; asm volatile("ld.shared.b32 %0, [%1];" : "=r"(v) : "r"(addr));
    return v;
}

template <int MODE>
__global__ __launch_bounds__(256)
void gemm_nt(const bf16* __restrict__ Ah, const bf16* __restrict__ Al,
             const bf16* __restrict__ Bh, const bf16* __restrict__ Bl,
             const float* __restrict__ bias,
             float* __restrict__ Cf, bf16* __restrict__ Ch, bf16* __restrict__ Cl,
             int M, int N, int K,
             long long sA, long long sB, long long sC, float alpha) {
    constexpr int STAGES = 3;
    constexpr int STAGE_BYTES = 32768;
    extern __shared__ char smem[];
    uint32_t sbase = (uint32_t)__cvta_generic_to_shared(smem);

    const int bz = blockIdx.z;
    const int bm = blockIdx.y * 128, bn = blockIdx.x * 128;
    const bf16* pAh = Ah + (size_t)bz * sA + (size_t)bm * K;
    const bf16* pAl = Al + (size_t)bz * sA + (size_t)bm * K;
    const bf16* pBh = Bh + (size_t)bz * sB + (size_t)bn * K;
    const bf16* pBl = Bl + (size_t)bz * sB + (size_t)bn * K;

    const int tid  = threadIdx.x;
    const int wid  = tid >> 5;
    const int lane = tid & 31;
    const int lr = lane >> 2, lc = lane & 3;
    const int mw = (wid & 1) * 64;
    const int nw = (wid >> 1) * 32;

    float acc[4][4][4];
    #pragma unroll
    for (int mi = 0; mi < 4; mi++)
        #pragma unroll
        for (int ni = 0; ni < 4; ni++)
            #pragma unroll
            for (int r = 0; r < 4; r++) acc[mi][ni][r] = 0.f;

    auto load_tile = [&](int k0, int slot) {
        uint32_t dA = sbase + slot * STAGE_BYTES;
        uint32_t dB = dA + 16384;
        #pragma unroll
        for (int i = 0; i < 4; i++) {
            int j = tid + 256 * i;
            int r = j >> 3, c = j & 7;
            const bf16* src = (c < 4) ? (pAh + (size_t)r * K + k0 + c * 8)
                                      : (pAl + (size_t)r * K + k0 + (c - 4) * 8);
            CP_ASYNC16(dA + r * 128 + ((c ^ (r & 7)) << 4), src);
        }
        #pragma unroll
        for (int i = 0; i < 4; i++) {
            int j = tid + 256 * i;
            int r = j >> 3, c = j & 7;
            const bf16* src = (c < 4) ? (pBh + (size_t)r * K + k0 + c * 8)
                                      : (pBl + (size_t)r * K + k0 + (c - 4) * 8);
            CP_ASYNC16(dB + r * 128 + ((c ^ (r & 7)) << 4), src);
        }
    };

    const int ntiles = K >> 5;
    #pragma unroll
    for (int s = 0; s < STAGES - 1; s++) {
        load_tile(s * 32, s);
        CP_COMMIT();
    }

    for (int i = 0; i < ntiles; i++) {
        CP_WAIT(STAGES - 2);
        __syncthreads();
        int nx = i + STAGES - 1;
        if (nx < ntiles) {
            load_tile(nx * 32, nx % STAGES);
            CP_COMMIT();
        }
        uint32_t sA_ = sbase + (i % STAGES) * STAGE_BYTES;
        uint32_t sB_ = sA_ + 16384;

        #pragma unroll
        for (int ks = 0; ks < 2; ks++) {
            const int kk = ks * 16;
            uint32_t ah[4][4], al[4][4], bh[4][2], bl[4][2];
            #pragma unroll
            for (int mi = 0; mi < 4; mi++) {
                int r0 = mw + mi * 16 + lr;
                int c0 = kk + lc * 2;
                ah[mi][0] = lds32(sA_, r0,     c0);
                ah[mi][1] = lds32(sA_, r0 + 8, c0);
                ah[mi][2] = lds32(sA_, r0,     c0 + 8);
                ah[mi][3] = lds32(sA_, r0 + 8, c0 + 8);
                al[mi][0] = lds32(sA_, r0,     c0 + 32);
                al[mi][1] = lds32(sA_, r0 + 8, c0 + 32);
                al[mi][2] = lds32(sA_, r0,     c0 + 40);
                al[mi][3] = lds32(sA_, r0 + 8, c0 + 40);
            }
            #pragma unroll
            for (int ni = 0; ni < 4; ni++) {
                int n0 = nw + ni * 8 + lr;
                int c0 = kk + lc * 2;
                bh[ni][0] = lds32(sB_, n0, c0);
                bh[ni][1] = lds32(sB_, n0, c0 + 8);
                bl[ni][0] = lds32(sB_, n0, c0 + 32);
                bl[ni][1] = lds32(sB_, n0, c0 + 40);
            }
            #pragma unroll
            for (int mi = 0; mi < 4; mi++)
                #pragma unroll
                for (int ni = 0; ni < 4; ni++) {
                    MMA_BF16(acc[mi][ni], ah[mi], bh[ni][0], bh[ni][1]);  // hi*hi
                    MMA_BF16(acc[mi][ni], ah[mi], bl[ni][0], bl[ni][1]);  // hi*lo
                    MMA_BF16(acc[mi][ni], al[mi], bh[ni][0], bh[ni][1]);  // lo*hi
                }
        }
    }
    CP_WAIT(0);

    // ---- epilogue ----
    float* Cfp = (MODE == 0) ? Cf + (size_t)bz * sC : nullptr;
    bf16*  Chp = (MODE == 1) ? Ch + (size_t)bz * sC : nullptr;
    bf16*  Clp = (MODE == 1) ? Cl + (size_t)bz * sC : nullptr;
    #pragma unroll
    for (int mi = 0; mi < 4; mi++) {
        int row = bm + mw + mi * 16 + lr;
        #pragma unroll
        for (int ni = 0; ni < 4; ni++) {
            int col = bn + nw + ni * 8 + lc * 2;
            float o0 = acc[mi][ni][0] * alpha;
            float o1 = acc[mi][ni][1] * alpha;
            float o2 = acc[mi][ni][2] * alpha;
            float o3 = acc[mi][ni][3] * alpha;
            if (bias) {
                float b0 = bias[col], b1 = bias[col + 1];
                o0 += b0; o1 += b1; o2 += b0; o3 += b1;
            }
            if (MODE == 0) {
                *(float2*)(Cfp + (size_t)row * N + col)       = make_float2(o0, o1);
                *(float2*)(Cfp + (size_t)(row + 8) * N + col) = make_float2(o2, o3);
            } else {
                bf16 h0,h1,h2,h3,l0,l1,l2,l3;
                split_bf16(o0,h0,l0); split_bf16(o1,h1,l1);
                split_bf16(o2,h2,l2); split_bf16(o3,h3,l3);
                *(bf162*)(Chp + (size_t)row * N + col)       = bf162(h0,h1);
                *(bf162*)(Chp + (size_t)(row + 8) * N + col) = bf162(h2,h3);
                *(bf162*)(Clp + (size_t)row * N + col)       = bf162(l0,l1);
                *(bf162*)(Clp + (size_t)(row + 8) * N + col) = bf162(l2,l3);
            }
        }
    }
}

// ---------------- 5) masked row softmax -> probs hi/lo bf16 ----------------
__global__ void softmax_kernel() {
    __shared__ float red[8];
    int row = blockIdx.x;
    int b = row >> 11;
    int nc = g_nchunks[b];
    const float* sc = g_scores + (size_t)row * SS;
    bf16* ph = g_p_hi + (size_t)row * SS;
    bf16* pl = g_p_lo + (size_t)row * SS;

    const float NEG_INF = __int_as_float(0xff800000);
    float x[8];
    float m = NEG_INF;
    #pragma unroll
    for (int i = 0; i < 8; i++) {
        int c = threadIdx.x + i * 256;
        x[i] = (c < nc) ? sc[c] : NEG_INF;
        m = fmaxf(m, x[i]);
    }
    #pragma unroll
    for (int o = 16; o; o >>= 1) m = fmaxf(m, __shfl_xor_sync(0xffffffffu, m, o));
    if ((threadIdx.x & 31) == 0) red[threadIdx.x >> 5] = m;
    __syncthreads();
    m = red[0];
    #pragma unroll
    for (int i = 1; i < 8; i++) m = fmaxf(m, red[i]);
    __syncthreads();

    float s = 0.f;
    #pragma unroll
    for (int i = 0; i < 8; i++) {
        int c = threadIdx.x + i * 256;
        x[i] = (c < nc) ? expf(x[i] - m) : 0.f;
        s += x[i];
    }
    #pragma unroll
    for (int o = 16; o; o >>= 1) s += __shfl_xor_sync(0xffffffffu, s, o);
    if ((threadIdx.x & 31) == 0) red[threadIdx.x >> 5] = s;
    __syncthreads();
    s = 0.f;
    #pragma unroll
    for (int i = 0; i < 8; i++) s += red[i];
    float inv = 1.f / s;

    #pragma unroll
    for (int i = 0; i < 8; i++) {
        int c = threadIdx.x + i * 256;
        bf16 h, l; split_bf16(x[i] * inv, h, l);
        ph[c] = h; pl[c] = l;
    }
}

// ---------------- host side ----------------
static void launch_gemm(int mode,
                        const bf16* Ah, const bf16* Al, const bf16* Bh, const bf16* Bl,
                        const float* bias, float* Cf, bf16* Ch, bf16* Cl,
                        int M, int N, int K,
                        long long sA, long long sB, long long sC, int batch, float alpha) {
    constexpr int SMEM = 3 * 32768;
    dim3 grid(N / 128, M / 128, batch), block(256);
    if (mode == 0) {
        cudaFuncSetAttribute(gemm_nt<0>, cudaFuncAttributeMaxDynamicSharedMemorySize, SMEM);
        gemm_nt<0><<<grid, block, SMEM>>>(Ah, Al, Bh, Bl, bias, Cf, Ch, Cl,
                                          M, N, K, sA, sB, sC, alpha);
    } else {
        cudaFuncSetAttribute(gemm_nt<1>, cudaFuncAttributeMaxDynamicSharedMemorySize, SMEM);
        gemm_nt<1><<<grid, block, SMEM>>>(Ah, Al, Bh, Bl, bias, Cf, Ch, Cl,
                                          M, N, K, sA, sB, sC, alpha);
    }
}

extern "C" void kernel_launch(void* const* d_in, const int* in_sizes, int n_in,
                              void* d_out, int out_size) {
    (void)in_sizes; (void)n_in; (void)out_size;
    const float* h    = (const float*)d_in[0];
    const float* Wlab = (const float*)d_in[1];
    const float* blab = (const float*)d_in[2];
    const float* Wq   = (const float*)d_in[3];
    const float* bq   = (const float*)d_in[4];
    const float* Wk   = (const float*)d_in[5];
    const float* bk   = (const float*)d_in[6];
    const float* Wv   = (const float*)d_in[7];
    const float* bv   = (const float*)d_in[8];
    const float* Wo   = (const float*)d_in[9];
    const float* bo   = (const float*)d_in[10];
    float* out = (float*)d_out;

    bf16 *h_hi,*h_lo,*ce_hi,*ce_lo,*wqh,*wql,*wkh,*wkl,*wvh,*wvl,*woh,*wol;
    bf16 *q_hi,*q_lo,*k_hi,*k_lo,*v_hi,*v_lo,*vT_hi,*vT_lo,*p_hi,*p_lo,*a_hi,*a_lo;
    float* sc;
    cudaGetSymbolAddress((void**)&h_hi,  g_h_hi);  cudaGetSymbolAddress((void**)&h_lo,  g_h_lo);
    cudaGetSymbolAddress((void**)&ce_hi, g_ce_hi); cudaGetSymbolAddress((void**)&ce_lo, g_ce_lo);
    cudaGetSymbolAddress((void**)&wqh, g_wqT_hi);  cudaGetSymbolAddress((void**)&wql, g_wqT_lo);
    cudaGetSymbolAddress((void**)&wkh, g_wkT_hi);  cudaGetSymbolAddress((void**)&wkl, g_wkT_lo);
    cudaGetSymbolAddress((void**)&wvh, g_wvT_hi);  cudaGetSymbolAddress((void**)&wvl, g_wvT_lo);
    cudaGetSymbolAddress((void**)&woh, g_woT_hi);  cudaGetSymbolAddress((void**)&wol, g_woT_lo);
    cudaGetSymbolAddress((void**)&q_hi, g_q_hi);   cudaGetSymbolAddress((void**)&q_lo, g_q_lo);
    cudaGetSymbolAddress((void**)&k_hi, g_k_hi);   cudaGetSymbolAddress((void**)&k_lo, g_k_lo);
    cudaGetSymbolAddress((void**)&v_hi, g_v_hi);   cudaGetSymbolAddress((void**)&v_lo, g_v_lo);
    cudaGetSymbolAddress((void**)&vT_hi, g_vT_hi); cudaGetSymbolAddress((void**)&vT_lo, g_vT_lo);
    cudaGetSymbolAddress((void**)&p_hi, g_p_hi);   cudaGetSymbolAddress((void**)&p_lo, g_p_lo);
    cudaGetSymbolAddress((void**)&a_hi, g_att_hi); cudaGetSymbolAddress((void**)&a_lo, g_att_lo);
    cudaGetSymbolAddress((void**)&sc, g_scores);

    const int M = BB * SS;                        // 16384
    const long long sQ = (long long)SS * DD;      // per-batch q/k/v/att stride
    const long long sS = (long long)SS * SS;      // per-batch scores/probs stride
    const long long sV = (long long)DD * SS;      // per-batch vT stride

    // prep: splits, weight transposes, labels/chunks
    split4_kernel<<<(M * DD / 4) / 256, 256>>>(h, h_hi, h_lo);
    wtrans_kernel<<<dim3(32, 32), dim3(32, 8)>>>(Wq, wqh, wql);
    wtrans_kernel<<<dim3(32, 32), dim3(32, 8)>>>(Wk, wkh, wkl);
    wtrans_kernel<<<dim3(32, 32), dim3(32, 8)>>>(Wv, wvh, wvl);
    wtrans_kernel<<<dim3(32, 32), dim3(32, 8)>>>(Wo, woh, wol);
    label_kernel<<<M / 8, 256>>>(h, Wlab, blab);
    scan_kernel<<<BB, 256>>>();
    chunk_mean_kernel<<<dim3(SS, BB), 256>>>(h);

    // projections (NT vs transposed-split weights) -> hi/lo outputs
    launch_gemm(1, h_hi,  h_lo,  wqh, wql, bq, nullptr, q_hi, q_lo, M, DD, DD, 0, 0, 0, 1, 1.f);
    launch_gemm(1, ce_hi, ce_lo, wkh, wkl, bk, nullptr, k_hi, k_lo, M, DD, DD, 0, 0, 0, 1, 1.f);
    launch_gemm(1, ce_hi, ce_lo, wvh, wvl, bv, nullptr, v_hi, v_lo, M, DD, DD, 0, 0, 0, 1, 1.f);
    vtrans_kernel<<<dim3(DD / 32, SS / 32, BB), dim3(32, 8)>>>();

    // scores[b] = (q[b] @ k[b]^T) / 32  -> fp32
    launch_gemm(0, q_hi, q_lo, k_hi, k_lo, nullptr, sc, nullptr, nullptr,
                SS, SS, DD, sQ, sQ, sS, BB, 0.03125f);

    softmax_kernel<<<M, 256>>>();   // -> probs hi/lo (masked cols exactly 0)

    // attended[b] = probs[b] @ vT[b]^T -> hi/lo
    launch_gemm(1, p_hi, p_lo, vT_hi, vT_lo, nullptr, nullptr, a_hi, a_lo,
                SS, DD, SS, sS, sV, sQ, BB, 1.f);

    // out = att @ Wo^T^T + bo -> fp32 d_out
    launch_gemm(0, a_hi, a_lo, woh, wol, bo, out, nullptr, nullptr,
                M, DD, DD, 0, 0, 0, 1, 1.f);
}

// round 6
// speedup vs baseline: 2.4289x; 1.0752x over previous
#include <cuda_runtime.h>
#include <cuda_bf16.h>
#include <cstdint>
#include <cstddef>

#define BB 8
#define SS 2048
#define DD 1024
// DC == DD == 1024, scale = 1/sqrt(1024) = 1/32

typedef __nv_bfloat16 bf16;
typedef __nv_bfloat162 bf162;

// ---------------- scratch (static device globals; no allocation) ----------------
__device__ int   g_labels[BB * SS];
__device__ int   g_chunk_start[BB * SS];
__device__ int   g_chunk_len[BB * SS];
__device__ int   g_nchunks[BB];

__device__ bf16  g_h_hi[(size_t)BB * SS * DD],  g_h_lo[(size_t)BB * SS * DD];
__device__ bf16  g_ce_hi[(size_t)BB * SS * DD], g_ce_lo[(size_t)BB * SS * DD];
__device__ bf16  g_wqT_hi[DD * DD], g_wqT_lo[DD * DD];
__device__ bf16  g_wkT_hi[DD * DD], g_wkT_lo[DD * DD];
__device__ bf16  g_wvT_hi[DD * DD], g_wvT_lo[DD * DD];
__device__ bf16  g_woT_hi[DD * DD], g_woT_lo[DD * DD];
__device__ bf16  g_q_hi[(size_t)BB * SS * DD],  g_q_lo[(size_t)BB * SS * DD];
__device__ bf16  g_k_hi[(size_t)BB * SS * DD],  g_k_lo[(size_t)BB * SS * DD];
__device__ bf16  g_v_hi[(size_t)BB * SS * DD],  g_v_lo[(size_t)BB * SS * DD];
__device__ bf16  g_vT_hi[(size_t)BB * DD * SS], g_vT_lo[(size_t)BB * DD * SS];
__device__ bf16  g_p_hi[(size_t)BB * SS * SS],  g_p_lo[(size_t)BB * SS * SS];
__device__ bf16  g_att_hi[(size_t)BB * SS * DD], g_att_lo[(size_t)BB * SS * DD];
__device__ float g_scores[(size_t)BB * SS * SS];      // 128 MB

__device__ __forceinline__ void split_bf16(float x, bf16& hi, bf16& lo) {
    hi = __float2bfloat16(x);
    lo = __float2bfloat16(x - __bfloat162float(hi));
}

// ---------------- 0) fp32 -> hi/lo split (for h) ----------------
__global__ void split4_kernel(const float* __restrict__ src,
                              bf16* __restrict__ hi, bf16* __restrict__ lo) {
    size_t i = (size_t)blockIdx.x * blockDim.x + threadIdx.x;  // float4 index
    float4 v = ((const float4*)src)[i];
    bf16 h0,h1,h2,h3,l0,l1,l2,l3;
    split_bf16(v.x,h0,l0); split_bf16(v.y,h1,l1);
    split_bf16(v.z,h2,l2); split_bf16(v.w,h3,l3);
    ((bf162*)hi)[i*2+0] = bf162(h0,h1); ((bf162*)hi)[i*2+1] = bf162(h2,h3);
    ((bf162*)lo)[i*2+0] = bf162(l0,l1); ((bf162*)lo)[i*2+1] = bf162(l2,l3);
}

// ---------------- 0b) weight transpose + split: W(K,N) -> WT(N,K) hi/lo ----------------
__global__ void wtrans_kernel(const float* __restrict__ W,
                              bf16* __restrict__ Th, bf16* __restrict__ Tl) {
    __shared__ float t[32][33];
    int tx = threadIdx.x, ty = threadIdx.y;          // (32, 8)
    int x = blockIdx.x * 32 + tx, y = blockIdx.y * 32 + ty;
    #pragma unroll
    for (int k = 0; k < 4; k++) t[ty + 8*k][tx] = W[(size_t)(y + 8*k) * DD + x];
    __syncthreads();
    int x2 = blockIdx.y * 32 + tx, y2 = blockIdx.x * 32 + ty;
    #pragma unroll
    for (int k = 0; k < 4; k++) {
        float v = t[tx][ty + 8*k];
        bf16 h, l; split_bf16(v, h, l);
        Th[(size_t)(y2 + 8*k) * DD + x2] = h;
        Tl[(size_t)(y2 + 8*k) * DD + x2] = l;
    }
}

// ---------------- 0c) bf16 pair transpose: v(S,D) -> vT(D,S), per batch ----------------
__global__ void vtrans_kernel() {
    __shared__ bf16 th[32][34], tl[32][34];
    int b = blockIdx.z;
    int tx = threadIdx.x, ty = threadIdx.y;          // (32, 8)
    const bf16* vh = g_v_hi + (size_t)b * SS * DD;
    const bf16* vl = g_v_lo + (size_t)b * SS * DD;
    bf16* oh = g_vT_hi + (size_t)b * DD * SS;
    bf16* ol = g_vT_lo + (size_t)b * DD * SS;
    int d0 = blockIdx.x * 32, s0 = blockIdx.y * 32;
    #pragma unroll
    for (int k = 0; k < 4; k++) {
        th[ty + 8*k][tx] = vh[(size_t)(s0 + ty + 8*k) * DD + d0 + tx];
        tl[ty + 8*k][tx] = vl[(size_t)(s0 + ty + 8*k) * DD + d0 + tx];
    }
    __syncthreads();
    #pragma unroll
    for (int k = 0; k < 4; k++) {
        oh[(size_t)(d0 + ty + 8*k) * SS + s0 + tx] = th[tx][ty + 8*k];
        ol[(size_t)(d0 + ty + 8*k) * SS + s0 + tx] = tl[tx][ty + 8*k];
    }
}

// ---------------- 1) labels = argmax(h @ W_lab + b_lab) (fp32: argmax cliff) ----------------
__global__ void label_kernel(const float* __restrict__ h,
                             const float* __restrict__ Wlab,
                             const float* __restrict__ blab) {
    int tok  = blockIdx.x * (blockDim.x >> 5) + (threadIdx.x >> 5);
    int lane = threadIdx.x & 31;
    const float* hr = h + (size_t)tok * DD;
    float a0 = 0.f, a1 = 0.f, a2 = 0.f, a3 = 0.f;
    for (int k = lane; k < DD; k += 32) {
        float hv = hr[k];
        float4 w = *(const float4*)(Wlab + k * 4);
        a0 += hv * w.x; a1 += hv * w.y; a2 += hv * w.z; a3 += hv * w.w;
    }
    #pragma unroll
    for (int o = 16; o; o >>= 1) {
        a0 += __shfl_down_sync(0xffffffffu, a0, o);
        a1 += __shfl_down_sync(0xffffffffu, a1, o);
        a2 += __shfl_down_sync(0xffffffffu, a2, o);
        a3 += __shfl_down_sync(0xffffffffu, a3, o);
    }
    if (lane == 0) {
        float lg[4] = { a0 + blab[0], a1 + blab[1], a2 + blab[2], a3 + blab[3] };
        int best = 0; float bv = lg[0];
        #pragma unroll
        for (int j = 1; j < 4; j++) if (lg[j] > bv) { bv = lg[j]; best = j; }
        g_labels[tok] = best;
    }
}

// ---------------- 2) sequential BIOS chunk scan ----------------
__global__ void scan_kernel() {
    __shared__ int lab[SS];
    int b = blockIdx.x;
    for (int s = threadIdx.x; s < SS; s += blockDim.x) lab[s] = g_labels[b * SS + s];
    __syncthreads();
    if (threadIdx.x == 0) {
        int* cs = g_chunk_start + b * SS;
        int* cl = g_chunk_len   + b * SS;
        bool open = false; int c = -1;
        for (int s = 0; s < SS; s++) {
            int l = lab[s];
            bool cont = (l == 1) && open;
            open = (l == 0) || cont;
            if (!cont) {
                if (c >= 0) cl[c] = s - cs[c];
                c++; cs[c] = s;
            }
        }
        cl[c] = SS - cs[c];
        g_nchunks[b] = c + 1;
    }
}

// ---------------- 3) per-chunk mean (contiguous ranges) -> split hi/lo ----------------
__global__ void chunk_mean_kernel(const float* __restrict__ h) {
    int b = blockIdx.y, c = blockIdx.x;
    size_t base_o = ((size_t)b * SS + c) * DD;
    int d = threadIdx.x * 4;
    int nc = g_nchunks[b];
    float4 acc = make_float4(0.f, 0.f, 0.f, 0.f);
    if (c < nc) {
        int st  = g_chunk_start[b * SS + c];
        int len = g_chunk_len[b * SS + c];
        const float* base = h + ((size_t)b * SS + st) * DD + d;
        for (int t = 0; t < len; t++) {
            float4 v = *(const float4*)(base + (size_t)t * DD);
            acc.x += v.x; acc.y += v.y; acc.z += v.z; acc.w += v.w;
        }
        float inv = 1.f / (float)len;
        acc.x *= inv; acc.y *= inv; acc.z *= inv; acc.w *= inv;
    }
    bf16 h0,h1,h2,h3,l0,l1,l2,l3;
    split_bf16(acc.x,h0,l0); split_bf16(acc.y,h1,l1);
    split_bf16(acc.z,h2,l2); split_bf16(acc.w,h3,l3);
    *(bf162*)(g_ce_hi + base_o + d)     = bf162(h0,h1);
    *(bf162*)(g_ce_hi + base_o + d + 2) = bf162(h2,h3);
    *(bf162*)(g_ce_lo + base_o + d)     = bf162(l0,l1);
    *(bf162*)(g_ce_lo + base_o + d + 2) = bf162(l2,l3);
}

// ---------------- 4) NT tensor-core GEMM, bf16x3, cp.async 4-stage + ldmatrix ----------------
// C(M,N) = alpha * A(M,K) @ B(N,K)^T [+ bias]; A,B pre-split hi/lo bf16 row-major.
// MODE 0: fp32 out.  MODE 1: split bf16 hi/lo out.
// BM=BN=128, BK=32, 256 thr = 8 warps (2m x 4n), warp tile 64x32.
// Stage 32KB: A[128 rows][128B: hi halves 0-31 | lo 32-63], B same.
// XOR-16B swizzle (chunk ^= row&7): conflict-free for both cp.async stores and ldmatrix.

#define MMA_BF16(d, a, b0v, b1v) \
    asm volatile("mma.sync.aligned.m16n8k16.row.col.f32.bf16.bf16.f32 " \
                 "{%0,%1,%2,%3}, {%4,%5,%6,%7}, {%8,%9}, {%0,%1,%2,%3};" \
                 : "+f"(d[0]), "+f"(d[1]), "+f"(d[2]), "+f"(d[3]) \
                 : "r"(a[0]), "r"(a[1]), "r"(a[2]), "r"(a[3]), "r"(b0v), "r"(b1v))

#define LDSM4(r, addr) \
    asm volatile("ldmatrix.sync.aligned.m8n8.x4.shared.b16 {%0,%1,%2,%3}, [%4];" \
                 : "=r"((r)[0]), "=r"((r)[1]), "=r"((r)[2]), "=r"((r)[3]) : "r"(addr))

#define CP_ASYNC16(dst, src) \
    asm volatile("cp.async.cg.shared.global [%0], [%1], 16;" :: "r"(dst), "l"(src))
#define CP_COMMIT() asm volatile("cp.async.commit_group;")
#define CP_WAIT(n)  asm volatile("cp.async.wait_group %0;" :: "n"(n))

template <int MODE>
__global__ __launch_bounds__(256)
void gemm_nt(const bf16* __restrict__ Ah, const bf16* __restrict__ Al,
             const bf16* __restrict__ Bh, const bf16* __restrict__ Bl,
             const float* __restrict__ bias,
             float* __restrict__ Cf, bf16* __restrict__ Ch, bf16* __restrict__ Cl,
             int M, int N, int K,
             long long sA, long long sB, long long sC, float alpha) {
    constexpr int STAGES = 4;
    constexpr int STAGE_BYTES = 32768;
    extern __shared__ char smem[];
    uint32_t sbase = (uint32_t)__cvta_generic_to_shared(smem);

    const int bz = blockIdx.z;
    const int bm = blockIdx.y * 128, bn = blockIdx.x * 128;
    const bf16* pAh = Ah + (size_t)bz * sA + (size_t)bm * K;
    const bf16* pAl = Al + (size_t)bz * sA + (size_t)bm * K;
    const bf16* pBh = Bh + (size_t)bz * sB + (size_t)bn * K;
    const bf16* pBl = Bl + (size_t)bz * sB + (size_t)bn * K;

    const int tid  = threadIdx.x;
    const int wid  = tid >> 5;
    const int lane = tid & 31;
    const int lr = lane >> 2, lc = lane & 3;     // fragment owner coords (epilogue)
    const int mw = (wid & 1) * 64;
    const int nw = (wid >> 1) * 32;

    // ldmatrix per-lane source coords
    const int l8  = lane & 7;
    const int lb  = (lane >> 3) & 1;
    const int lhb = lane >> 4;
    // A x4: matrices (rowblk = m&1 from lb, colblk = m>>1 from lhb)
    const int arow  = mw + l8 + lb * 8;          // + mi*16
    const int acolh = lhb * 8;                   // + kk (halves); lo: +32
    const uint32_t aswz = (uint32_t)((arow & 7) << 4);
    // B x4: matrices (rowblk = m>>1 from lhb, colblk = m&1 from lb)
    const int brow  = nw + l8 + lhb * 8;         // + p*16
    const int bcolh = lb * 8;                    // + kk; lo: +32
    const uint32_t bswz = (uint32_t)((brow & 7) << 4);

    float acc[4][4][4];
    #pragma unroll
    for (int mi = 0; mi < 4; mi++)
        #pragma unroll
        for (int ni = 0; ni < 4; ni++)
            #pragma unroll
            for (int r = 0; r < 4; r++) acc[mi][ni][r] = 0.f;

    auto load_tile = [&](int k0, int slot) {
        uint32_t dA = sbase + slot * STAGE_BYTES;
        uint32_t dB = dA + 16384;
        #pragma unroll
        for (int i = 0; i < 4; i++) {
            int j = tid + 256 * i;
            int r = j >> 3, c = j & 7;
            const bf16* src = (c < 4) ? (pAh + (size_t)r * K + k0 + c * 8)
                                      : (pAl + (size_t)r * K + k0 + (c - 4) * 8);
            CP_ASYNC16(dA + r * 128 + ((c ^ (r & 7)) << 4), src);
        }
        #pragma unroll
        for (int i = 0; i < 4; i++) {
            int j = tid + 256 * i;
            int r = j >> 3, c = j & 7;
            const bf16* src = (c < 4) ? (pBh + (size_t)r * K + k0 + c * 8)
                                      : (pBl + (size_t)r * K + k0 + (c - 4) * 8);
            CP_ASYNC16(dB + r * 128 + ((c ^ (r & 7)) << 4), src);
        }
    };

    const int ntiles = K >> 5;
    #pragma unroll
    for (int s = 0; s < STAGES - 1; s++) {
        load_tile(s * 32, s);
        CP_COMMIT();
    }

    for (int i = 0; i < ntiles; i++) {
        CP_WAIT(STAGES - 2);
        __syncthreads();
        int nx = i + STAGES - 1;
        if (nx < ntiles) {
            load_tile(nx * 32, nx % STAGES);
            CP_COMMIT();
        }
        uint32_t sA_ = sbase + (i % STAGES) * STAGE_BYTES;
        uint32_t sB_ = sA_ + 16384;

        #pragma unroll
        for (int ks = 0; ks < 2; ks++) {
            const int kk = ks * 16;
            uint32_t ah[4][4], al[4][4], bh[4][2], bl[4][2];
            // A fragments: one ldmatrix.x4 per mi (hi) + per mi (lo)
            {
                uint32_t ah_addr = sA_ + (uint32_t)arow * 128
                                 + (((uint32_t)(kk + acolh) * 2) ^ aswz);
                uint32_t al_addr = sA_ + (uint32_t)arow * 128
                                 + (((uint32_t)(kk + acolh + 32) * 2) ^ aswz);
                #pragma unroll
                for (int mi = 0; mi < 4; mi++) {
                    LDSM4(ah[mi], ah_addr + mi * (16 * 128));
                    LDSM4(al[mi], al_addr + mi * (16 * 128));
                }
            }
            // B fragments: one ldmatrix.x4 covers ni pair {2p, 2p+1}
            {
                uint32_t bh_addr = sB_ + (uint32_t)brow * 128
                                 + (((uint32_t)(kk + bcolh) * 2) ^ bswz);
                uint32_t bl_addr = sB_ + (uint32_t)brow * 128
                                 + (((uint32_t)(kk + bcolh + 32) * 2) ^ bswz);
                #pragma unroll
                for (int p = 0; p < 2; p++) {
                    uint32_t t[4];
                    LDSM4(t, bh_addr + p * (16 * 128));
                    bh[2*p][0] = t[0]; bh[2*p][1] = t[1];
                    bh[2*p+1][0] = t[2]; bh[2*p+1][1] = t[3];
                    LDSM4(t, bl_addr + p * (16 * 128));
                    bl[2*p][0] = t[0]; bl[2*p][1] = t[1];
                    bl[2*p+1][0] = t[2]; bl[2*p+1][1] = t[3];
                }
            }
            #pragma unroll
            for (int mi = 0; mi < 4; mi++)
                #pragma unroll
                for (int ni = 0; ni < 4; ni++) {
                    MMA_BF16(acc[mi][ni], ah[mi], bh[ni][0], bh[ni][1]);  // hi*hi
                    MMA_BF16(acc[mi][ni], ah[mi], bl[ni][0], bl[ni][1]);  // hi*lo
                    MMA_BF16(acc[mi][ni], al[mi], bh[ni][0], bh[ni][1]);  // lo*hi
                }
        }
    }
    CP_WAIT(0);

    // ---- epilogue ----
    float* Cfp = (MODE == 0) ? Cf + (size_t)bz * sC : nullptr;
    bf16*  Chp = (MODE == 1) ? Ch + (size_t)bz * sC : nullptr;
    bf16*  Clp = (MODE == 1) ? Cl + (size_t)bz * sC : nullptr;
    #pragma unroll
    for (int mi = 0; mi < 4; mi++) {
        int row = bm + mw + mi * 16 + lr;
        #pragma unroll
        for (int ni = 0; ni < 4; ni++) {
            int col = bn + nw + ni * 8 + lc * 2;
            float o0 = acc[mi][ni][0] * alpha;
            float o1 = acc[mi][ni][1] * alpha;
            float o2 = acc[mi][ni][2] * alpha;
            float o3 = acc[mi][ni][3] * alpha;
            if (bias) {
                float b0 = bias[col], b1 = bias[col + 1];
                o0 += b0; o1 += b1; o2 += b0; o3 += b1;
            }
            if (MODE == 0) {
                *(float2*)(Cfp + (size_t)row * N + col)       = make_float2(o0, o1);
                *(float2*)(Cfp + (size_t)(row + 8) * N + col) = make_float2(o2, o3);
            } else {
                bf16 h0,h1,h2,h3,l0,l1,l2,l3;
                split_bf16(o0,h0,l0); split_bf16(o1,h1,l1);
                split_bf16(o2,h2,l2); split_bf16(o3,h3,l3);
                *(bf162*)(Chp + (size_t)row * N + col)       = bf162(h0,h1);
                *(bf162*)(Chp + (size_t)(row + 8) * N + col) = bf162(h2,h3);
                *(bf162*)(Clp + (size_t)row * N + col)       = bf162(l0,l1);
                *(bf162*)(Clp + (size_t)(row + 8) * N + col) = bf162(l2,l3);
            }
        }
    }
}

// ---------------- 5) masked row softmax -> probs hi/lo bf16 ----------------
__global__ void softmax_kernel() {
    __shared__ float red[8];
    int row = blockIdx.x;
    int b = row >> 11;
    int nc = g_nchunks[b];
    const float* sc = g_scores + (size_t)row * SS;
    bf16* ph = g_p_hi + (size_t)row * SS;
    bf16* pl = g_p_lo + (size_t)row * SS;

    const float NEG_INF = __int_as_float(0xff800000);
    float x[8];
    float m = NEG_INF;
    #pragma unroll
    for (int i = 0; i < 8; i++) {
        int c = threadIdx.x + i * 256;
        x[i] = (c < nc) ? sc[c] : NEG_INF;
        m = fmaxf(m, x[i]);
    }
    #pragma unroll
    for (int o = 16; o; o >>= 1) m = fmaxf(m, __shfl_xor_sync(0xffffffffu, m, o));
    if ((threadIdx.x & 31) == 0) red[threadIdx.x >> 5] = m;
    __syncthreads();
    m = red[0];
    #pragma unroll
    for (int i = 1; i < 8; i++) m = fmaxf(m, red[i]);
    __syncthreads();

    float s = 0.f;
    #pragma unroll
    for (int i = 0; i < 8; i++) {
        int c = threadIdx.x + i * 256;
        x[i] = (c < nc) ? expf(x[i] - m) : 0.f;
        s += x[i];
    }
    #pragma unroll
    for (int o = 16; o; o >>= 1) s += __shfl_xor_sync(0xffffffffu, s, o);
    if ((threadIdx.x & 31) == 0) red[threadIdx.x >> 5] = s;
    __syncthreads();
    s = 0.f;
    #pragma unroll
    for (int i = 0; i < 8; i++) s += red[i];
    float inv = 1.f / s;

    #pragma unroll
    for (int i = 0; i < 8; i++) {
        int c = threadIdx.x + i * 256;
        bf16 h, l; split_bf16(x[i] * inv, h, l);
        ph[c] = h; pl[c] = l;
    }
}

// ---------------- host side ----------------
static void launch_gemm(int mode,
                        const bf16* Ah, const bf16* Al, const bf16* Bh, const bf16* Bl,
                        const float* bias, float* Cf, bf16* Ch, bf16* Cl,
                        int M, int N, int K,
                        long long sA, long long sB, long long sC, int batch, float alpha) {
    constexpr int SMEM = 4 * 32768;
    dim3 grid(N / 128, M / 128, batch), block(256);
    if (mode == 0) {
        cudaFuncSetAttribute(gemm_nt<0>, cudaFuncAttributeMaxDynamicSharedMemorySize, SMEM);
        gemm_nt<0><<<grid, block, SMEM>>>(Ah, Al, Bh, Bl, bias, Cf, Ch, Cl,
                                          M, N, K, sA, sB, sC, alpha);
    } else {
        cudaFuncSetAttribute(gemm_nt<1>, cudaFuncAttributeMaxDynamicSharedMemorySize, SMEM);
        gemm_nt<1><<<grid, block, SMEM>>>(Ah, Al, Bh, Bl, bias, Cf, Ch, Cl,
                                          M, N, K, sA, sB, sC, alpha);
    }
}

extern "C" void kernel_launch(void* const* d_in, const int* in_sizes, int n_in,
                              void* d_out, int out_size) {
    (void)in_sizes; (void)n_in; (void)out_size;
    const float* h    = (const float*)d_in[0];
    const float* Wlab = (const float*)d_in[1];
    const float* blab = (const float*)d_in[2];
    const float* Wq   = (const float*)d_in[3];
    const float* bq   = (const float*)d_in[4];
    const float* Wk   = (const float*)d_in[5];
    const float* bk   = (const float*)d_in[6];
    const float* Wv   = (const float*)d_in[7];
    const float* bv   = (const float*)d_in[8];
    const float* Wo   = (const float*)d_in[9];
    const float* bo   = (const float*)d_in[10];
    float* out = (float*)d_out;

    bf16 *h_hi,*h_lo,*ce_hi,*ce_lo,*wqh,*wql,*wkh,*wkl,*wvh,*wvl,*woh,*wol;
    bf16 *q_hi,*q_lo,*k_hi,*k_lo,*v_hi,*v_lo,*vT_hi,*vT_lo,*p_hi,*p_lo,*a_hi,*a_lo;
    float* sc;
    cudaGetSymbolAddress((void**)&h_hi,  g_h_hi);  cudaGetSymbolAddress((void**)&h_lo,  g_h_lo);
    cudaGetSymbolAddress((void**)&ce_hi, g_ce_hi); cudaGetSymbolAddress((void**)&ce_lo, g_ce_lo);
    cudaGetSymbolAddress((void**)&wqh, g_wqT_hi);  cudaGetSymbolAddress((void**)&wql, g_wqT_lo);
    cudaGetSymbolAddress((void**)&wkh, g_wkT_hi);  cudaGetSymbolAddress((void**)&wkl, g_wkT_lo);
    cudaGetSymbolAddress((void**)&wvh, g_wvT_hi);  cudaGetSymbolAddress((void**)&wvl, g_wvT_lo);
    cudaGetSymbolAddress((void**)&woh, g_woT_hi);  cudaGetSymbolAddress((void**)&wol, g_woT_lo);
    cudaGetSymbolAddress((void**)&q_hi, g_q_hi);   cudaGetSymbolAddress((void**)&q_lo, g_q_lo);
    cudaGetSymbolAddress((void**)&k_hi, g_k_hi);   cudaGetSymbolAddress((void**)&k_lo, g_k_lo);
    cudaGetSymbolAddress((void**)&v_hi, g_v_hi);   cudaGetSymbolAddress((void**)&v_lo, g_v_lo);
    cudaGetSymbolAddress((void**)&vT_hi, g_vT_hi); cudaGetSymbolAddress((void**)&vT_lo, g_vT_lo);
    cudaGetSymbolAddress((void**)&p_hi, g_p_hi);   cudaGetSymbolAddress((void**)&p_lo, g_p_lo);
    cudaGetSymbolAddress((void**)&a_hi, g_att_hi); cudaGetSymbolAddress((void**)&a_lo, g_att_lo);
    cudaGetSymbolAddress((void**)&sc, g_scores);

    const int M = BB * SS;                        // 16384
    const long long sQ = (long long)SS * DD;      // per-batch q/k/v/att stride
    const long long sS = (long long)SS * SS;      // per-batch scores/probs stride
    const long long sV = (long long)DD * SS;      // per-batch vT stride

    // prep: splits, weight transposes, labels/chunks
    split4_kernel<<<(M * DD / 4) / 256, 256>>>(h, h_hi, h_lo);
    wtrans_kernel<<<dim3(32, 32), dim3(32, 8)>>>(Wq, wqh, wql);
    wtrans_kernel<<<dim3(32, 32), dim3(32, 8)>>>(Wk, wkh, wkl);
    wtrans_kernel<<<dim3(32, 32), dim3(32, 8)>>>(Wv, wvh, wvl);
    wtrans_kernel<<<dim3(32, 32), dim3(32, 8)>>>(Wo, woh, wol);
    label_kernel<<<M / 8, 256>>>(h, Wlab, blab);
    scan_kernel<<<BB, 256>>>();
    chunk_mean_kernel<<<dim3(SS, BB), 256>>>(h);

    // projections (NT vs transposed-split weights) -> hi/lo outputs
    launch_gemm(1, h_hi,  h_lo,  wqh, wql, bq, nullptr, q_hi, q_lo, M, DD, DD, 0, 0, 0, 1, 1.f);
    launch_gemm(1, ce_hi, ce_lo, wkh, wkl, bk, nullptr, k_hi, k_lo, M, DD, DD, 0, 0, 0, 1, 1.f);
    launch_gemm(1, ce_hi, ce_lo, wvh, wvl, bv, nullptr, v_hi, v_lo, M, DD, DD, 0, 0, 0, 1, 1.f);
    vtrans_kernel<<<dim3(DD / 32, SS / 32, BB), dim3(32, 8)>>>();

    // scores[b] = (q[b] @ k[b]^T) / 32  -> fp32
    launch_gemm(0, q_hi, q_lo, k_hi, k_lo, nullptr, sc, nullptr, nullptr,
                SS, SS, DD, sQ, sQ, sS, BB, 0.03125f);

    softmax_kernel<<<M, 256>>>();   // -> probs hi/lo (masked cols exactly 0)

    // attended[b] = probs[b] @ vT[b]^T -> hi/lo
    launch_gemm(1, p_hi, p_lo, vT_hi, vT_lo, nullptr, nullptr, a_hi, a_lo,
                SS, DD, SS, sS, sV, sQ, BB, 1.f);

    // out = att @ Wo^T^T + bo -> fp32 d_out
    launch_gemm(0, a_hi, a_lo, woh, wol, bo, out, nullptr, nullptr,
                M, DD, DD, 0, 0, 0, 1, 1.f);
}

// round 8
// speedup vs baseline: 2.4307x; 1.0008x over previous
#include <cuda_runtime.h>
#include <cuda_bf16.h>
#include <cstdint>
#include <cstddef>

#define BB 8
#define SS 2048
#define DD 1024
// DC == DD == 1024, scale = 1/sqrt(1024) = 1/32

typedef __nv_bfloat16 bf16;
typedef __nv_bfloat162 bf162;

// ---------------- scratch (static device globals; no allocation) ----------------
__device__ int   g_labels[BB * SS];
__device__ int   g_chunk_start[BB * SS];
__device__ int   g_chunk_len[BB * SS];
__device__ int   g_nchunks[BB];

__device__ bf16  g_h_hi[(size_t)BB * SS * DD],  g_h_lo[(size_t)BB * SS * DD];
__device__ bf16  g_ce_hi[(size_t)BB * SS * DD], g_ce_lo[(size_t)BB * SS * DD];
__device__ bf16  g_wqT_hi[DD * DD], g_wqT_lo[DD * DD];
__device__ bf16  g_wkT_hi[DD * DD], g_wkT_lo[DD * DD];
__device__ bf16  g_wvT_hi[DD * DD], g_wvT_lo[DD * DD];
__device__ bf16  g_woT_hi[DD * DD], g_woT_lo[DD * DD];
__device__ bf16  g_q_hi[(size_t)BB * SS * DD],  g_q_lo[(size_t)BB * SS * DD];
__device__ bf16  g_k_hi[(size_t)BB * SS * DD],  g_k_lo[(size_t)BB * SS * DD];
__device__ bf16  g_v_hi[(size_t)BB * SS * DD],  g_v_lo[(size_t)BB * SS * DD];
__device__ bf16  g_vT_hi[(size_t)BB * DD * SS], g_vT_lo[(size_t)BB * DD * SS];
__device__ bf16  g_p_hi[(size_t)BB * SS * SS],  g_p_lo[(size_t)BB * SS * SS];
__device__ bf16  g_att_hi[(size_t)BB * SS * DD], g_att_lo[(size_t)BB * SS * DD];
__device__ float g_scores[(size_t)BB * SS * SS];      // 128 MB

__device__ __forceinline__ void split_bf16(float x, bf16& hi, bf16& lo) {
    hi = __float2bfloat16(x);
    lo = __float2bfloat16(x - __bfloat162float(hi));
}

// ---------------- 0) fp32 -> hi/lo split (for h) ----------------
__global__ void split4_kernel(const float* __restrict__ src,
                              bf16* __restrict__ hi, bf16* __restrict__ lo) {
    size_t i = (size_t)blockIdx.x * blockDim.x + threadIdx.x;  // float4 index
    float4 v = ((const float4*)src)[i];
    bf16 h0,h1,h2,h3,l0,l1,l2,l3;
    split_bf16(v.x,h0,l0); split_bf16(v.y,h1,l1);
    split_bf16(v.z,h2,l2); split_bf16(v.w,h3,l3);
    ((bf162*)hi)[i*2+0] = bf162(h0,h1); ((bf162*)hi)[i*2+1] = bf162(h2,h3);
    ((bf162*)lo)[i*2+0] = bf162(l0,l1); ((bf162*)lo)[i*2+1] = bf162(l2,l3);
}

// ---------------- 0b) weight transpose + split: W(K,N) -> WT(N,K) hi/lo ----------------
__global__ void wtrans_kernel(const float* __restrict__ W,
                              bf16* __restrict__ Th, bf16* __restrict__ Tl) {
    __shared__ float t[32][33];
    int tx = threadIdx.x, ty = threadIdx.y;          // (32, 8)
    int x = blockIdx.x * 32 + tx, y = blockIdx.y * 32 + ty;
    #pragma unroll
    for (int k = 0; k < 4; k++) t[ty + 8*k][tx] = W[(size_t)(y + 8*k) * DD + x];
    __syncthreads();
    int x2 = blockIdx.y * 32 + tx, y2 = blockIdx.x * 32 + ty;
    #pragma unroll
    for (int k = 0; k < 4; k++) {
        float v = t[tx][ty + 8*k];
        bf16 h, l; split_bf16(v, h, l);
        Th[(size_t)(y2 + 8*k) * DD + x2] = h;
        Tl[(size_t)(y2 + 8*k) * DD + x2] = l;
    }
}

// ---------------- 0c) bf16 pair transpose: v(S,D) -> vT(D,S), per batch ----------------
__global__ void vtrans_kernel() {
    __shared__ bf16 th[32][34], tl[32][34];
    int b = blockIdx.z;
    int tx = threadIdx.x, ty = threadIdx.y;          // (32, 8)
    const bf16* vh = g_v_hi + (size_t)b * SS * DD;
    const bf16* vl = g_v_lo + (size_t)b * SS * DD;
    bf16* oh = g_vT_hi + (size_t)b * DD * SS;
    bf16* ol = g_vT_lo + (size_t)b * DD * SS;
    int d0 = blockIdx.x * 32, s0 = blockIdx.y * 32;
    #pragma unroll
    for (int k = 0; k < 4; k++) {
        th[ty + 8*k][tx] = vh[(size_t)(s0 + ty + 8*k) * DD + d0 + tx];
        tl[ty + 8*k][tx] = vl[(size_t)(s0 + ty + 8*k) * DD + d0 + tx];
    }
    __syncthreads();
    #pragma unroll
    for (int k = 0; k < 4; k++) {
        oh[(size_t)(d0 + ty + 8*k) * SS + s0 + tx] = th[tx][ty + 8*k];
        ol[(size_t)(d0 + ty + 8*k) * SS + s0 + tx] = tl[tx][ty + 8*k];
    }
}

// ---------------- 1) labels = argmax(h @ W_lab + b_lab) (fp32: argmax cliff) ----------------
__global__ void label_kernel(const float* __restrict__ h,
                             const float* __restrict__ Wlab,
                             const float* __restrict__ blab) {
    int tok  = blockIdx.x * (blockDim.x >> 5) + (threadIdx.x >> 5);
    int lane = threadIdx.x & 31;
    const float* hr = h + (size_t)tok * DD;
    float a0 = 0.f, a1 = 0.f, a2 = 0.f, a3 = 0.f;
    for (int k = lane; k < DD; k += 32) {
        float hv = hr[k];
        float4 w = *(const float4*)(Wlab + k * 4);
        a0 += hv * w.x; a1 += hv * w.y; a2 += hv * w.z; a3 += hv * w.w;
    }
    #pragma unroll
    for (int o = 16; o; o >>= 1) {
        a0 += __shfl_down_sync(0xffffffffu, a0, o);
        a1 += __shfl_down_sync(0xffffffffu, a1, o);
        a2 += __shfl_down_sync(0xffffffffu, a2, o);
        a3 += __shfl_down_sync(0xffffffffu, a3, o);
    }
    if (lane == 0) {
        float lg[4] = { a0 + blab[0], a1 + blab[1], a2 + blab[2], a3 + blab[3] };
        int best = 0; float bv = lg[0];
        #pragma unroll
        for (int j = 1; j < 4; j++) if (lg[j] > bv) { bv = lg[j]; best = j; }
        g_labels[tok] = best;
    }
}

// ---------------- 2) sequential BIOS chunk scan ----------------
__global__ void scan_kernel() {
    __shared__ int lab[SS];
    int b = blockIdx.x;
    for (int s = threadIdx.x; s < SS; s += blockDim.x) lab[s] = g_labels[b * SS + s];
    __syncthreads();
    if (threadIdx.x == 0) {
        int* cs = g_chunk_start + b * SS;
        int* cl = g_chunk_len   + b * SS;
        bool open = false; int c = -1;
        for (int s = 0; s < SS; s++) {
            int l = lab[s];
            bool cont = (l == 1) && open;
            open = (l == 0) || cont;
            if (!cont) {
                if (c >= 0) cl[c] = s - cs[c];
                c++; cs[c] = s;
            }
        }
        cl[c] = SS - cs[c];
        g_nchunks[b] = c + 1;
    }
}

// ---------------- 3) per-chunk mean (contiguous ranges) -> split hi/lo ----------------
__global__ void chunk_mean_kernel(const float* __restrict__ h) {
    int b = blockIdx.y, c = blockIdx.x;
    size_t base_o = ((size_t)b * SS + c) * DD;
    int d = threadIdx.x * 4;
    int nc = g_nchunks[b];
    float4 acc = make_float4(0.f, 0.f, 0.f, 0.f);
    if (c < nc) {
        int st  = g_chunk_start[b * SS + c];
        int len = g_chunk_len[b * SS + c];
        const float* base = h + ((size_t)b * SS + st) * DD + d;
        for (int t = 0; t < len; t++) {
            float4 v = *(const float4*)(base + (size_t)t * DD);
            acc.x += v.x; acc.y += v.y; acc.z += v.z; acc.w += v.w;
        }
        float inv = 1.f / (float)len;
        acc.x *= inv; acc.y *= inv; acc.z *= inv; acc.w *= inv;
    }
    bf16 h0,h1,h2,h3,l0,l1,l2,l3;
    split_bf16(acc.x,h0,l0); split_bf16(acc.y,h1,l1);
    split_bf16(acc.z,h2,l2); split_bf16(acc.w,h3,l3);
    *(bf162*)(g_ce_hi + base_o + d)     = bf162(h0,h1);
    *(bf162*)(g_ce_hi + base_o + d + 2) = bf162(h2,h3);
    *(bf162*)(g_ce_lo + base_o + d)     = bf162(l0,l1);
    *(bf162*)(g_ce_lo + base_o + d + 2) = bf162(l2,l3);
}

// ---------------- 4) NT tensor-core GEMM, bf16x3, cp.async 4-stage + ldmatrix -------------
// C(M,N) = alpha * A(M,K) @ B(N,K)^T [+ bias]; A,B pre-split hi/lo bf16 row-major.
// MODE 0: fp32 out.  MODE 1: split bf16 hi/lo out.
// BM=BN=128, BK=32, 256 thr = 8 warps (2m x 4n), warp tile 64x32.
// Stage 32KB: A[128 rows][128B: hi halves 0-31 | lo 32-63], B same.
// XOR-16B swizzle (chunk ^= row&7): conflict-free for cp.async stores and ldmatrix.
// MMA issue is TERM-MAJOR (all hh, then hl, then lh): dependent MMAs on the same
// accumulator are 16 apart -> tensor-op latency fully pipelined.

#define MMA_BF16(d, a, b0v, b1v) \
    asm volatile("mma.sync.aligned.m16n8k16.row.col.f32.bf16.bf16.f32 " \
                 "{%0,%1,%2,%3}, {%4,%5,%6,%7}, {%8,%9}, {%0,%1,%2,%3};" \
                 : "+f"(d[0]), "+f"(d[1]), "+f"(d[2]), "+f"(d[3]) \
                 : "r"(a[0]), "r"(a[1]), "r"(a[2]), "r"(a[3]), "r"(b0v), "r"(b1v))

#define LDSM4(r, addr) \
    asm volatile("ldmatrix.sync.aligned.m8n8.x4.shared.b16 {%0,%1,%2,%3}, [%4];" \
                 : "=r"((r)[0]), "=r"((r)[1]), "=r"((r)[2]), "=r"((r)[3]) : "r"(addr))

#define CP_ASYNC16(dst, src) \
    asm volatile("cp.async.cg.shared.global [%0], [%1], 16;" :: "r"(dst), "l"(src))
#define CP_COMMIT() asm volatile("cp.async.commit_group;")
#define CP_WAIT(n)  asm volatile("cp.async.wait_group %0;" :: "n"(n))

template <int MODE>
__global__ __launch_bounds__(256)
void gemm_nt(const bf16* __restrict__ Ah, const bf16* __restrict__ Al,
             const bf16* __restrict__ Bh, const bf16* __restrict__ Bl,
             const float* __restrict__ bias,
             float* __restrict__ Cf, bf16* __restrict__ Ch, bf16* __restrict__ Cl,
             int M, int N, int K,
             long long sA, long long sB, long long sC, float alpha) {
    constexpr int STAGES = 4;
    constexpr int STAGE_BYTES = 32768;
    extern __shared__ char smem[];
    uint32_t sbase = (uint32_t)__cvta_generic_to_shared(smem);

    const int bz = blockIdx.z;
    const int bm = blockIdx.y * 128, bn = blockIdx.x * 128;
    const bf16* pAh = Ah + (size_t)bz * sA + (size_t)bm * K;
    const bf16* pAl = Al + (size_t)bz * sA + (size_t)bm * K;
    const bf16* pBh = Bh + (size_t)bz * sB + (size_t)bn * K;
    const bf16* pBl = Bl + (size_t)bz * sB + (size_t)bn * K;

    const int tid  = threadIdx.x;
    const int wid  = tid >> 5;
    const int lane = tid & 31;
    const int lr = lane >> 2, lc = lane & 3;     // fragment owner coords (epilogue)
    const int mw = (wid & 1) * 64;
    const int nw = (wid >> 1) * 32;

    // ldmatrix per-lane source coords
    const int l8  = lane & 7;
    const int lb  = (lane >> 3) & 1;
    const int lhb = lane >> 4;
    const int arow  = mw + l8 + lb * 8;          // + mi*16
    const int acolh = lhb * 8;                   // + kk (halves); lo: +32
    const uint32_t aswz = (uint32_t)((arow & 7) << 4);
    const int brow  = nw + l8 + lhb * 8;         // + p*16
    const int bcolh = lb * 8;                    // + kk; lo: +32
    const uint32_t bswz = (uint32_t)((brow & 7) << 4);

    float acc[4][4][4];
    #pragma unroll
    for (int mi = 0; mi < 4; mi++)
        #pragma unroll
        for (int ni = 0; ni < 4; ni++)
            #pragma unroll
            for (int r = 0; r < 4; r++) acc[mi][ni][r] = 0.f;

    auto load_tile = [&](int k0, int slot) {
        uint32_t dA = sbase + slot * STAGE_BYTES;
        uint32_t dB = dA + 16384;
        #pragma unroll
        for (int i = 0; i < 4; i++) {
            int j = tid + 256 * i;
            int r = j >> 3, c = j & 7;
            const bf16* src = (c < 4) ? (pAh + (size_t)r * K + k0 + c * 8)
                                      : (pAl + (size_t)r * K + k0 + (c - 4) * 8);
            CP_ASYNC16(dA + r * 128 + ((c ^ (r & 7)) << 4), src);
        }
        #pragma unroll
        for (int i = 0; i < 4; i++) {
            int j = tid + 256 * i;
            int r = j >> 3, c = j & 7;
            const bf16* src = (c < 4) ? (pBh + (size_t)r * K + k0 + c * 8)
                                      : (pBl + (size_t)r * K + k0 + (c - 4) * 8);
            CP_ASYNC16(dB + r * 128 + ((c ^ (r & 7)) << 4), src);
        }
    };

    const int ntiles = K >> 5;
    #pragma unroll
    for (int s = 0; s < STAGES - 1; s++) {
        load_tile(s * 32, s);
        CP_COMMIT();
    }

    for (int i = 0; i < ntiles; i++) {
        CP_WAIT(STAGES - 2);
        __syncthreads();
        int nx = i + STAGES - 1;
        if (nx < ntiles) {
            load_tile(nx * 32, nx % STAGES);
            CP_COMMIT();
        }
        uint32_t sA_ = sbase + (i % STAGES) * STAGE_BYTES;
        uint32_t sB_ = sA_ + 16384;

        #pragma unroll
        for (int ks = 0; ks < 2; ks++) {
            const int kk = ks * 16;
            uint32_t ah[4][4], al[4][4], bh[4][2], bl[4][2];
            // A fragments
            {
                uint32_t ah_addr = sA_ + (uint32_t)arow * 128
                                 + (((uint32_t)(kk + acolh) * 2) ^ aswz);
                uint32_t al_addr = sA_ + (uint32_t)arow * 128
                                 + (((uint32_t)(kk + acolh + 32) * 2) ^ aswz);
                #pragma unroll
                for (int mi = 0; mi < 4; mi++) {
                    LDSM4(ah[mi], ah_addr + mi * (16 * 128));
                    LDSM4(al[mi], al_addr + mi * (16 * 128));
                }
            }
            // B fragments
            {
                uint32_t bh_addr = sB_ + (uint32_t)brow * 128
                                 + (((uint32_t)(kk + bcolh) * 2) ^ bswz);
                uint32_t bl_addr = sB_ + (uint32_t)brow * 128
                                 + (((uint32_t)(kk + bcolh + 32) * 2) ^ bswz);
                #pragma unroll
                for (int p = 0; p < 2; p++) {
                    uint32_t t[4];
                    LDSM4(t, bh_addr + p * (16 * 128));
                    bh[2*p][0] = t[0]; bh[2*p][1] = t[1];
                    bh[2*p+1][0] = t[2]; bh[2*p+1][1] = t[3];
                    LDSM4(t, bl_addr + p * (16 * 128));
                    bl[2*p][0] = t[0]; bl[2*p][1] = t[1];
                    bl[2*p+1][0] = t[2]; bl[2*p+1][1] = t[3];
                }
            }
            // TERM-MAJOR issue: 16 independent MMAs between dependents
            #pragma unroll
            for (int mi = 0; mi < 4; mi++)
                #pragma unroll
                for (int ni = 0; ni < 4; ni++)
                    MMA_BF16(acc[mi][ni], ah[mi], bh[ni][0], bh[ni][1]);  // hi*hi
            #pragma unroll
            for (int mi = 0; mi < 4; mi++)
                #pragma unroll
                for (int ni = 0; ni < 4; ni++)
                    MMA_BF16(acc[mi][ni], ah[mi], bl[ni][0], bl[ni][1]);  // hi*lo
            #pragma unroll
            for (int mi = 0; mi < 4; mi++)
                #pragma unroll
                for (int ni = 0; ni < 4; ni++)
                    MMA_BF16(acc[mi][ni], al[mi], bh[ni][0], bh[ni][1]);  // lo*hi
        }
    }
    CP_WAIT(0);

    // ---- epilogue ----
    float* Cfp = (MODE == 0) ? Cf + (size_t)bz * sC : nullptr;
    bf16*  Chp = (MODE == 1) ? Ch + (size_t)bz * sC : nullptr;
    bf16*  Clp = (MODE == 1) ? Cl + (size_t)bz * sC : nullptr;
    #pragma unroll
    for (int mi = 0; mi < 4; mi++) {
        int row = bm + mw + mi * 16 + lr;
        #pragma unroll
        for (int ni = 0; ni < 4; ni++) {
            int col = bn + nw + ni * 8 + lc * 2;
            float o0 = acc[mi][ni][0] * alpha;
            float o1 = acc[mi][ni][1] * alpha;
            float o2 = acc[mi][ni][2] * alpha;
            float o3 = acc[mi][ni][3] * alpha;
            if (bias) {
                float b0 = bias[col], b1 = bias[col + 1];
                o0 += b0; o1 += b1; o2 += b0; o3 += b1;
            }
            if (MODE == 0) {
                *(float2*)(Cfp + (size_t)row * N + col)       = make_float2(o0, o1);
                *(float2*)(Cfp + (size_t)(row + 8) * N + col) = make_float2(o2, o3);
            } else {
                bf16 h0,h1,h2,h3,l0,l1,l2,l3;
                split_bf16(o0,h0,l0); split_bf16(o1,h1,l1);
                split_bf16(o2,h2,l2); split_bf16(o3,h3,l3);
                *(bf162*)(Chp + (size_t)row * N + col)       = bf162(h0,h1);
                *(bf162*)(Chp + (size_t)(row + 8) * N + col) = bf162(h2,h3);
                *(bf162*)(Clp + (size_t)row * N + col)       = bf162(l0,l1);
                *(bf162*)(Clp + (size_t)(row + 8) * N + col) = bf162(l2,l3);
            }
        }
    }
}

// ---------------- 5) masked row softmax -> probs hi/lo bf16 ----------------
__global__ void softmax_kernel() {
    __shared__ float red[8];
    int row = blockIdx.x;
    int b = row >> 11;
    int nc = g_nchunks[b];
    const float* sc = g_scores + (size_t)row * SS;
    bf16* ph = g_p_hi + (size_t)row * SS;
    bf16* pl = g_p_lo + (size_t)row * SS;

    const float NEG_INF = __int_as_float(0xff800000);
    float x[8];
    float m = NEG_INF;
    #pragma unroll
    for (int i = 0; i < 8; i++) {
        int c = threadIdx.x + i * 256;
        x[i] = (c < nc) ? sc[c] : NEG_INF;
        m = fmaxf(m, x[i]);
    }
    #pragma unroll
    for (int o = 16; o; o >>= 1) m = fmaxf(m, __shfl_xor_sync(0xffffffffu, m, o));
    if ((threadIdx.x & 31) == 0) red[threadIdx.x >> 5] = m;
    __syncthreads();
    m = red[0];
    #pragma unroll
    for (int i = 1; i < 8; i++) m = fmaxf(m, red[i]);
    __syncthreads();

    float s = 0.f;
    #pragma unroll
    for (int i = 0; i < 8; i++) {
        int c = threadIdx.x + i * 256;
        x[i] = (c < nc) ? expf(x[i] - m) : 0.f;
        s += x[i];
    }
    #pragma unroll
    for (int o = 16; o; o >>= 1) s += __shfl_xor_sync(0xffffffffu, s, o);
    if ((threadIdx.x & 31) == 0) red[threadIdx.x >> 5] = s;
    __syncthreads();
    s = 0.f;
    #pragma unroll
    for (int i = 0; i < 8; i++) s += red[i];
    float inv = 1.f / s;

    #pragma unroll
    for (int i = 0; i < 8; i++) {
        int c = threadIdx.x + i * 256;
        bf16 h, l; split_bf16(x[i] * inv, h, l);
        ph[c] = h; pl[c] = l;
    }
}

// ---------------- host side ----------------
static void launch_gemm(int mode,
                        const bf16* Ah, const bf16* Al, const bf16* Bh, const bf16* Bl,
                        const float* bias, float* Cf, bf16* Ch, bf16* Cl,
                        int M, int N, int K,
                        long long sA, long long sB, long long sC, int batch, float alpha) {
    constexpr int SMEM = 4 * 32768;
    dim3 grid(N / 128, M / 128, batch), block(256);
    if (mode == 0) {
        cudaFuncSetAttribute(gemm_nt<0>, cudaFuncAttributeMaxDynamicSharedMemorySize, SMEM);
        gemm_nt<0><<<grid, block, SMEM>>>(Ah, Al, Bh, Bl, bias, Cf, Ch, Cl,
                                          M, N, K, sA, sB, sC, alpha);
    } else {
        cudaFuncSetAttribute(gemm_nt<1>, cudaFuncAttributeMaxDynamicSharedMemorySize, SMEM);
        gemm_nt<1><<<grid, block, SMEM>>>(Ah, Al, Bh, Bl, bias, Cf, Ch, Cl,
                                          M, N, K, sA, sB, sC, alpha);
    }
}

extern "C" void kernel_launch(void* const* d_in, const int* in_sizes, int n_in,
                              void* d_out, int out_size) {
    (void)in_sizes; (void)n_in; (void)out_size;
    const float* h    = (const float*)d_in[0];
    const float* Wlab = (const float*)d_in[1];
    const float* blab = (const float*)d_in[2];
    const float* Wq   = (const float*)d_in[3];
    const float* bq   = (const float*)d_in[4];
    const float* Wk   = (const float*)d_in[5];
    const float* bk   = (const float*)d_in[6];
    const float* Wv   = (const float*)d_in[7];
    const float* bv   = (const float*)d_in[8];
    const float* Wo   = (const float*)d_in[9];
    const float* bo   = (const float*)d_in[10];
    float* out = (float*)d_out;

    bf16 *h_hi,*h_lo,*ce_hi,*ce_lo,*wqh,*wql,*wkh,*wkl,*wvh,*wvl,*woh,*wol;
    bf16 *q_hi,*q_lo,*k_hi,*k_lo,*v_hi,*v_lo,*vT_hi,*vT_lo,*p_hi,*p_lo,*a_hi,*a_lo;
    float* sc;
    cudaGetSymbolAddress((void**)&h_hi,  g_h_hi);  cudaGetSymbolAddress((void**)&h_lo,  g_h_lo);
    cudaGetSymbolAddress((void**)&ce_hi, g_ce_hi); cudaGetSymbolAddress((void**)&ce_lo, g_ce_lo);
    cudaGetSymbolAddress((void**)&wqh, g_wqT_hi);  cudaGetSymbolAddress((void**)&wql, g_wqT_lo);
    cudaGetSymbolAddress((void**)&wkh, g_wkT_hi);  cudaGetSymbolAddress((void**)&wkl, g_wkT_lo);
    cudaGetSymbolAddress((void**)&wvh, g_wvT_hi);  cudaGetSymbolAddress((void**)&wvl, g_wvT_lo);
    cudaGetSymbolAddress((void**)&woh, g_woT_hi);  cudaGetSymbolAddress((void**)&wol, g_woT_lo);
    cudaGetSymbolAddress((void**)&q_hi, g_q_hi);   cudaGetSymbolAddress((void**)&q_lo, g_q_lo);
    cudaGetSymbolAddress((void**)&k_hi, g_k_hi);   cudaGetSymbolAddress((void**)&k_lo, g_k_lo);
    cudaGetSymbolAddress((void**)&v_hi, g_v_hi);   cudaGetSymbolAddress((void**)&v_lo, g_v_lo);
    cudaGetSymbolAddress((void**)&vT_hi, g_vT_hi); cudaGetSymbolAddress((void**)&vT_lo, g_vT_lo);
    cudaGetSymbolAddress((void**)&p_hi, g_p_hi);   cudaGetSymbolAddress((void**)&p_lo, g_p_lo);
    cudaGetSymbolAddress((void**)&a_hi, g_att_hi); cudaGetSymbolAddress((void**)&a_lo, g_att_lo);
    cudaGetSymbolAddress((void**)&sc, g_scores);

    const int M = BB * SS;                        // 16384
    const long long sQ = (long long)SS * DD;      // per-batch q/k/v/att stride
    const long long sS = (long long)SS * SS;      // per-batch scores/probs stride
    const long long sV = (long long)DD * SS;      // per-batch vT stride

    // prep: splits, weight transposes, labels/chunks
    split4_kernel<<<(M * DD / 4) / 256, 256>>>(h, h_hi, h_lo);
    wtrans_kernel<<<dim3(32, 32), dim3(32, 8)>>>(Wq, wqh, wql);
    wtrans_kernel<<<dim3(32, 32), dim3(32, 8)>>>(Wk, wkh, wkl);
    wtrans_kernel<<<dim3(32, 32), dim3(32, 8)>>>(Wv, wvh, wvl);
    wtrans_kernel<<<dim3(32, 32), dim3(32, 8)>>>(Wo, woh, wol);
    label_kernel<<<M / 8, 256>>>(h, Wlab, blab);
    scan_kernel<<<BB, 256>>>();
    chunk_mean_kernel<<<dim3(SS, BB), 256>>>(h);

    // projections (NT vs transposed-split weights) -> hi/lo outputs
    launch_gemm(1, h_hi,  h_lo,  wqh, wql, bq, nullptr, q_hi, q_lo, M, DD, DD, 0, 0, 0, 1, 1.f);
    launch_gemm(1, ce_hi, ce_lo, wkh, wkl, bk, nullptr, k_hi, k_lo, M, DD, DD, 0, 0, 0, 1, 1.f);
    launch_gemm(1, ce_hi, ce_lo, wvh, wvl, bv, nullptr, v_hi, v_lo, M, DD, DD, 0, 0, 0, 1, 1.f);
    vtrans_kernel<<<dim3(DD / 32, SS / 32, BB), dim3(32, 8)>>>();

    // scores[b] = (q[b] @ k[b]^T) / 32  -> fp32
    launch_gemm(0, q_hi, q_lo, k_hi, k_lo, nullptr, sc, nullptr, nullptr,
                SS, SS, DD, sQ, sQ, sS, BB, 0.03125f);

    softmax_kernel<<<M, 256>>>();   // -> probs hi/lo (masked cols exactly 0)

    // attended[b] = probs[b] @ vT[b]^T -> hi/lo
    launch_gemm(1, p_hi, p_lo, vT_hi, vT_lo, nullptr, nullptr, a_hi, a_lo,
                SS, DD, SS, sS, sV, sQ, BB, 1.f);

    // out = att @ Wo^T + bo -> fp32 d_out
    launch_gemm(0, a_hi, a_lo, woh, wol, bo, out, nullptr, nullptr,
                M, DD, DD, 0, 0, 0, 1, 1.f);
}

// round 9
// speedup vs baseline: 3.3768x; 1.3892x over previous
#include <cuda_runtime.h>
#include <cuda_bf16.h>
#include <cstdint>
#include <cstddef>

#define BB 8
#define SS 2048
#define DD 1024
// DC == DD == 1024, scale = 1/sqrt(1024) = 1/32
// int8 2-digit scheme: x ~= S * X / 32512, X = 256*d0 + d1, d0,d1 in int8.

typedef __nv_bfloat16 bf16;

// ---------------- scratch (static device globals; no allocation) ----------------
__device__ int    g_labels[BB * SS];
__device__ int    g_chunk_start[BB * SS];
__device__ int    g_chunk_len[BB * SS];
__device__ int    g_nchunks[BB];

// digit arrays + scales
__device__ int8_t g_h_d0[(size_t)BB * SS * DD],  g_h_d1[(size_t)BB * SS * DD];
__device__ float  g_Sh[BB * SS];
__device__ int8_t g_ce_d0[(size_t)BB * SS * DD], g_ce_d1[(size_t)BB * SS * DD];
__device__ float  g_Sce[BB * SS];
__device__ int8_t g_wq_d0[DD * DD], g_wq_d1[DD * DD];
__device__ int8_t g_wk_d0[DD * DD], g_wk_d1[DD * DD];
__device__ int8_t g_wv_d0[DD * DD], g_wv_d1[DD * DD];
__device__ int8_t g_wo_d0[DD * DD], g_wo_d1[DD * DD];
__device__ float  g_Swq[DD], g_Swk[DD], g_Swv[DD], g_Swo[DD];
__device__ int8_t g_q_d0[(size_t)BB * SS * DD],  g_q_d1[(size_t)BB * SS * DD];
__device__ float  g_Sq[BB * SS];
__device__ int8_t g_k_d0[(size_t)BB * SS * DD],  g_k_d1[(size_t)BB * SS * DD];
__device__ float  g_Sk[BB * SS];
__device__ int8_t g_vT_d0[(size_t)BB * DD * SS], g_vT_d1[(size_t)BB * DD * SS];
__device__ float  g_SvT[BB * DD];
__device__ int8_t g_p_d0[(size_t)BB * SS * SS],  g_p_d1[(size_t)BB * SS * SS];
__device__ float  g_SP[BB * SS];
__device__ int8_t g_at_d0[(size_t)BB * SS * DD], g_at_d1[(size_t)BB * SS * DD];
__device__ float  g_Sat[BB * SS];

// fp32 intermediates
__device__ float  g_qf[(size_t)BB * SS * DD];
__device__ float  g_kf[(size_t)BB * SS * DD];
__device__ float  g_vf[(size_t)BB * SS * DD];
__device__ float  g_vTf[(size_t)BB * DD * SS];
__device__ float  g_atf[(size_t)BB * SS * DD];
__device__ float  g_scores[(size_t)BB * SS * SS];   // 128 MB

__device__ __forceinline__ void q2dig(float x, float sc, int8_t& q0, int8_t& q1) {
    int X = __float2int_rn(x * sc);
    int d0 = (X + 128) >> 8;         // arithmetic shift: floor((X+128)/256)
    q0 = (int8_t)d0;
    q1 = (int8_t)(X - (d0 << 8));
}

// ---------------- 1) labels = argmax(h @ W_lab + b_lab) (fp32: argmax cliff) ----------------
__global__ void label_kernel(const float* __restrict__ h,
                             const float* __restrict__ Wlab,
                             const float* __restrict__ blab) {
    int tok  = blockIdx.x * (blockDim.x >> 5) + (threadIdx.x >> 5);
    int lane = threadIdx.x & 31;
    const float* hr = h + (size_t)tok * DD;
    float a0 = 0.f, a1 = 0.f, a2 = 0.f, a3 = 0.f;
    for (int k = lane; k < DD; k += 32) {
        float hv = hr[k];
        float4 w = *(const float4*)(Wlab + k * 4);
        a0 += hv * w.x; a1 += hv * w.y; a2 += hv * w.z; a3 += hv * w.w;
    }
    #pragma unroll
    for (int o = 16; o; o >>= 1) {
        a0 += __shfl_down_sync(0xffffffffu, a0, o);
        a1 += __shfl_down_sync(0xffffffffu, a1, o);
        a2 += __shfl_down_sync(0xffffffffu, a2, o);
        a3 += __shfl_down_sync(0xffffffffu, a3, o);
    }
    if (lane == 0) {
        float lg[4] = { a0 + blab[0], a1 + blab[1], a2 + blab[2], a3 + blab[3] };
        int best = 0; float bv = lg[0];
        #pragma unroll
        for (int j = 1; j < 4; j++) if (lg[j] > bv) { bv = lg[j]; best = j; }
        g_labels[tok] = best;
    }
}

// ---------------- 2) sequential BIOS chunk scan ----------------
__global__ void scan_kernel() {
    __shared__ int lab[SS];
    int b = blockIdx.x;
    for (int s = threadIdx.x; s < SS; s += blockDim.x) lab[s] = g_labels[b * SS + s];
    __syncthreads();
    if (threadIdx.x == 0) {
        int* cs = g_chunk_start + b * SS;
        int* cl = g_chunk_len   + b * SS;
        bool open = false; int c = -1;
        for (int s = 0; s < SS; s++) {
            int l = lab[s];
            bool cont = (l == 1) && open;
            open = (l == 0) || cont;
            if (!cont) {
                if (c >= 0) cl[c] = s - cs[c];
                c++; cs[c] = s;
            }
        }
        cl[c] = SS - cs[c];
        g_nchunks[b] = c + 1;
    }
}

// ---------------- 3) per-chunk mean -> row-quantized int8 digits ----------------
__global__ void chunk_meanq_kernel(const float* __restrict__ h) {
    __shared__ float red[8];
    int b = blockIdx.y, c = blockIdx.x;
    int row = b * SS + c;
    int d = threadIdx.x * 4;
    int nc = g_nchunks[b];
    float4 acc = make_float4(0.f, 0.f, 0.f, 0.f);
    if (c < nc) {
        int st  = g_chunk_start[b * SS + c];
        int len = g_chunk_len[b * SS + c];
        const float* base = h + ((size_t)b * SS + st) * DD + d;
        for (int t = 0; t < len; t++) {
            float4 v = *(const float4*)(base + (size_t)t * DD);
            acc.x += v.x; acc.y += v.y; acc.z += v.z; acc.w += v.w;
        }
        float inv = 1.f / (float)len;
        acc.x *= inv; acc.y *= inv; acc.z *= inv; acc.w *= inv;
    }
    // block-wide max |.|
    float m = fmaxf(fmaxf(fabsf(acc.x), fabsf(acc.y)), fmaxf(fabsf(acc.z), fabsf(acc.w)));
    #pragma unroll
    for (int o = 16; o; o >>= 1) m = fmaxf(m, __shfl_xor_sync(0xffffffffu, m, o));
    if ((threadIdx.x & 31) == 0) red[threadIdx.x >> 5] = m;
    __syncthreads();
    float M = red[0];
    #pragma unroll
    for (int i = 1; i < 8; i++) M = fmaxf(M, red[i]);
    float sc = (M > 0.f) ? 32512.f / M : 0.f;
    if (threadIdx.x == 0) g_Sce[row] = (M > 0.f) ? M : 1.f;
    int8_t a0,a1,b0_,b1_,c0,c1,d0_,d1_;
    q2dig(acc.x, sc, a0, a1); q2dig(acc.y, sc, b0_, b1_);
    q2dig(acc.z, sc, c0, c1); q2dig(acc.w, sc, d0_, d1_);
    *(char4*)(g_ce_d0 + (size_t)row * DD + d) = make_char4(a0, b0_, c0, d0_);
    *(char4*)(g_ce_d1 + (size_t)row * DD + d) = make_char4(a1, b1_, c1, d1_);
}

// ---------------- 4) generic row quantizer: fp32 [rows][L] -> digits + per-row scale ------
__global__ void quant_rows_kernel(const float* __restrict__ X, int L,
                                  int8_t* __restrict__ D0, int8_t* __restrict__ D1,
                                  float* __restrict__ S) {
    int row  = blockIdx.x * 8 + (threadIdx.x >> 5);
    int lane = threadIdx.x & 31;
    const float* xr = X + (size_t)row * L;
    int iters = L >> 7;                       // 128 floats per warp per iter
    float m = 0.f;
    for (int j = 0; j < iters; j++) {
        float4 v = *(const float4*)(xr + lane * 4 + j * 128);
        m = fmaxf(m, fmaxf(fmaxf(fabsf(v.x), fabsf(v.y)), fmaxf(fabsf(v.z), fabsf(v.w))));
    }
    #pragma unroll
    for (int o = 16; o; o >>= 1) m = fmaxf(m, __shfl_xor_sync(0xffffffffu, m, o));
    m = __shfl_sync(0xffffffffu, m, 0);
    if (lane == 0) S[row] = (m > 0.f) ? m : 1.f;
    float sc = (m > 0.f) ? 32512.f / m : 0.f;
    for (int j = 0; j < iters; j++) {
        float4 v = *(const float4*)(xr + lane * 4 + j * 128);
        int8_t a0,a1,b0_,b1_,c0,c1,d0_,d1_;
        q2dig(v.x, sc, a0, a1); q2dig(v.y, sc, b0_, b1_);
        q2dig(v.z, sc, c0, c1); q2dig(v.w, sc, d0_, d1_);
        *(char4*)(D0 + (size_t)row * L + lane * 4 + j * 128) = make_char4(a0, b0_, c0, d0_);
        *(char4*)(D1 + (size_t)row * L + lane * 4 + j * 128) = make_char4(a1, b1_, c1, d1_);
    }
}

// ---------------- 4b) weight col-max + transpose-quantize: W(K,N) -> WT(N,K) digits -------
__global__ void colmax_kernel(const float* __restrict__ W, float* __restrict__ S) {
    int c = blockIdx.x * 256 + threadIdx.x;
    float m = 0.f;
    for (int r = 0; r < DD; r++) m = fmaxf(m, fabsf(W[(size_t)r * DD + c]));
    S[c] = (m > 0.f) ? m : 1.f;
}

__global__ void wtransq_kernel(const float* __restrict__ W, const float* __restrict__ S,
                               int8_t* __restrict__ D0, int8_t* __restrict__ D1) {
    __shared__ float t[32][33];
    int tx = threadIdx.x, ty = threadIdx.y;          // (32, 8)
    int x = blockIdx.x * 32 + tx, y = blockIdx.y * 32 + ty;
    #pragma unroll
    for (int k = 0; k < 4; k++) t[ty + 8*k][tx] = W[(size_t)(y + 8*k) * DD + x];
    __syncthreads();
    int x2 = blockIdx.y * 32 + tx, y2 = blockIdx.x * 32 + ty;
    #pragma unroll
    for (int k = 0; k < 4; k++) {
        int n = y2 + 8*k;                            // WT row = W column
        float v = t[tx][ty + 8*k];
        float sc = 32512.f / S[n];
        int8_t q0, q1; q2dig(v, sc, q0, q1);
        D0[(size_t)n * DD + x2] = q0;
        D1[(size_t)n * DD + x2] = q1;
    }
}

// ---------------- 4c) fp32 transpose: v(S,D) -> vT(D,S), per batch ----------------
__global__ void vtransf_kernel() {
    __shared__ float t[32][33];
    int b = blockIdx.z;
    int tx = threadIdx.x, ty = threadIdx.y;          // (32, 8)
    const float* vf = g_vf + (size_t)b * SS * DD;
    float* o = g_vTf + (size_t)b * DD * SS;
    int d0 = blockIdx.x * 32, s0 = blockIdx.y * 32;
    #pragma unroll
    for (int k = 0; k < 4; k++)
        t[ty + 8*k][tx] = vf[(size_t)(s0 + ty + 8*k) * DD + d0 + tx];
    __syncthreads();
    #pragma unroll
    for (int k = 0; k < 4; k++)
        o[(size_t)(d0 + ty + 8*k) * SS + s0 + tx] = t[tx][ty + 8*k];
}

// ---------------- 5) int8 NT tensor-core GEMM (2-digit, 3 terms), cp.async 4-stage --------
// C(M,N) = alpha*SA[r]*SB[c]/32512^2 * (65536*G00 + 256*(G01+G10)) [+ bias]
// A digits (M,K), B digits (N,K) row-major.  BM=BN=128, BK=64 int8.
// Stage 32KB: A[128 rows][128B: d0 0-63 | d1 64-127], B same; XOR-16B swizzle.
// ldmatrix/IMMA addressing is byte-isomorphic to the validated bf16 kernel (1 half = 2 s8).

#define MMA_S8(d, a, b0v, b1v) \
    asm volatile("mma.sync.aligned.m16n8k32.row.col.s32.s8.s8.s32 " \
                 "{%0,%1,%2,%3}, {%4,%5,%6,%7}, {%8,%9}, {%0,%1,%2,%3};" \
                 : "+r"((d)[0]), "+r"((d)[1]), "+r"((d)[2]), "+r"((d)[3]) \
                 : "r"((a)[0]), "r"((a)[1]), "r"((a)[2]), "r"((a)[3]), "r"(b0v), "r"(b1v))

#define LDSM4(r, addr) \
    asm volatile("ldmatrix.sync.aligned.m8n8.x4.shared.b16 {%0,%1,%2,%3}, [%4];" \
                 : "=r"((r)[0]), "=r"((r)[1]), "=r"((r)[2]), "=r"((r)[3]) : "r"(addr))

#define CP_ASYNC16(dst, src) \
    asm volatile("cp.async.cg.shared.global [%0], [%1], 16;" :: "r"(dst), "l"(src))
#define CP_COMMIT() asm volatile("cp.async.commit_group;")
#define CP_WAIT(n)  asm volatile("cp.async.wait_group %0;" :: "n"(n))

__global__ __launch_bounds__(256)
void gemm_s8(const int8_t* __restrict__ Ad0, const int8_t* __restrict__ Ad1,
             const int8_t* __restrict__ Bd0, const int8_t* __restrict__ Bd1,
             const float* __restrict__ SA, const float* __restrict__ SB,
             const float* __restrict__ bias, float* __restrict__ Cf,
             int M, int N, int K,
             long long sA, long long sB, long long sC,
             long long sSA, long long sSB, float alpha) {
    constexpr int STAGES = 4;
    constexpr int STAGE_BYTES = 32768;
    extern __shared__ char smem[];
    uint32_t sbase = (uint32_t)__cvta_generic_to_shared(smem);

    const int bz = blockIdx.z;
    const int bm = blockIdx.y * 128, bn = blockIdx.x * 128;
    const int8_t* pA0 = Ad0 + (size_t)bz * sA + (size_t)bm * K;
    const int8_t* pA1 = Ad1 + (size_t)bz * sA + (size_t)bm * K;
    const int8_t* pB0 = Bd0 + (size_t)bz * sB + (size_t)bn * K;
    const int8_t* pB1 = Bd1 + (size_t)bz * sB + (size_t)bn * K;
    const float* SAb = SA + (size_t)bz * sSA;
    const float* SBb = SB + (size_t)bz * sSB;

    const int tid  = threadIdx.x;
    const int wid  = tid >> 5;
    const int lane = tid & 31;
    const int lr = lane >> 2, lc = lane & 3;
    const int mw = (wid & 1) * 64;
    const int nw = (wid >> 1) * 32;

    // ldmatrix per-lane coords (identical to validated bf16 layout; "half" = 2 s8)
    const int l8  = lane & 7;
    const int lb  = (lane >> 3) & 1;
    const int lhb = lane >> 4;
    const int arow  = mw + l8 + lb * 8;
    const int acolh = lhb * 8;
    const uint32_t aswz = (uint32_t)((arow & 7) << 4);
    const int brow  = nw + l8 + lhb * 8;
    const int bcolh = lb * 8;
    const uint32_t bswz = (uint32_t)((brow & 7) << 4);

    int acc0[4][4][4], accX[4][4][4];
    #pragma unroll
    for (int mi = 0; mi < 4; mi++)
        #pragma unroll
        for (int ni = 0; ni < 4; ni++)
            #pragma unroll
            for (int r = 0; r < 4; r++) { acc0[mi][ni][r] = 0; accX[mi][ni][r] = 0; }

    auto load_tile = [&](int k0, int slot) {   // k0 in int8 elems (multiple of 64)
        uint32_t dA = sbase + slot * STAGE_BYTES;
        uint32_t dB = dA + 16384;
        #pragma unroll
        for (int i = 0; i < 4; i++) {
            int j = tid + 256 * i;
            int r = j >> 3, c = j & 7;
            const int8_t* src = (c < 4) ? (pA0 + (size_t)r * K + k0 + c * 16)
                                        : (pA1 + (size_t)r * K + k0 + (c - 4) * 16);
            CP_ASYNC16(dA + r * 128 + ((c ^ (r & 7)) << 4), src);
        }
        #pragma unroll
        for (int i = 0; i < 4; i++) {
            int j = tid + 256 * i;
            int r = j >> 3, c = j & 7;
            const int8_t* src = (c < 4) ? (pB0 + (size_t)r * K + k0 + c * 16)
                                        : (pB1 + (size_t)r * K + k0 + (c - 4) * 16);
            CP_ASYNC16(dB + r * 128 + ((c ^ (r & 7)) << 4), src);
        }
    };

    const int ntiles = K >> 6;                 // 64 int8 per tile
    #pragma unroll
    for (int s = 0; s < STAGES - 1; s++) {
        load_tile(s * 64, s);
        CP_COMMIT();
    }

    for (int i = 0; i < ntiles; i++) {
        CP_WAIT(STAGES - 2);
        __syncthreads();
        int nx = i + STAGES - 1;
        if (nx < ntiles) {
            load_tile(nx * 64, nx % STAGES);
            CP_COMMIT();
        }
        uint32_t sA_ = sbase + (i % STAGES) * STAGE_BYTES;
        uint32_t sB_ = sA_ + 16384;

        #pragma unroll
        for (int g = 0; g < 2; g++) {          // two k32 groups per 64-K tile
            const int kk = g * 16;             // offset in 16-bit halves
            uint32_t a0f[4][4], a1f[4][4], b0f[4][2], b1f[4][2];
            {
                uint32_t a0_addr = sA_ + (uint32_t)arow * 128
                                 + (((uint32_t)(kk + acolh) * 2) ^ aswz);
                uint32_t a1_addr = sA_ + (uint32_t)arow * 128
                                 + (((uint32_t)(kk + acolh + 32) * 2) ^ aswz);
                #pragma unroll
                for (int mi = 0; mi < 4; mi++) {
                    LDSM4(a0f[mi], a0_addr + mi * (16 * 128));
                    LDSM4(a1f[mi], a1_addr + mi * (16 * 128));
                }
            }
            {
                uint32_t b0_addr = sB_ + (uint32_t)brow * 128
                                 + (((uint32_t)(kk + bcolh) * 2) ^ bswz);
                uint32_t b1_addr = sB_ + (uint32_t)brow * 128
                                 + (((uint32_t)(kk + bcolh + 32) * 2) ^ bswz);
                #pragma unroll
                for (int p = 0; p < 2; p++) {
                    uint32_t t[4];
                    LDSM4(t, b0_addr + p * (16 * 128));
                    b0f[2*p][0] = t[0]; b0f[2*p][1] = t[1];
                    b0f[2*p+1][0] = t[2]; b0f[2*p+1][1] = t[3];
                    LDSM4(t, b1_addr + p * (16 * 128));
                    b1f[2*p][0] = t[0]; b1f[2*p][1] = t[1];
                    b1f[2*p+1][0] = t[2]; b1f[2*p+1][1] = t[3];
                }
            }
            #pragma unroll
            for (int mi = 0; mi < 4; mi++)
                #pragma unroll
                for (int ni = 0; ni < 4; ni++)
                    MMA_S8(acc0[mi][ni], a0f[mi], b0f[ni][0], b0f[ni][1]);  // d0*d0
            #pragma unroll
            for (int mi = 0; mi < 4; mi++)
                #pragma unroll
                for (int ni = 0; ni < 4; ni++)
                    MMA_S8(accX[mi][ni], a0f[mi], b1f[ni][0], b1f[ni][1]);  // d0*d1
            #pragma unroll
            for (int mi = 0; mi < 4; mi++)
                #pragma unroll
                for (int ni = 0; ni < 4; ni++)
                    MMA_S8(accX[mi][ni], a1f[mi], b0f[ni][0], b0f[ni][1]);  // d1*d0
        }
    }
    CP_WAIT(0);

    // ---- epilogue: combine digits, apply scales/alpha/bias, fp32 stores ----
    const float qs = alpha * (1.f / (32512.f * 32512.f));
    float* Cp = Cf + (size_t)bz * sC;
    #pragma unroll
    for (int mi = 0; mi < 4; mi++) {
        int r0 = bm + mw + mi * 16 + lr;
        float sr0 = SAb[r0] * qs, sr1 = SAb[r0 + 8] * qs;
        #pragma unroll
        for (int ni = 0; ni < 4; ni++) {
            int c0 = bn + nw + ni * 8 + lc * 2;
            float sb0 = SBb[c0], sb1 = SBb[c0 + 1];
            float o0 = (65536.f * (float)acc0[mi][ni][0] + 256.f * (float)accX[mi][ni][0]) * sr0 * sb0;
            float o1 = (65536.f * (float)acc0[mi][ni][1] + 256.f * (float)accX[mi][ni][1]) * sr0 * sb1;
            float o2 = (65536.f * (float)acc0[mi][ni][2] + 256.f * (float)accX[mi][ni][2]) * sr1 * sb0;
            float o3 = (65536.f * (float)acc0[mi][ni][3] + 256.f * (float)accX[mi][ni][3]) * sr1 * sb1;
            if (bias) {
                float b0 = bias[c0], b1 = bias[c0 + 1];
                o0 += b0; o1 += b1; o2 += b0; o3 += b1;
            }
            *(float2*)(Cp + (size_t)r0 * N + c0)       = make_float2(o0, o1);
            *(float2*)(Cp + (size_t)(r0 + 8) * N + c0) = make_float2(o2, o3);
        }
    }
}

// ---------------- 6) masked row softmax -> probs digits (scale = 1/s, free) ----------------
__global__ void softmax_kernel() {
    __shared__ float red[8];
    int row = blockIdx.x;
    int b = row >> 11;
    int nc = g_nchunks[b];
    const float* sc = g_scores + (size_t)row * SS;
    int8_t* pd0 = g_p_d0 + (size_t)row * SS;
    int8_t* pd1 = g_p_d1 + (size_t)row * SS;

    const float NEG_INF = __int_as_float(0xff800000);
    float x[8];
    float m = NEG_INF;
    #pragma unroll
    for (int i = 0; i < 8; i++) {
        int c = threadIdx.x + i * 256;
        x[i] = (c < nc) ? sc[c] : NEG_INF;
        m = fmaxf(m, x[i]);
    }
    #pragma unroll
    for (int o = 16; o; o >>= 1) m = fmaxf(m, __shfl_xor_sync(0xffffffffu, m, o));
    if ((threadIdx.x & 31) == 0) red[threadIdx.x >> 5] = m;
    __syncthreads();
    m = red[0];
    #pragma unroll
    for (int i = 1; i < 8; i++) m = fmaxf(m, red[i]);
    __syncthreads();

    float s = 0.f;
    #pragma unroll
    for (int i = 0; i < 8; i++) {
        int c = threadIdx.x + i * 256;
        x[i] = (c < nc) ? expf(x[i] - m) : 0.f;   // in [0,1], max is exactly 1
        s += x[i];
    }
    #pragma unroll
    for (int o = 16; o; o >>= 1) s += __shfl_xor_sync(0xffffffffu, s, o);
    if ((threadIdx.x & 31) == 0) red[threadIdx.x >> 5] = s;
    __syncthreads();
    s = 0.f;
    #pragma unroll
    for (int i = 0; i < 8; i++) s += red[i];
    float inv = 1.f / s;
    if (threadIdx.x == 0) g_SP[row] = inv;        // p = inv * (X/32512)

    #pragma unroll
    for (int i = 0; i < 8; i++) {
        int c = threadIdx.x + i * 256;
        int8_t q0, q1; q2dig(x[i], 32512.f, q0, q1);
        pd0[c] = q0; pd1[c] = q1;
    }
}

// ---------------- host side ----------------
static void launch_gemm(const int8_t* Ad0, const int8_t* Ad1,
                        const int8_t* Bd0, const int8_t* Bd1,
                        const float* SA, const float* SB,
                        const float* bias, float* Cf,
                        int M, int N, int K,
                        long long sA, long long sB, long long sC,
                        long long sSA, long long sSB, int batch, float alpha) {
    constexpr int SMEM = 4 * 32768;
    dim3 grid(N / 128, M / 128, batch), block(256);
    cudaFuncSetAttribute(gemm_s8, cudaFuncAttributeMaxDynamicSharedMemorySize, SMEM);
    gemm_s8<<<grid, block, SMEM>>>(Ad0, Ad1, Bd0, Bd1, SA, SB, bias, Cf,
                                   M, N, K, sA, sB, sC, sSA, sSB, alpha);
}

extern "C" void kernel_launch(void* const* d_in, const int* in_sizes, int n_in,
                              void* d_out, int out_size) {
    (void)in_sizes; (void)n_in; (void)out_size;
    const float* h    = (const float*)d_in[0];
    const float* Wlab = (const float*)d_in[1];
    const float* blab = (const float*)d_in[2];
    const float* Wq   = (const float*)d_in[3];
    const float* bq   = (const float*)d_in[4];
    const float* Wk   = (const float*)d_in[5];
    const float* bk   = (const float*)d_in[6];
    const float* Wv   = (const float*)d_in[7];
    const float* bv   = (const float*)d_in[8];
    const float* Wo   = (const float*)d_in[9];
    const float* bo   = (const float*)d_in[10];
    float* out = (float*)d_out;

    int8_t *hd0,*hd1,*ced0,*ced1,*wqd0,*wqd1,*wkd0,*wkd1,*wvd0,*wvd1,*wod0,*wod1;
    int8_t *qd0,*qd1,*kd0,*kd1,*vTd0,*vTd1,*pd0,*pd1,*atd0,*atd1;
    float *Sh,*Sce,*Swq,*Swk,*Swv,*Swo,*Sq,*Sk,*SvT,*SP,*Sat;
    float *qf,*kf,*vf,*vTf,*atf,*scb;
    cudaGetSymbolAddress((void**)&hd0, g_h_d0);   cudaGetSymbolAddress((void**)&hd1, g_h_d1);
    cudaGetSymbolAddress((void**)&ced0, g_ce_d0); cudaGetSymbolAddress((void**)&ced1, g_ce_d1);
    cudaGetSymbolAddress((void**)&wqd0, g_wq_d0); cudaGetSymbolAddress((void**)&wqd1, g_wq_d1);
    cudaGetSymbolAddress((void**)&wkd0, g_wk_d0); cudaGetSymbolAddress((void**)&wkd1, g_wk_d1);
    cudaGetSymbolAddress((void**)&wvd0, g_wv_d0); cudaGetSymbolAddress((void**)&wvd1, g_wv_d1);
    cudaGetSymbolAddress((void**)&wod0, g_wo_d0); cudaGetSymbolAddress((void**)&wod1, g_wo_d1);
    cudaGetSymbolAddress((void**)&qd0, g_q_d0);   cudaGetSymbolAddress((void**)&qd1, g_q_d1);
    cudaGetSymbolAddress((void**)&kd0, g_k_d0);   cudaGetSymbolAddress((void**)&kd1, g_k_d1);
    cudaGetSymbolAddress((void**)&vTd0, g_vT_d0); cudaGetSymbolAddress((void**)&vTd1, g_vT_d1);
    cudaGetSymbolAddress((void**)&pd0, g_p_d0);   cudaGetSymbolAddress((void**)&pd1, g_p_d1);
    cudaGetSymbolAddress((void**)&atd0, g_at_d0); cudaGetSymbolAddress((void**)&atd1, g_at_d1);
    cudaGetSymbolAddress((void**)&Sh, g_Sh);   cudaGetSymbolAddress((void**)&Sce, g_Sce);
    cudaGetSymbolAddress((void**)&Swq, g_Swq); cudaGetSymbolAddress((void**)&Swk, g_Swk);
    cudaGetSymbolAddress((void**)&Swv, g_Swv); cudaGetSymbolAddress((void**)&Swo, g_Swo);
    cudaGetSymbolAddress((void**)&Sq, g_Sq);   cudaGetSymbolAddress((void**)&Sk, g_Sk);
    cudaGetSymbolAddress((void**)&SvT, g_SvT); cudaGetSymbolAddress((void**)&SP, g_SP);
    cudaGetSymbolAddress((void**)&Sat, g_Sat);
    cudaGetSymbolAddress((void**)&qf, g_qf);   cudaGetSymbolAddress((void**)&kf, g_kf);
    cudaGetSymbolAddress((void**)&vf, g_vf);   cudaGetSymbolAddress((void**)&vTf, g_vTf);
    cudaGetSymbolAddress((void**)&atf, g_atf); cudaGetSymbolAddress((void**)&scb, g_scores);

    const int M = BB * SS;                        // 16384
    const long long sQ = (long long)SS * DD;
    const long long sS = (long long)SS * SS;
    const long long sV = (long long)DD * SS;

    // prep: labels/chunks, quantize h + weights, chunk means (quantized in-kernel)
    label_kernel<<<M / 8, 256>>>(h, Wlab, blab);
    scan_kernel<<<BB, 256>>>();
    quant_rows_kernel<<<M / 8, 256>>>(h, DD, hd0, hd1, Sh);
    colmax_kernel<<<4, 256>>>(Wq, Swq);
    colmax_kernel<<<4, 256>>>(Wk, Swk);
    colmax_kernel<<<4, 256>>>(Wv, Swv);
    colmax_kernel<<<4, 256>>>(Wo, Swo);
    wtransq_kernel<<<dim3(32, 32), dim3(32, 8)>>>(Wq, Swq, wqd0, wqd1);
    wtransq_kernel<<<dim3(32, 32), dim3(32, 8)>>>(Wk, Swk, wkd0, wkd1);
    wtransq_kernel<<<dim3(32, 32), dim3(32, 8)>>>(Wv, Swv, wvd0, wvd1);
    wtransq_kernel<<<dim3(32, 32), dim3(32, 8)>>>(Wo, Swo, wod0, wod1);
    chunk_meanq_kernel<<<dim3(SS, BB), 256>>>(h);

    // projections: int8 GEMMs -> fp32, then row-quantize
    launch_gemm(hd0, hd1, wqd0, wqd1, Sh, Swq, bq, qf, M, DD, DD, 0,0,0, 0,0, 1, 1.f);
    launch_gemm(ced0, ced1, wkd0, wkd1, Sce, Swk, bk, kf, M, DD, DD, 0,0,0, 0,0, 1, 1.f);
    launch_gemm(ced0, ced1, wvd0, wvd1, Sce, Swv, bv, vf, M, DD, DD, 0,0,0, 0,0, 1, 1.f);
    quant_rows_kernel<<<M / 8, 256>>>(qf, DD, qd0, qd1, Sq);
    quant_rows_kernel<<<M / 8, 256>>>(kf, DD, kd0, kd1, Sk);
    vtransf_kernel<<<dim3(DD / 32, SS / 32, BB), dim3(32, 8)>>>();
    quant_rows_kernel<<<(BB * DD) / 8, 256>>>(vTf, SS, vTd0, vTd1, SvT);

    // scores[b] = (q[b] @ k[b]^T) / 32 -> fp32
    launch_gemm(qd0, qd1, kd0, kd1, Sq, Sk, nullptr, scb,
                SS, SS, DD, sQ, sQ, sS, SS, SS, BB, 0.03125f);

    softmax_kernel<<<M, 256>>>();   // -> probs digits + SP (masked cols exactly 0)

    // attended[b] = probs[b] @ vT[b]^T -> fp32, then row-quantize
    launch_gemm(pd0, pd1, vTd0, vTd1, SP, SvT, nullptr, atf,
                SS, DD, SS, sS, sV, sQ, SS, DD, BB, 1.f);
    quant_rows_kernel<<<M / 8, 256>>>(atf, DD, atd0, atd1, Sat);

    // out = att @ Wo^T + bo -> fp32 d_out
    launch_gemm(atd0, atd1, wod0, wod1, Sat, Swo, bo, out, M, DD, DD, 0,0,0, 0,0, 1, 1.f);
}

// round 10
// speedup vs baseline: 3.6320x; 1.0756x over previous
#include <cuda_runtime.h>
#include <cuda_bf16.h>
#include <cstdint>
#include <cstddef>

#define BB 8
#define SS 2048
#define DD 1024
// DC == DD == 1024, scale = 1/sqrt(1024) = 1/32
// int8 2-digit scheme: x ~= S * X / 32512, X = 256*d0 + d1, d0,d1 in int8.

typedef __nv_bfloat16 bf16;

// ---------------- scratch (static device globals; no allocation) ----------------
__device__ int    g_labels[BB * SS];
__device__ int    g_chunk_start[BB * SS];
__device__ int    g_chunk_len[BB * SS];
__device__ int    g_nchunks[BB];
__device__ float  g_cmax_part[8 * DD];

// digit arrays + scales
__device__ int8_t g_h_d0[(size_t)BB * SS * DD],  g_h_d1[(size_t)BB * SS * DD];
__device__ float  g_Sh[BB * SS];
__device__ int8_t g_ce_d0[(size_t)BB * SS * DD], g_ce_d1[(size_t)BB * SS * DD];
__device__ float  g_Sce[BB * SS];
__device__ int8_t g_wq_d0[DD * DD], g_wq_d1[DD * DD];
__device__ int8_t g_wk_d0[DD * DD], g_wk_d1[DD * DD];
__device__ int8_t g_wv_d0[DD * DD], g_wv_d1[DD * DD];
__device__ int8_t g_wo_d0[DD * DD], g_wo_d1[DD * DD];
__device__ float  g_Swq[DD], g_Swk[DD], g_Swv[DD], g_Swo[DD];
__device__ int8_t g_q_d0[(size_t)BB * SS * DD],  g_q_d1[(size_t)BB * SS * DD];
__device__ float  g_Sq[BB * SS];
__device__ int8_t g_k_d0[(size_t)BB * SS * DD],  g_k_d1[(size_t)BB * SS * DD];
__device__ float  g_Sk[BB * SS];
__device__ int8_t g_vT_d0[(size_t)BB * DD * SS], g_vT_d1[(size_t)BB * DD * SS];
__device__ float  g_SvT[BB * DD];
__device__ int8_t g_p_d0[(size_t)BB * SS * SS],  g_p_d1[(size_t)BB * SS * SS];
__device__ float  g_SP[BB * SS];
__device__ int8_t g_at_d0[(size_t)BB * SS * DD], g_at_d1[(size_t)BB * SS * DD];
__device__ float  g_Sat[BB * SS];

// fp32 intermediates
__device__ float  g_qf[(size_t)BB * SS * DD];
__device__ float  g_kf[(size_t)BB * SS * DD];
__device__ float  g_vf[(size_t)BB * SS * DD];
__device__ float  g_vTf[(size_t)BB * DD * SS];
__device__ float  g_atf[(size_t)BB * SS * DD];
__device__ float  g_scores[(size_t)BB * SS * SS];   // 128 MB

__device__ __forceinline__ void q2dig(float x, float sc, int8_t& q0, int8_t& q1) {
    int X = __float2int_rn(x * sc);
    int d0 = (X + 128) >> 8;         // arithmetic shift: floor((X+128)/256)
    q0 = (int8_t)d0;
    q1 = (int8_t)(X - (d0 << 8));
}

// ---------------- 1) labels = argmax(h @ W_lab + b_lab) (fp32: argmax cliff) ----------------
__global__ void label_kernel(const float* __restrict__ h,
                             const float* __restrict__ Wlab,
                             const float* __restrict__ blab) {
    int tok  = blockIdx.x * (blockDim.x >> 5) + (threadIdx.x >> 5);
    int lane = threadIdx.x & 31;
    const float* hr = h + (size_t)tok * DD;
    float a0 = 0.f, a1 = 0.f, a2 = 0.f, a3 = 0.f;
    for (int k = lane; k < DD; k += 32) {
        float hv = hr[k];
        float4 w = *(const float4*)(Wlab + k * 4);
        a0 += hv * w.x; a1 += hv * w.y; a2 += hv * w.z; a3 += hv * w.w;
    }
    #pragma unroll
    for (int o = 16; o; o >>= 1) {
        a0 += __shfl_down_sync(0xffffffffu, a0, o);
        a1 += __shfl_down_sync(0xffffffffu, a1, o);
        a2 += __shfl_down_sync(0xffffffffu, a2, o);
        a3 += __shfl_down_sync(0xffffffffu, a3, o);
    }
    if (lane == 0) {
        float lg[4] = { a0 + blab[0], a1 + blab[1], a2 + blab[2], a3 + blab[3] };
        int best = 0; float bv = lg[0];
        #pragma unroll
        for (int j = 1; j < 4; j++) if (lg[j] > bv) { bv = lg[j]; best = j; }
        g_labels[tok] = best;
    }
}

// ---------------- 2) sequential BIOS chunk scan ----------------
__global__ void scan_kernel() {
    __shared__ int lab[SS];
    int b = blockIdx.x;
    for (int s = threadIdx.x; s < SS; s += blockDim.x) lab[s] = g_labels[b * SS + s];
    __syncthreads();
    if (threadIdx.x == 0) {
        int* cs = g_chunk_start + b * SS;
        int* cl = g_chunk_len   + b * SS;
        bool open = false; int c = -1;
        for (int s = 0; s < SS; s++) {
            int l = lab[s];
            bool cont = (l == 1) && open;
            open = (l == 0) || cont;
            if (!cont) {
                if (c >= 0) cl[c] = s - cs[c];
                c++; cs[c] = s;
            }
        }
        cl[c] = SS - cs[c];
        g_nchunks[b] = c + 1;
    }
}

// ---------------- 3) per-chunk mean -> row-quantized int8 digits ----------------
__global__ void chunk_meanq_kernel(const float* __restrict__ h) {
    __shared__ float red[8];
    int b = blockIdx.y, c = blockIdx.x;
    int row = b * SS + c;
    int d = threadIdx.x * 4;
    int nc = g_nchunks[b];
    float4 acc = make_float4(0.f, 0.f, 0.f, 0.f);
    if (c < nc) {
        int st  = g_chunk_start[b * SS + c];
        int len = g_chunk_len[b * SS + c];
        const float* base = h + ((size_t)b * SS + st) * DD + d;
        for (int t = 0; t < len; t++) {
            float4 v = *(const float4*)(base + (size_t)t * DD);
            acc.x += v.x; acc.y += v.y; acc.z += v.z; acc.w += v.w;
        }
        float inv = 1.f / (float)len;
        acc.x *= inv; acc.y *= inv; acc.z *= inv; acc.w *= inv;
    }
    float m = fmaxf(fmaxf(fabsf(acc.x), fabsf(acc.y)), fmaxf(fabsf(acc.z), fabsf(acc.w)));
    #pragma unroll
    for (int o = 16; o; o >>= 1) m = fmaxf(m, __shfl_xor_sync(0xffffffffu, m, o));
    if ((threadIdx.x & 31) == 0) red[threadIdx.x >> 5] = m;
    __syncthreads();
    float M = red[0];
    #pragma unroll
    for (int i = 1; i < 8; i++) M = fmaxf(M, red[i]);
    float sc = (M > 0.f) ? 32512.f / M : 0.f;
    if (threadIdx.x == 0) g_Sce[row] = (M > 0.f) ? M : 1.f;
    int8_t a0,a1,b0_,b1_,c0,c1,d0_,d1_;
    q2dig(acc.x, sc, a0, a1); q2dig(acc.y, sc, b0_, b1_);
    q2dig(acc.z, sc, c0, c1); q2dig(acc.w, sc, d0_, d1_);
    *(char4*)(g_ce_d0 + (size_t)row * DD + d) = make_char4(a0, b0_, c0, d0_);
    *(char4*)(g_ce_d1 + (size_t)row * DD + d) = make_char4(a1, b1_, c1, d1_);
}

// ---------------- 4) generic row quantizer: fp32 [rows][L] -> digits + per-row scale ------
__global__ void quant_rows_kernel(const float* __restrict__ X, int L,
                                  int8_t* __restrict__ D0, int8_t* __restrict__ D1,
                                  float* __restrict__ S) {
    int row  = blockIdx.x * 8 + (threadIdx.x >> 5);
    int lane = threadIdx.x & 31;
    const float* xr = X + (size_t)row * L;
    int iters = L >> 7;                       // 128 floats per warp per iter
    float m = 0.f;
    for (int j = 0; j < iters; j++) {
        float4 v = *(const float4*)(xr + lane * 4 + j * 128);
        m = fmaxf(m, fmaxf(fmaxf(fabsf(v.x), fabsf(v.y)), fmaxf(fabsf(v.z), fabsf(v.w))));
    }
    #pragma unroll
    for (int o = 16; o; o >>= 1) m = fmaxf(m, __shfl_xor_sync(0xffffffffu, m, o));
    m = __shfl_sync(0xffffffffu, m, 0);
    if (lane == 0) S[row] = (m > 0.f) ? m : 1.f;
    float sc = (m > 0.f) ? 32512.f / m : 0.f;
    for (int j = 0; j < iters; j++) {
        float4 v = *(const float4*)(xr + lane * 4 + j * 128);
        int8_t a0,a1,b0_,b1_,c0,c1,d0_,d1_;
        q2dig(v.x, sc, a0, a1); q2dig(v.y, sc, b0_, b1_);
        q2dig(v.z, sc, c0, c1); q2dig(v.w, sc, d0_, d1_);
        *(char4*)(D0 + (size_t)row * L + lane * 4 + j * 128) = make_char4(a0, b0_, c0, d0_);
        *(char4*)(D1 + (size_t)row * L + lane * 4 + j * 128) = make_char4(a1, b1_, c1, d1_);
    }
}

// ---------------- 4b) weight col-max (parallel two-phase) + transpose-quantize -------------
__global__ void colmax_part_kernel(const float* __restrict__ W, float* __restrict__ part) {
    int c  = blockIdx.x * 256 + threadIdx.x;
    int r0 = blockIdx.y * 128;
    float m = 0.f;
    #pragma unroll 4
    for (int r = r0; r < r0 + 128; r++) m = fmaxf(m, fabsf(W[(size_t)r * DD + c]));
    part[blockIdx.y * DD + c] = m;
}
__global__ void colmax_reduce_kernel(const float* __restrict__ part, float* __restrict__ S) {
    int c = blockIdx.x * 256 + threadIdx.x;
    float m = 0.f;
    #pragma unroll
    for (int j = 0; j < 8; j++) m = fmaxf(m, part[j * DD + c]);
    S[c] = (m > 0.f) ? m : 1.f;
}

__global__ void wtransq_kernel(const float* __restrict__ W, const float* __restrict__ S,
                               int8_t* __restrict__ D0, int8_t* __restrict__ D1) {
    __shared__ float t[32][33];
    int tx = threadIdx.x, ty = threadIdx.y;          // (32, 8)
    int x = blockIdx.x * 32 + tx, y = blockIdx.y * 32 + ty;
    #pragma unroll
    for (int k = 0; k < 4; k++) t[ty + 8*k][tx] = W[(size_t)(y + 8*k) * DD + x];
    __syncthreads();
    int x2 = blockIdx.y * 32 + tx, y2 = blockIdx.x * 32 + ty;
    #pragma unroll
    for (int k = 0; k < 4; k++) {
        int n = y2 + 8*k;                            // WT row = W column
        float v = t[tx][ty + 8*k];
        float sc = 32512.f / S[n];
        int8_t q0, q1; q2dig(v, sc, q0, q1);
        D0[(size_t)n * DD + x2] = q0;
        D1[(size_t)n * DD + x2] = q1;
    }
}

// ---------------- 4c) fp32 transpose: v(S,D) -> vT(D,S), per batch ----------------
__global__ void vtransf_kernel() {
    __shared__ float t[32][33];
    int b = blockIdx.z;
    int tx = threadIdx.x, ty = threadIdx.y;          // (32, 8)
    const float* vf = g_vf + (size_t)b * SS * DD;
    float* o = g_vTf + (size_t)b * DD * SS;
    int d0 = blockIdx.x * 32, s0 = blockIdx.y * 32;
    #pragma unroll
    for (int k = 0; k < 4; k++)
        t[ty + 8*k][tx] = vf[(size_t)(s0 + ty + 8*k) * DD + d0 + tx];
    __syncthreads();
    #pragma unroll
    for (int k = 0; k < 4; k++)
        o[(size_t)(d0 + ty + 8*k) * SS + s0 + tx] = t[tx][ty + 8*k];
}

// ---------------- 5) int8 NT tensor-core GEMM (2-digit, 3 terms), cp.async 4-stage --------
// C(M,N) = alpha*SA[r]*SB[c]/32512^2 * (65536*G00 + 256*(G01+G10)) [+ bias]
// lim & 1: skip M-blocks whose (row % SS) >= nchunks[row / SS]   (chunk-row outputs)
// lim & 2: skip N-blocks with bn >= nchunks[bz]                  (masked score cols)
// lim & 4: truncate K loop to ceil(nchunks[bz]/64) tiles         (zero probs tail)

#define MMA_S8(d, a, b0v, b1v) \
    asm volatile("mma.sync.aligned.m16n8k32.row.col.s32.s8.s8.s32 " \
                 "{%0,%1,%2,%3}, {%4,%5,%6,%7}, {%8,%9}, {%0,%1,%2,%3};" \
                 : "+r"((d)[0]), "+r"((d)[1]), "+r"((d)[2]), "+r"((d)[3]) \
                 : "r"((a)[0]), "r"((a)[1]), "r"((a)[2]), "r"((a)[3]), "r"(b0v), "r"(b1v))

#define LDSM4(r, addr) \
    asm volatile("ldmatrix.sync.aligned.m8n8.x4.shared.b16 {%0,%1,%2,%3}, [%4];" \
                 : "=r"((r)[0]), "=r"((r)[1]), "=r"((r)[2]), "=r"((r)[3]) : "r"(addr))

#define CP_ASYNC16(dst, src) \
    asm volatile("cp.async.cg.shared.global [%0], [%1], 16;" :: "r"(dst), "l"(src))
#define CP_COMMIT() asm volatile("cp.async.commit_group;")
#define CP_WAIT(n)  asm volatile("cp.async.wait_group %0;" :: "n"(n))

__global__ __launch_bounds__(256)
void gemm_s8(const int8_t* __restrict__ Ad0, const int8_t* __restrict__ Ad1,
             const int8_t* __restrict__ Bd0, const int8_t* __restrict__ Bd1,
             const float* __restrict__ SA, const float* __restrict__ SB,
             const float* __restrict__ bias, float* __restrict__ Cf,
             int M, int N, int K,
             long long sA, long long sB, long long sC,
             long long sSA, long long sSB, float alpha,
             const int* __restrict__ ncs, int lim) {
    constexpr int STAGES = 4;
    constexpr int STAGE_BYTES = 32768;
    extern __shared__ char smem[];
    uint32_t sbase = (uint32_t)__cvta_generic_to_shared(smem);

    const int bz = blockIdx.z;
    const int bm = blockIdx.y * 128, bn = blockIdx.x * 128;

    if (lim & 1) {                               // chunk-row M blocks
        int batch = bm >> 11;                    // 2048 rows per batch
        if ((bm & 2047) >= ncs[batch]) return;
    }
    if (lim & 2) {                               // masked score N blocks
        if (bn >= ncs[bz]) return;
    }
    int ntiles = K >> 6;                         // 64 int8 per tile
    if (lim & 4) ntiles = (ncs[bz] + 63) >> 6;   // zero-probs K tail

    const int8_t* pA0 = Ad0 + (size_t)bz * sA + (size_t)bm * K;
    const int8_t* pA1 = Ad1 + (size_t)bz * sA + (size_t)bm * K;
    const int8_t* pB0 = Bd0 + (size_t)bz * sB + (size_t)bn * K;
    const int8_t* pB1 = Bd1 + (size_t)bz * sB + (size_t)bn * K;
    const float* SAb = SA + (size_t)bz * sSA;
    const float* SBb = SB + (size_t)bz * sSB;

    const int tid  = threadIdx.x;
    const int wid  = tid >> 5;
    const int lane = tid & 31;
    const int lr = lane >> 2, lc = lane & 3;
    const int mw = (wid & 1) * 64;
    const int nw = (wid >> 1) * 32;

    const int l8  = lane & 7;
    const int lb  = (lane >> 3) & 1;
    const int lhb = lane >> 4;
    const int arow  = mw + l8 + lb * 8;
    const int acolh = lhb * 8;
    const uint32_t aswz = (uint32_t)((arow & 7) << 4);
    const int brow  = nw + l8 + lhb * 8;
    const int bcolh = lb * 8;
    const uint32_t bswz = (uint32_t)((brow & 7) << 4);

    int acc0[4][4][4], accX[4][4][4];
    #pragma unroll
    for (int mi = 0; mi < 4; mi++)
        #pragma unroll
        for (int ni = 0; ni < 4; ni++)
            #pragma unroll
            for (int r = 0; r < 4; r++) { acc0[mi][ni][r] = 0; accX[mi][ni][r] = 0; }

    auto load_tile = [&](int k0, int slot) {
        uint32_t dA = sbase + slot * STAGE_BYTES;
        uint32_t dB = dA + 16384;
        #pragma unroll
        for (int i = 0; i < 4; i++) {
            int j = tid + 256 * i;
            int r = j >> 3, c = j & 7;
            const int8_t* src = (c < 4) ? (pA0 + (size_t)r * K + k0 + c * 16)
                                        : (pA1 + (size_t)r * K + k0 + (c - 4) * 16);
            CP_ASYNC16(dA + r * 128 + ((c ^ (r & 7)) << 4), src);
        }
        #pragma unroll
        for (int i = 0; i < 4; i++) {
            int j = tid + 256 * i;
            int r = j >> 3, c = j & 7;
            const int8_t* src = (c < 4) ? (pB0 + (size_t)r * K + k0 + c * 16)
                                        : (pB1 + (size_t)r * K + k0 + (c - 4) * 16);
            CP_ASYNC16(dB + r * 128 + ((c ^ (r & 7)) << 4), src);
        }
    };

    #pragma unroll
    for (int s = 0; s < STAGES - 1; s++) {       // prologue loads stay in-bounds (k < K)
        load_tile(s * 64, s);
        CP_COMMIT();
    }

    for (int i = 0; i < ntiles; i++) {
        CP_WAIT(STAGES - 2);
        __syncthreads();
        int nx = i + STAGES - 1;
        if (nx < ntiles) {
            load_tile(nx * 64, nx % STAGES);
            CP_COMMIT();
        }
        uint32_t sA_ = sbase + (i % STAGES) * STAGE_BYTES;
        uint32_t sB_ = sA_ + 16384;

        #pragma unroll
        for (int g = 0; g < 2; g++) {
            const int kk = g * 16;
            uint32_t a0f[4][4], a1f[4][4], b0f[4][2], b1f[4][2];
            {
                uint32_t a0_addr = sA_ + (uint32_t)arow * 128
                                 + (((uint32_t)(kk + acolh) * 2) ^ aswz);
                uint32_t a1_addr = sA_ + (uint32_t)arow * 128
                                 + (((uint32_t)(kk + acolh + 32) * 2) ^ aswz);
                #pragma unroll
                for (int mi = 0; mi < 4; mi++) {
                    LDSM4(a0f[mi], a0_addr + mi * (16 * 128));
                    LDSM4(a1f[mi], a1_addr + mi * (16 * 128));
                }
            }
            {
                uint32_t b0_addr = sB_ + (uint32_t)brow * 128
                                 + (((uint32_t)(kk + bcolh) * 2) ^ bswz);
                uint32_t b1_addr = sB_ + (uint32_t)brow * 128
                                 + (((uint32_t)(kk + bcolh + 32) * 2) ^ bswz);
                #pragma unroll
                for (int p = 0; p < 2; p++) {
                    uint32_t t[4];
                    LDSM4(t, b0_addr + p * (16 * 128));
                    b0f[2*p][0] = t[0]; b0f[2*p][1] = t[1];
                    b0f[2*p+1][0] = t[2]; b0f[2*p+1][1] = t[3];
                    LDSM4(t, b1_addr + p * (16 * 128));
                    b1f[2*p][0] = t[0]; b1f[2*p][1] = t[1];
                    b1f[2*p+1][0] = t[2]; b1f[2*p+1][1] = t[3];
                }
            }
            #pragma unroll
            for (int mi = 0; mi < 4; mi++)
                #pragma unroll
                for (int ni = 0; ni < 4; ni++)
                    MMA_S8(acc0[mi][ni], a0f[mi], b0f[ni][0], b0f[ni][1]);  // d0*d0
            #pragma unroll
            for (int mi = 0; mi < 4; mi++)
                #pragma unroll
                for (int ni = 0; ni < 4; ni++)
                    MMA_S8(accX[mi][ni], a0f[mi], b1f[ni][0], b1f[ni][1]);  // d0*d1
            #pragma unroll
            for (int mi = 0; mi < 4; mi++)
                #pragma unroll
                for (int ni = 0; ni < 4; ni++)
                    MMA_S8(accX[mi][ni], a1f[mi], b0f[ni][0], b0f[ni][1]);  // d1*d0
        }
    }
    CP_WAIT(0);

    // ---- epilogue ----
    const float qs = alpha * (1.f / (32512.f * 32512.f));
    float* Cp = Cf + (size_t)bz * sC;
    #pragma unroll
    for (int mi = 0; mi < 4; mi++) {
        int r0 = bm + mw + mi * 16 + lr;
        float sr0 = SAb[r0] * qs, sr1 = SAb[r0 + 8] * qs;
        #pragma unroll
        for (int ni = 0; ni < 4; ni++) {
            int c0 = bn + nw + ni * 8 + lc * 2;
            float sb0 = SBb[c0], sb1 = SBb[c0 + 1];
            float o0 = (65536.f * (float)acc0[mi][ni][0] + 256.f * (float)accX[mi][ni][0]) * sr0 * sb0;
            float o1 = (65536.f * (float)acc0[mi][ni][1] + 256.f * (float)accX[mi][ni][1]) * sr0 * sb1;
            float o2 = (65536.f * (float)acc0[mi][ni][2] + 256.f * (float)accX[mi][ni][2]) * sr1 * sb0;
            float o3 = (65536.f * (float)acc0[mi][ni][3] + 256.f * (float)accX[mi][ni][3]) * sr1 * sb1;
            if (bias) {
                float b0 = bias[c0], b1 = bias[c0 + 1];
                o0 += b0; o1 += b1; o2 += b0; o3 += b1;
            }
            *(float2*)(Cp + (size_t)r0 * N + c0)       = make_float2(o0, o1);
            *(float2*)(Cp + (size_t)(r0 + 8) * N + c0) = make_float2(o2, o3);
        }
    }
}

// ---------------- 6) masked row softmax -> probs digits (scale = 1/s, free) ----------------
__global__ void softmax_kernel() {
    __shared__ float red[8];
    int row = blockIdx.x;
    int b = row >> 11;
    int nc = g_nchunks[b];
    const float* sc = g_scores + (size_t)row * SS;
    int8_t* pd0 = g_p_d0 + (size_t)row * SS;
    int8_t* pd1 = g_p_d1 + (size_t)row * SS;

    const float NEG_INF = __int_as_float(0xff800000);
    float x[8];
    float m = NEG_INF;
    #pragma unroll
    for (int i = 0; i < 8; i++) {
        int c = threadIdx.x + i * 256;
        x[i] = (c < nc) ? sc[c] : NEG_INF;
        m = fmaxf(m, x[i]);
    }
    #pragma unroll
    for (int o = 16; o; o >>= 1) m = fmaxf(m, __shfl_xor_sync(0xffffffffu, m, o));
    if ((threadIdx.x & 31) == 0) red[threadIdx.x >> 5] = m;
    __syncthreads();
    m = red[0];
    #pragma unroll
    for (int i = 1; i < 8; i++) m = fmaxf(m, red[i]);
    __syncthreads();

    float s = 0.f;
    #pragma unroll
    for (int i = 0; i < 8; i++) {
        int c = threadIdx.x + i * 256;
        x[i] = (c < nc) ? expf(x[i] - m) : 0.f;   // in [0,1], max is exactly 1
        s += x[i];
    }
    #pragma unroll
    for (int o = 16; o; o >>= 1) s += __shfl_xor_sync(0xffffffffu, s, o);
    if ((threadIdx.x & 31) == 0) red[threadIdx.x >> 5] = s;
    __syncthreads();
    s = 0.f;
    #pragma unroll
    for (int i = 0; i < 8; i++) s += red[i];
    float inv = 1.f / s;
    if (threadIdx.x == 0) g_SP[row] = inv;        // p = inv * (X/32512)

    #pragma unroll
    for (int i = 0; i < 8; i++) {
        int c = threadIdx.x + i * 256;
        int8_t q0, q1; q2dig(x[i], 32512.f, q0, q1);
        pd0[c] = q0; pd1[c] = q1;
    }
}

// ---------------- host side ----------------
static void launch_gemm(const int8_t* Ad0, const int8_t* Ad1,
                        const int8_t* Bd0, const int8_t* Bd1,
                        const float* SA, const float* SB,
                        const float* bias, float* Cf,
                        int M, int N, int K,
                        long long sA, long long sB, long long sC,
                        long long sSA, long long sSB, int batch, float alpha,
                        const int* ncs, int lim) {
    constexpr int SMEM = 4 * 32768;
    dim3 grid(N / 128, M / 128, batch), block(256);
    cudaFuncSetAttribute(gemm_s8, cudaFuncAttributeMaxDynamicSharedMemorySize, SMEM);
    gemm_s8<<<grid, block, SMEM>>>(Ad0, Ad1, Bd0, Bd1, SA, SB, bias, Cf,
                                   M, N, K, sA, sB, sC, sSA, sSB, alpha, ncs, lim);
}

extern "C" void kernel_launch(void* const* d_in, const int* in_sizes, int n_in,
                              void* d_out, int out_size) {
    (void)in_sizes; (void)n_in; (void)out_size;
    const float* h    = (const float*)d_in[0];
    const float* Wlab = (const float*)d_in[1];
    const float* blab = (const float*)d_in[2];
    const float* Wq   = (const float*)d_in[3];
    const float* bq   = (const float*)d_in[4];
    const float* Wk   = (const float*)d_in[5];
    const float* bk   = (const float*)d_in[6];
    const float* Wv   = (const float*)d_in[7];
    const float* bv   = (const float*)d_in[8];
    const float* Wo   = (const float*)d_in[9];
    const float* bo   = (const float*)d_in[10];
    float* out = (float*)d_out;

    int8_t *hd0,*hd1,*ced0,*ced1,*wqd0,*wqd1,*wkd0,*wkd1,*wvd0,*wvd1,*wod0,*wod1;
    int8_t *qd0,*qd1,*kd0,*kd1,*vTd0,*vTd1,*pd0,*pd1,*atd0,*atd1;
    float *Sh,*Sce,*Swq,*Swk,*Swv,*Swo,*Sq,*Sk,*SvT,*SP,*Sat;
    float *qf,*kf,*vf,*vTf,*atf,*scb,*cpart;
    int *ncs;
    cudaGetSymbolAddress((void**)&hd0, g_h_d0);   cudaGetSymbolAddress((void**)&hd1, g_h_d1);
    cudaGetSymbolAddress((void**)&ced0, g_ce_d0); cudaGetSymbolAddress((void**)&ced1, g_ce_d1);
    cudaGetSymbolAddress((void**)&wqd0, g_wq_d0); cudaGetSymbolAddress((void**)&wqd1, g_wq_d1);
    cudaGetSymbolAddress((void**)&wkd0, g_wk_d0); cudaGetSymbolAddress((void**)&wkd1, g_wk_d1);
    cudaGetSymbolAddress((void**)&wvd0, g_wv_d0); cudaGetSymbolAddress((void**)&wvd1, g_wv_d1);
    cudaGetSymbolAddress((void**)&wod0, g_wo_d0); cudaGetSymbolAddress((void**)&wod1, g_wo_d1);
    cudaGetSymbolAddress((void**)&qd0, g_q_d0);   cudaGetSymbolAddress((void**)&qd1, g_q_d1);
    cudaGetSymbolAddress((void**)&kd0, g_k_d0);   cudaGetSymbolAddress((void**)&kd1, g_k_d1);
    cudaGetSymbolAddress((void**)&vTd0, g_vT_d0); cudaGetSymbolAddress((void**)&vTd1, g_vT_d1);
    cudaGetSymbolAddress((void**)&pd0, g_p_d0);   cudaGetSymbolAddress((void**)&pd1, g_p_d1);
    cudaGetSymbolAddress((void**)&atd0, g_at_d0); cudaGetSymbolAddress((void**)&atd1, g_at_d1);
    cudaGetSymbolAddress((void**)&Sh, g_Sh);   cudaGetSymbolAddress((void**)&Sce, g_Sce);
    cudaGetSymbolAddress((void**)&Swq, g_Swq); cudaGetSymbolAddress((void**)&Swk, g_Swk);
    cudaGetSymbolAddress((void**)&Swv, g_Swv); cudaGetSymbolAddress((void**)&Swo, g_Swo);
    cudaGetSymbolAddress((void**)&Sq, g_Sq);   cudaGetSymbolAddress((void**)&Sk, g_Sk);
    cudaGetSymbolAddress((void**)&SvT, g_SvT); cudaGetSymbolAddress((void**)&SP, g_SP);
    cudaGetSymbolAddress((void**)&Sat, g_Sat);
    cudaGetSymbolAddress((void**)&qf, g_qf);   cudaGetSymbolAddress((void**)&kf, g_kf);
    cudaGetSymbolAddress((void**)&vf, g_vf);   cudaGetSymbolAddress((void**)&vTf, g_vTf);
    cudaGetSymbolAddress((void**)&atf, g_atf); cudaGetSymbolAddress((void**)&scb, g_scores);
    cudaGetSymbolAddress((void**)&cpart, g_cmax_part);
    cudaGetSymbolAddress((void**)&ncs, g_nchunks);

    const int M = BB * SS;                        // 16384
    const long long sQ = (long long)SS * DD;
    const long long sS = (long long)SS * SS;
    const long long sV = (long long)DD * SS;

    // prep: labels/chunks, quantize h + weights, chunk means (quantized in-kernel)
    label_kernel<<<M / 8, 256>>>(h, Wlab, blab);
    scan_kernel<<<BB, 256>>>();
    quant_rows_kernel<<<M / 8, 256>>>(h, DD, hd0, hd1, Sh);
    colmax_part_kernel<<<dim3(4, 8), 256>>>(Wq, cpart);
    colmax_reduce_kernel<<<4, 256>>>(cpart, Swq);
    colmax_part_kernel<<<dim3(4, 8), 256>>>(Wk, cpart);
    colmax_reduce_kernel<<<4, 256>>>(cpart, Swk);
    colmax_part_kernel<<<dim3(4, 8), 256>>>(Wv, cpart);
    colmax_reduce_kernel<<<4, 256>>>(cpart, Swv);
    colmax_part_kernel<<<dim3(4, 8), 256>>>(Wo, cpart);
    colmax_reduce_kernel<<<4, 256>>>(cpart, Swo);
    wtransq_kernel<<<dim3(32, 32), dim3(32, 8)>>>(Wq, Swq, wqd0, wqd1);
    wtransq_kernel<<<dim3(32, 32), dim3(32, 8)>>>(Wk, Swk, wkd0, wkd1);
    wtransq_kernel<<<dim3(32, 32), dim3(32, 8)>>>(Wv, Swv, wvd0, wvd1);
    wtransq_kernel<<<dim3(32, 32), dim3(32, 8)>>>(Wo, Swo, wod0, wod1);
    chunk_meanq_kernel<<<dim3(SS, BB), 256>>>(h);

    // projections: int8 GEMMs -> fp32, then row-quantize
    launch_gemm(hd0, hd1, wqd0, wqd1, Sh, Swq, bq, qf, M, DD, DD, 0,0,0, 0,0, 1, 1.f,
                ncs, 0);
    launch_gemm(ced0, ced1, wkd0, wkd1, Sce, Swk, bk, kf, M, DD, DD, 0,0,0, 0,0, 1, 1.f,
                ncs, 1);                                   // skip all-padding chunk rows
    launch_gemm(ced0, ced1, wvd0, wvd1, Sce, Swv, bv, vf, M, DD, DD, 0,0,0, 0,0, 1, 1.f,
                ncs, 1);
    quant_rows_kernel<<<M / 8, 256>>>(qf, DD, qd0, qd1, Sq);
    quant_rows_kernel<<<M / 8, 256>>>(kf, DD, kd0, kd1, Sk);
    vtransf_kernel<<<dim3(DD / 32, SS / 32, BB), dim3(32, 8)>>>();
    quant_rows_kernel<<<(BB * DD) / 8, 256>>>(vTf, SS, vTd0, vTd1, SvT);

    // scores[b] = (q[b] @ k[b]^T) / 32 -> fp32 (masked N blocks skipped)
    launch_gemm(qd0, qd1, kd0, kd1, Sq, Sk, nullptr, scb,
                SS, SS, DD, sQ, sQ, sS, SS, SS, BB, 0.03125f, ncs, 2);

    softmax_kernel<<<M, 256>>>();   // -> probs digits + SP (masked cols exactly 0)

    // attended[b] = probs[b] @ vT[b]^T -> fp32 (zero-probs K tail truncated)
    launch_gemm(pd0, pd1, vTd0, vTd1, SP, SvT, nullptr, atf,
                SS, DD, SS, sS, sV, sQ, SS, DD, BB, 1.f, ncs, 4);
    quant_rows_kernel<<<M / 8, 256>>>(atf, DD, atd0, atd1, Sat);

    // out = att @ Wo^T + bo -> fp32 d_out
    launch_gemm(atd0, atd1, wod0, wod1, Sat, Swo, bo, out, M, DD, DD, 0,0,0, 0,0, 1, 1.f,
                ncs, 0);
}

// round 11
// speedup vs baseline: 3.7984x; 1.0458x over previous
#include <cuda_runtime.h>
#include <cuda_bf16.h>
#include <cstdint>
#include <cstddef>

#define BB 8
#define SS 2048
#define DD 1024
// DC == DD == 1024, scale = 1/sqrt(1024) = 1/32
// int8 2-digit scheme: x ~= S * X / 32512, X = 256*d0 + d1, d0,d1 in int8.

typedef __nv_bfloat16 bf16;

// ---------------- scratch (static device globals; no allocation) ----------------
__device__ int    g_labels[BB * SS];
__device__ int    g_chunk_start[BB * SS];
__device__ int    g_chunk_len[BB * SS];
__device__ int    g_nchunks[BB];
__device__ float  g_cmax_part[64 * DD];              // 16 rowchunks x 4 weights

// digit arrays + scales
__device__ int8_t g_h_d0[(size_t)BB * SS * DD],  g_h_d1[(size_t)BB * SS * DD];
__device__ float  g_Sh[BB * SS];
__device__ int8_t g_ce_d0[(size_t)BB * SS * DD], g_ce_d1[(size_t)BB * SS * DD];
__device__ float  g_Sce[BB * SS];
__device__ int8_t g_wq_d0[DD * DD], g_wq_d1[DD * DD];
__device__ int8_t g_wk_d0[DD * DD], g_wk_d1[DD * DD];
__device__ int8_t g_wv_d0[DD * DD], g_wv_d1[DD * DD];
__device__ int8_t g_wo_d0[DD * DD], g_wo_d1[DD * DD];
__device__ float  g_Swq[DD], g_Swk[DD], g_Swv[DD], g_Swo[DD];
__device__ int8_t g_q_d0[(size_t)BB * SS * DD],  g_q_d1[(size_t)BB * SS * DD];
__device__ float  g_Sq[BB * SS];
__device__ int8_t g_k_d0[(size_t)BB * SS * DD],  g_k_d1[(size_t)BB * SS * DD];
__device__ float  g_Sk[BB * SS];
__device__ int8_t g_vT_d0[(size_t)BB * DD * SS], g_vT_d1[(size_t)BB * DD * SS];
__device__ float  g_SvT[BB * DD];
__device__ int8_t g_p_d0[(size_t)BB * SS * SS],  g_p_d1[(size_t)BB * SS * SS];
__device__ float  g_SP[BB * SS];
__device__ int8_t g_at_d0[(size_t)BB * SS * DD], g_at_d1[(size_t)BB * SS * DD];
__device__ float  g_Sat[BB * SS];

// fp32 intermediates
__device__ float  g_qf[(size_t)BB * SS * DD];
__device__ float  g_kf[(size_t)BB * SS * DD];
__device__ float  g_vf[(size_t)BB * SS * DD];
__device__ float  g_vTf[(size_t)BB * DD * SS];
__device__ float  g_atf[(size_t)BB * SS * DD];
__device__ float  g_scores[(size_t)BB * SS * SS];   // 128 MB

__device__ __forceinline__ void q2dig(float x, float sc, int8_t& q0, int8_t& q1) {
    int X = __float2int_rn(x * sc);
    int d0 = (X + 128) >> 8;         // arithmetic shift: floor((X+128)/256)
    q0 = (int8_t)d0;
    q1 = (int8_t)(X - (d0 << 8));
}

// ---------------- 1) labels = argmax(h @ W_lab + b_lab) (fp32: argmax cliff) ----------------
__global__ void label_kernel(const float* __restrict__ h,
                             const float* __restrict__ Wlab,
                             const float* __restrict__ blab) {
    int tok  = blockIdx.x * (blockDim.x >> 5) + (threadIdx.x >> 5);
    int lane = threadIdx.x & 31;
    const float* hr = h + (size_t)tok * DD;
    float a0 = 0.f, a1 = 0.f, a2 = 0.f, a3 = 0.f;
    for (int k = lane; k < DD; k += 32) {
        float hv = hr[k];
        float4 w = *(const float4*)(Wlab + k * 4);
        a0 += hv * w.x; a1 += hv * w.y; a2 += hv * w.z; a3 += hv * w.w;
    }
    #pragma unroll
    for (int o = 16; o; o >>= 1) {
        a0 += __shfl_down_sync(0xffffffffu, a0, o);
        a1 += __shfl_down_sync(0xffffffffu, a1, o);
        a2 += __shfl_down_sync(0xffffffffu, a2, o);
        a3 += __shfl_down_sync(0xffffffffu, a3, o);
    }
    if (lane == 0) {
        float lg[4] = { a0 + blab[0], a1 + blab[1], a2 + blab[2], a3 + blab[3] };
        int best = 0; float bv = lg[0];
        #pragma unroll
        for (int j = 1; j < 4; j++) if (lg[j] > bv) { bv = lg[j]; best = j; }
        g_labels[tok] = best;
    }
}

// ---------------- 2) sequential BIOS chunk scan ----------------
__global__ void scan_kernel() {
    __shared__ int lab[SS];
    int b = blockIdx.x;
    for (int s = threadIdx.x; s < SS; s += blockDim.x) lab[s] = g_labels[b * SS + s];
    __syncthreads();
    if (threadIdx.x == 0) {
        int* cs = g_chunk_start + b * SS;
        int* cl = g_chunk_len   + b * SS;
        bool open = false; int c = -1;
        for (int s = 0; s < SS; s++) {
            int l = lab[s];
            bool cont = (l == 1) && open;
            open = (l == 0) || cont;
            if (!cont) {
                if (c >= 0) cl[c] = s - cs[c];
                c++; cs[c] = s;
            }
        }
        cl[c] = SS - cs[c];
        g_nchunks[b] = c + 1;
    }
}

// ---------------- 3) per-chunk mean -> row-quantized int8 digits ----------------
__global__ void chunk_meanq_kernel(const float* __restrict__ h) {
    __shared__ float red[8];
    int b = blockIdx.y, c = blockIdx.x;
    int row = b * SS + c;
    int d = threadIdx.x * 4;
    int nc = g_nchunks[b];
    float4 acc = make_float4(0.f, 0.f, 0.f, 0.f);
    if (c < nc) {
        int st  = g_chunk_start[b * SS + c];
        int len = g_chunk_len[b * SS + c];
        const float* base = h + ((size_t)b * SS + st) * DD + d;
        for (int t = 0; t < len; t++) {
            float4 v = *(const float4*)(base + (size_t)t * DD);
            acc.x += v.x; acc.y += v.y; acc.z += v.z; acc.w += v.w;
        }
        float inv = 1.f / (float)len;
        acc.x *= inv; acc.y *= inv; acc.z *= inv; acc.w *= inv;
    }
    float m = fmaxf(fmaxf(fabsf(acc.x), fabsf(acc.y)), fmaxf(fabsf(acc.z), fabsf(acc.w)));
    #pragma unroll
    for (int o = 16; o; o >>= 1) m = fmaxf(m, __shfl_xor_sync(0xffffffffu, m, o));
    if ((threadIdx.x & 31) == 0) red[threadIdx.x >> 5] = m;
    __syncthreads();
    float M = red[0];
    #pragma unroll
    for (int i = 1; i < 8; i++) M = fmaxf(M, red[i]);
    float sc = (M > 0.f) ? 32512.f / M : 0.f;
    if (threadIdx.x == 0) g_Sce[row] = (M > 0.f) ? M : 1.f;
    int8_t a0,a1,b0_,b1_,c0,c1,d0_,d1_;
    q2dig(acc.x, sc, a0, a1); q2dig(acc.y, sc, b0_, b1_);
    q2dig(acc.z, sc, c0, c1); q2dig(acc.w, sc, d0_, d1_);
    *(char4*)(g_ce_d0 + (size_t)row * DD + d) = make_char4(a0, b0_, c0, d0_);
    *(char4*)(g_ce_d1 + (size_t)row * DD + d) = make_char4(a1, b1_, c1, d1_);
}

// ---------------- 4) row quantizer, single-read (L=1024): row cached in registers --------
__global__ void quant_rows1k_kernel(const float* __restrict__ X,
                                    int8_t* __restrict__ D0, int8_t* __restrict__ D1,
                                    float* __restrict__ S) {
    int row  = blockIdx.x * 8 + (threadIdx.x >> 5);
    int lane = threadIdx.x & 31;
    const float* xr = X + (size_t)row * DD;
    float4 v[8];
    float m = 0.f;
    #pragma unroll
    for (int j = 0; j < 8; j++) {
        v[j] = *(const float4*)(xr + lane * 4 + j * 128);
        m = fmaxf(m, fmaxf(fmaxf(fabsf(v[j].x), fabsf(v[j].y)),
                           fmaxf(fabsf(v[j].z), fabsf(v[j].w))));
    }
    #pragma unroll
    for (int o = 16; o; o >>= 1) m = fmaxf(m, __shfl_xor_sync(0xffffffffu, m, o));
    m = __shfl_sync(0xffffffffu, m, 0);
    if (lane == 0) S[row] = (m > 0.f) ? m : 1.f;
    float sc = (m > 0.f) ? 32512.f / m : 0.f;
    #pragma unroll
    for (int j = 0; j < 8; j++) {
        int8_t a0,a1,b0_,b1_,c0,c1,d0_,d1_;
        q2dig(v[j].x, sc, a0, a1); q2dig(v[j].y, sc, b0_, b1_);
        q2dig(v[j].z, sc, c0, c1); q2dig(v[j].w, sc, d0_, d1_);
        *(char4*)(D0 + (size_t)row * DD + lane * 4 + j * 128) = make_char4(a0, b0_, c0, d0_);
        *(char4*)(D1 + (size_t)row * DD + lane * 4 + j * 128) = make_char4(a1, b1_, c1, d1_);
    }
}

// ---------------- 4a) row quantizer, two-pass (general L; used for vT, L=2048) ------------
__global__ void quant_rows_kernel(const float* __restrict__ X, int L,
                                  int8_t* __restrict__ D0, int8_t* __restrict__ D1,
                                  float* __restrict__ S) {
    int row  = blockIdx.x * 8 + (threadIdx.x >> 5);
    int lane = threadIdx.x & 31;
    const float* xr = X + (size_t)row * L;
    int iters = L >> 7;
    float m = 0.f;
    for (int j = 0; j < iters; j++) {
        float4 v = *(const float4*)(xr + lane * 4 + j * 128);
        m = fmaxf(m, fmaxf(fmaxf(fabsf(v.x), fabsf(v.y)), fmaxf(fabsf(v.z), fabsf(v.w))));
    }
    #pragma unroll
    for (int o = 16; o; o >>= 1) m = fmaxf(m, __shfl_xor_sync(0xffffffffu, m, o));
    m = __shfl_sync(0xffffffffu, m, 0);
    if (lane == 0) S[row] = (m > 0.f) ? m : 1.f;
    float sc = (m > 0.f) ? 32512.f / m : 0.f;
    for (int j = 0; j < iters; j++) {
        float4 v = *(const float4*)(xr + lane * 4 + j * 128);
        int8_t a0,a1,b0_,b1_,c0,c1,d0_,d1_;
        q2dig(v.x, sc, a0, a1); q2dig(v.y, sc, b0_, b1_);
        q2dig(v.z, sc, c0, c1); q2dig(v.w, sc, d0_, d1_);
        *(char4*)(D0 + (size_t)row * L + lane * 4 + j * 128) = make_char4(a0, b0_, c0, d0_);
        *(char4*)(D1 + (size_t)row * L + lane * 4 + j * 128) = make_char4(a1, b1_, c1, d1_);
    }
}

// ---------------- 4b) fused weight col-max (4 weights, two-phase) + transpose-quantize ----
__global__ void colmax4_part_kernel(const float* __restrict__ W0, const float* __restrict__ W1,
                                    const float* __restrict__ W2, const float* __restrict__ W3,
                                    float* __restrict__ part) {
    const float* W = (blockIdx.z == 0) ? W0 : (blockIdx.z == 1) ? W1
                   : (blockIdx.z == 2) ? W2 : W3;
    int c  = blockIdx.x * 256 + threadIdx.x;
    int r0 = blockIdx.y * 64;
    float m = 0.f;
    #pragma unroll 8
    for (int r = r0; r < r0 + 64; r++) m = fmaxf(m, fabsf(W[(size_t)r * DD + c]));
    part[(blockIdx.z * 16 + blockIdx.y) * DD + c] = m;
}
__global__ void colmax4_reduce_kernel(const float* __restrict__ part,
                                      float* __restrict__ S0, float* __restrict__ S1,
                                      float* __restrict__ S2, float* __restrict__ S3) {
    float* S = (blockIdx.y == 0) ? S0 : (blockIdx.y == 1) ? S1
             : (blockIdx.y == 2) ? S2 : S3;
    int c = blockIdx.x * 256 + threadIdx.x;
    float m = 0.f;
    #pragma unroll
    for (int j = 0; j < 16; j++) m = fmaxf(m, part[(blockIdx.y * 16 + j) * DD + c]);
    S[c] = (m > 0.f) ? m : 1.f;
}

__global__ void wtransq4_kernel(const float* __restrict__ W0, const float* __restrict__ W1,
                                const float* __restrict__ W2, const float* __restrict__ W3,
                                const float* __restrict__ S0, const float* __restrict__ S1,
                                const float* __restrict__ S2, const float* __restrict__ S3,
                                int8_t* __restrict__ Dq0, int8_t* __restrict__ Dq1,
                                int8_t* __restrict__ Dk0, int8_t* __restrict__ Dk1,
                                int8_t* __restrict__ Dv0, int8_t* __restrict__ Dv1,
                                int8_t* __restrict__ Do0, int8_t* __restrict__ Do1) {
    const int z = blockIdx.z;
    const float* W = (z == 0) ? W0 : (z == 1) ? W1 : (z == 2) ? W2 : W3;
    const float* S = (z == 0) ? S0 : (z == 1) ? S1 : (z == 2) ? S2 : S3;
    int8_t* D0 = (z == 0) ? Dq0 : (z == 1) ? Dk0 : (z == 2) ? Dv0 : Do0;
    int8_t* D1 = (z == 0) ? Dq1 : (z == 1) ? Dk1 : (z == 2) ? Dv1 : Do1;
    __shared__ float t[32][33];
    int tx = threadIdx.x, ty = threadIdx.y;          // (32, 8)
    int x = blockIdx.x * 32 + tx, y = blockIdx.y * 32 + ty;
    #pragma unroll
    for (int k = 0; k < 4; k++) t[ty + 8*k][tx] = W[(size_t)(y + 8*k) * DD + x];
    __syncthreads();
    int x2 = blockIdx.y * 32 + tx, y2 = blockIdx.x * 32 + ty;
    #pragma unroll
    for (int k = 0; k < 4; k++) {
        int n = y2 + 8*k;
        float v = t[tx][ty + 8*k];
        float sc = 32512.f / S[n];
        int8_t q0, q1; q2dig(v, sc, q0, q1);
        D0[(size_t)n * DD + x2] = q0;
        D1[(size_t)n * DD + x2] = q1;
    }
}

// ---------------- 4c) fp32 transpose: v(S,D) -> vT(D,S), per batch ----------------
__global__ void vtransf_kernel() {
    __shared__ float t[32][33];
    int b = blockIdx.z;
    int tx = threadIdx.x, ty = threadIdx.y;          // (32, 8)
    const float* vf = g_vf + (size_t)b * SS * DD;
    float* o = g_vTf + (size_t)b * DD * SS;
    int d0 = blockIdx.x * 32, s0 = blockIdx.y * 32;
    #pragma unroll
    for (int k = 0; k < 4; k++)
        t[ty + 8*k][tx] = vf[(size_t)(s0 + ty + 8*k) * DD + d0 + tx];
    __syncthreads();
    #pragma unroll
    for (int k = 0; k < 4; k++)
        o[(size_t)(d0 + ty + 8*k) * SS + s0 + tx] = t[tx][ty + 8*k];
}

// ---------------- 5) int8 NT tensor-core GEMM (2-digit, 3 terms), cp.async 4-stage --------
// C(M,N) = alpha*SA[r]*SB[c]/32512^2 * (65536*G00 + 256*(G01+G10)) [+ bias]
// lim & 1: skip M-blocks whose (row % SS) >= nchunks[row / SS]   (chunk-row outputs)
// lim & 2: skip N-blocks with bn >= nchunks[bz]                  (masked score cols)
// lim & 4: truncate K loop to ceil(nchunks[bz]/64) tiles         (zero probs tail)

#define MMA_S8(d, a, b0v, b1v) \
    asm volatile("mma.sync.aligned.m16n8k32.row.col.s32.s8.s8.s32 " \
                 "{%0,%1,%2,%3}, {%4,%5,%6,%7}, {%8,%9}, {%0,%1,%2,%3};" \
                 : "+r"((d)[0]), "+r"((d)[1]), "+r"((d)[2]), "+r"((d)[3]) \
                 : "r"((a)[0]), "r"((a)[1]), "r"((a)[2]), "r"((a)[3]), "r"(b0v), "r"(b1v))

#define LDSM4(r, addr) \
    asm volatile("ldmatrix.sync.aligned.m8n8.x4.shared.b16 {%0,%1,%2,%3}, [%4];" \
                 : "=r"((r)[0]), "=r"((r)[1]), "=r"((r)[2]), "=r"((r)[3]) : "r"(addr))

#define CP_ASYNC16(dst, src) \
    asm volatile("cp.async.cg.shared.global [%0], [%1], 16;" :: "r"(dst), "l"(src))
#define CP_COMMIT() asm volatile("cp.async.commit_group;")
#define CP_WAIT(n)  asm volatile("cp.async.wait_group %0;" :: "n"(n))

__global__ __launch_bounds__(256)
void gemm_s8(const int8_t* __restrict__ Ad0, const int8_t* __restrict__ Ad1,
             const int8_t* __restrict__ Bd0, const int8_t* __restrict__ Bd1,
             const float* __restrict__ SA, const float* __restrict__ SB,
             const float* __restrict__ bias, float* __restrict__ Cf,
             int M, int N, int K,
             long long sA, long long sB, long long sC,
             long long sSA, long long sSB, float alpha,
             const int* __restrict__ ncs, int lim) {
    constexpr int STAGES = 4;
    constexpr int STAGE_BYTES = 32768;
    extern __shared__ char smem[];
    uint32_t sbase = (uint32_t)__cvta_generic_to_shared(smem);

    const int bz = blockIdx.z;
    const int bm = blockIdx.y * 128, bn = blockIdx.x * 128;

    if (lim & 1) {                               // chunk-row M blocks
        int batch = bm >> 11;
        if ((bm & 2047) >= ncs[batch]) return;
    }
    if (lim & 2) {                               // masked score N blocks
        if (bn >= ncs[bz]) return;
    }
    int ntiles = K >> 6;                         // 64 int8 per tile
    if (lim & 4) ntiles = (ncs[bz] + 63) >> 6;   // zero-probs K tail

    const int8_t* pA0 = Ad0 + (size_t)bz * sA + (size_t)bm * K;
    const int8_t* pA1 = Ad1 + (size_t)bz * sA + (size_t)bm * K;
    const int8_t* pB0 = Bd0 + (size_t)bz * sB + (size_t)bn * K;
    const int8_t* pB1 = Bd1 + (size_t)bz * sB + (size_t)bn * K;
    const float* SAb = SA + (size_t)bz * sSA;
    const float* SBb = SB + (size_t)bz * sSB;

    const int tid  = threadIdx.x;
    const int wid  = tid >> 5;
    const int lane = tid & 31;
    const int lr = lane >> 2, lc = lane & 3;
    const int mw = (wid & 1) * 64;
    const int nw = (wid >> 1) * 32;

    const int l8  = lane & 7;
    const int lb  = (lane >> 3) & 1;
    const int lhb = lane >> 4;
    const int arow  = mw + l8 + lb * 8;
    const int acolh = lhb * 8;
    const uint32_t aswz = (uint32_t)((arow & 7) << 4);
    const int brow  = nw + l8 + lhb * 8;
    const int bcolh = lb * 8;
    const uint32_t bswz = (uint32_t)((brow & 7) << 4);

    int acc0[4][4][4], accX[4][4][4];
    #pragma unroll
    for (int mi = 0; mi < 4; mi++)
        #pragma unroll
        for (int ni = 0; ni < 4; ni++)
            #pragma unroll
            for (int r = 0; r < 4; r++) { acc0[mi][ni][r] = 0; accX[mi][ni][r] = 0; }

    auto load_tile = [&](int k0, int slot) {
        uint32_t dA = sbase + slot * STAGE_BYTES;
        uint32_t dB = dA + 16384;
        #pragma unroll
        for (int i = 0; i < 4; i++) {
            int j = tid + 256 * i;
            int r = j >> 3, c = j & 7;
            const int8_t* src = (c < 4) ? (pA0 + (size_t)r * K + k0 + c * 16)
                                        : (pA1 + (size_t)r * K + k0 + (c - 4) * 16);
            CP_ASYNC16(dA + r * 128 + ((c ^ (r & 7)) << 4), src);
        }
        #pragma unroll
        for (int i = 0; i < 4; i++) {
            int j = tid + 256 * i;
            int r = j >> 3, c = j & 7;
            const int8_t* src = (c < 4) ? (pB0 + (size_t)r * K + k0 + c * 16)
                                        : (pB1 + (size_t)r * K + k0 + (c - 4) * 16);
            CP_ASYNC16(dB + r * 128 + ((c ^ (r & 7)) << 4), src);
        }
    };

    #pragma unroll
    for (int s = 0; s < STAGES - 1; s++) {       // prologue loads stay in-bounds (k < K)
        load_tile(s * 64, s);
        CP_COMMIT();
    }

    for (int i = 0; i < ntiles; i++) {
        CP_WAIT(STAGES - 2);
        __syncthreads();
        int nx = i + STAGES - 1;
        if (nx < ntiles) {
            load_tile(nx * 64, nx % STAGES);
            CP_COMMIT();
        }
        uint32_t sA_ = sbase + (i % STAGES) * STAGE_BYTES;
        uint32_t sB_ = sA_ + 16384;

        #pragma unroll
        for (int g = 0; g < 2; g++) {
            const int kk = g * 16;
            uint32_t a0f[4][4], a1f[4][4], b0f[4][2], b1f[4][2];
            {
                uint32_t a0_addr = sA_ + (uint32_t)arow * 128
                                 + (((uint32_t)(kk + acolh) * 2) ^ aswz);
                uint32_t a1_addr = sA_ + (uint32_t)arow * 128
                                 + (((uint32_t)(kk + acolh + 32) * 2) ^ aswz);
                #pragma unroll
                for (int mi = 0; mi < 4; mi++) {
                    LDSM4(a0f[mi], a0_addr + mi * (16 * 128));
                    LDSM4(a1f[mi], a1_addr + mi * (16 * 128));
                }
            }
            {
                uint32_t b0_addr = sB_ + (uint32_t)brow * 128
                                 + (((uint32_t)(kk + bcolh) * 2) ^ bswz);
                uint32_t b1_addr = sB_ + (uint32_t)brow * 128
                                 + (((uint32_t)(kk + bcolh + 32) * 2) ^ bswz);
                #pragma unroll
                for (int p = 0; p < 2; p++) {
                    uint32_t t[4];
                    LDSM4(t, b0_addr + p * (16 * 128));
                    b0f[2*p][0] = t[0]; b0f[2*p][1] = t[1];
                    b0f[2*p+1][0] = t[2]; b0f[2*p+1][1] = t[3];
                    LDSM4(t, b1_addr + p * (16 * 128));
                    b1f[2*p][0] = t[0]; b1f[2*p][1] = t[1];
                    b1f[2*p+1][0] = t[2]; b1f[2*p+1][1] = t[3];
                }
            }
            #pragma unroll
            for (int mi = 0; mi < 4; mi++)
                #pragma unroll
                for (int ni = 0; ni < 4; ni++)
                    MMA_S8(acc0[mi][ni], a0f[mi], b0f[ni][0], b0f[ni][1]);  // d0*d0
            #pragma unroll
            for (int mi = 0; mi < 4; mi++)
                #pragma unroll
                for (int ni = 0; ni < 4; ni++)
                    MMA_S8(accX[mi][ni], a0f[mi], b1f[ni][0], b1f[ni][1]);  // d0*d1
            #pragma unroll
            for (int mi = 0; mi < 4; mi++)
                #pragma unroll
                for (int ni = 0; ni < 4; ni++)
                    MMA_S8(accX[mi][ni], a1f[mi], b0f[ni][0], b0f[ni][1]);  // d1*d0
        }
    }
    CP_WAIT(0);

    // ---- epilogue ----
    const float qs = alpha * (1.f / (32512.f * 32512.f));
    float* Cp = Cf + (size_t)bz * sC;
    #pragma unroll
    for (int mi = 0; mi < 4; mi++) {
        int r0 = bm + mw + mi * 16 + lr;
        float sr0 = SAb[r0] * qs, sr1 = SAb[r0 + 8] * qs;
        #pragma unroll
        for (int ni = 0; ni < 4; ni++) {
            int c0 = bn + nw + ni * 8 + lc * 2;
            float sb0 = SBb[c0], sb1 = SBb[c0 + 1];
            float o0 = (65536.f * (float)acc0[mi][ni][0] + 256.f * (float)accX[mi][ni][0]) * sr0 * sb0;
            float o1 = (65536.f * (float)acc0[mi][ni][1] + 256.f * (float)accX[mi][ni][1]) * sr0 * sb1;
            float o2 = (65536.f * (float)acc0[mi][ni][2] + 256.f * (float)accX[mi][ni][2]) * sr1 * sb0;
            float o3 = (65536.f * (float)acc0[mi][ni][3] + 256.f * (float)accX[mi][ni][3]) * sr1 * sb1;
            if (bias) {
                float b0 = bias[c0], b1 = bias[c0 + 1];
                o0 += b0; o1 += b1; o2 += b0; o3 += b1;
            }
            *(float2*)(Cp + (size_t)r0 * N + c0)       = make_float2(o0, o1);
            *(float2*)(Cp + (size_t)(r0 + 8) * N + c0) = make_float2(o2, o3);
        }
    }
}

// ---------------- 6) masked row softmax -> probs digits (scale = 1/s, free) ----------------
__global__ void softmax_kernel() {
    __shared__ float red[8];
    int row = blockIdx.x;
    int b = row >> 11;
    int nc = g_nchunks[b];
    const float* sc = g_scores + (size_t)row * SS;
    int8_t* pd0 = g_p_d0 + (size_t)row * SS;
    int8_t* pd1 = g_p_d1 + (size_t)row * SS;

    const float NEG_INF = __int_as_float(0xff800000);
    float x[8];
    float m = NEG_INF;
    #pragma unroll
    for (int i = 0; i < 8; i++) {
        int c = threadIdx.x + i * 256;
        x[i] = (c < nc) ? sc[c] : NEG_INF;
        m = fmaxf(m, x[i]);
    }
    #pragma unroll
    for (int o = 16; o; o >>= 1) m = fmaxf(m, __shfl_xor_sync(0xffffffffu, m, o));
    if ((threadIdx.x & 31) == 0) red[threadIdx.x >> 5] = m;
    __syncthreads();
    m = red[0];
    #pragma unroll
    for (int i = 1; i < 8; i++) m = fmaxf(m, red[i]);
    __syncthreads();

    float s = 0.f;
    #pragma unroll
    for (int i = 0; i < 8; i++) {
        int c = threadIdx.x + i * 256;
        x[i] = (c < nc) ? expf(x[i] - m) : 0.f;   // in [0,1], max is exactly 1
        s += x[i];
    }
    #pragma unroll
    for (int o = 16; o; o >>= 1) s += __shfl_xor_sync(0xffffffffu, s, o);
    if ((threadIdx.x & 31) == 0) red[threadIdx.x >> 5] = s;
    __syncthreads();
    s = 0.f;
    #pragma unroll
    for (int i = 0; i < 8; i++) s += red[i];
    float inv = 1.f / s;
    if (threadIdx.x == 0) g_SP[row] = inv;        // p = inv * (X/32512)

    #pragma unroll
    for (int i = 0; i < 8; i++) {
        int c = threadIdx.x + i * 256;
        int8_t q0, q1; q2dig(x[i], 32512.f, q0, q1);
        pd0[c] = q0; pd1[c] = q1;
    }
}

// ---------------- host side ----------------
static void launch_gemm(const int8_t* Ad0, const int8_t* Ad1,
                        const int8_t* Bd0, const int8_t* Bd1,
                        const float* SA, const float* SB,
                        const float* bias, float* Cf,
                        int M, int N, int K,
                        long long sA, long long sB, long long sC,
                        long long sSA, long long sSB, int batch, float alpha,
                        const int* ncs, int lim) {
    constexpr int SMEM = 4 * 32768;
    dim3 grid(N / 128, M / 128, batch), block(256);
    cudaFuncSetAttribute(gemm_s8, cudaFuncAttributeMaxDynamicSharedMemorySize, SMEM);
    gemm_s8<<<grid, block, SMEM>>>(Ad0, Ad1, Bd0, Bd1, SA, SB, bias, Cf,
                                   M, N, K, sA, sB, sC, sSA, sSB, alpha, ncs, lim);
}

extern "C" void kernel_launch(void* const* d_in, const int* in_sizes, int n_in,
                              void* d_out, int out_size) {
    (void)in_sizes; (void)n_in; (void)out_size;
    const float* h    = (const float*)d_in[0];
    const float* Wlab = (const float*)d_in[1];
    const float* blab = (const float*)d_in[2];
    const float* Wq   = (const float*)d_in[3];
    const float* bq   = (const float*)d_in[4];
    const float* Wk   = (const float*)d_in[5];
    const float* bk   = (const float*)d_in[6];
    const float* Wv   = (const float*)d_in[7];
    const float* bv   = (const float*)d_in[8];
    const float* Wo   = (const float*)d_in[9];
    const float* bo   = (const float*)d_in[10];
    float* out = (float*)d_out;

    int8_t *hd0,*hd1,*ced0,*ced1,*wqd0,*wqd1,*wkd0,*wkd1,*wvd0,*wvd1,*wod0,*wod1;
    int8_t *qd0,*qd1,*kd0,*kd1,*vTd0,*vTd1,*pd0,*pd1,*atd0,*atd1;
    float *Sh,*Sce,*Swq,*Swk,*Swv,*Swo,*Sq,*Sk,*SvT,*SP,*Sat;
    float *qf,*kf,*vf,*vTf,*atf,*scb,*cpart;
    int *ncs;
    cudaGetSymbolAddress((void**)&hd0, g_h_d0);   cudaGetSymbolAddress((void**)&hd1, g_h_d1);
    cudaGetSymbolAddress((void**)&ced0, g_ce_d0); cudaGetSymbolAddress((void**)&ced1, g_ce_d1);
    cudaGetSymbolAddress((void**)&wqd0, g_wq_d0); cudaGetSymbolAddress((void**)&wqd1, g_wq_d1);
    cudaGetSymbolAddress((void**)&wkd0, g_wk_d0); cudaGetSymbolAddress((void**)&wkd1, g_wk_d1);
    cudaGetSymbolAddress((void**)&wvd0, g_wv_d0); cudaGetSymbolAddress((void**)&wvd1, g_wv_d1);
    cudaGetSymbolAddress((void**)&wod0, g_wo_d0); cudaGetSymbolAddress((void**)&wod1, g_wo_d1);
    cudaGetSymbolAddress((void**)&qd0, g_q_d0);   cudaGetSymbolAddress((void**)&qd1, g_q_d1);
    cudaGetSymbolAddress((void**)&kd0, g_k_d0);   cudaGetSymbolAddress((void**)&kd1, g_k_d1);
    cudaGetSymbolAddress((void**)&vTd0, g_vT_d0); cudaGetSymbolAddress((void**)&vTd1, g_vT_d1);
    cudaGetSymbolAddress((void**)&pd0, g_p_d0);   cudaGetSymbolAddress((void**)&pd1, g_p_d1);
    cudaGetSymbolAddress((void**)&atd0, g_at_d0); cudaGetSymbolAddress((void**)&atd1, g_at_d1);
    cudaGetSymbolAddress((void**)&Sh, g_Sh);   cudaGetSymbolAddress((void**)&Sce, g_Sce);
    cudaGetSymbolAddress((void**)&Swq, g_Swq); cudaGetSymbolAddress((void**)&Swk, g_Swk);
    cudaGetSymbolAddress((void**)&Swv, g_Swv); cudaGetSymbolAddress((void**)&Swo, g_Swo);
    cudaGetSymbolAddress((void**)&Sq, g_Sq);   cudaGetSymbolAddress((void**)&Sk, g_Sk);
    cudaGetSymbolAddress((void**)&SvT, g_SvT); cudaGetSymbolAddress((void**)&SP, g_SP);
    cudaGetSymbolAddress((void**)&Sat, g_Sat);
    cudaGetSymbolAddress((void**)&qf, g_qf);   cudaGetSymbolAddress((void**)&kf, g_kf);
    cudaGetSymbolAddress((void**)&vf, g_vf);   cudaGetSymbolAddress((void**)&vTf, g_vTf);
    cudaGetSymbolAddress((void**)&atf, g_atf); cudaGetSymbolAddress((void**)&scb, g_scores);
    cudaGetSymbolAddress((void**)&cpart, g_cmax_part);
    cudaGetSymbolAddress((void**)&ncs, g_nchunks);

    const int M = BB * SS;                        // 16384
    const long long sQ = (long long)SS * DD;
    const long long sS = (long long)SS * SS;
    const long long sV = (long long)DD * SS;

    // prep: labels/chunks, quantize h + weights, chunk means (quantized in-kernel)
    label_kernel<<<M / 8, 256>>>(h, Wlab, blab);
    scan_kernel<<<BB, 256>>>();
    quant_rows1k_kernel<<<M / 8, 256>>>(h, hd0, hd1, Sh);
    colmax4_part_kernel<<<dim3(4, 16, 4), 256>>>(Wq, Wk, Wv, Wo, cpart);
    colmax4_reduce_kernel<<<dim3(4, 4), 256>>>(cpart, Swq, Swk, Swv, Swo);
    wtransq4_kernel<<<dim3(32, 32, 4), dim3(32, 8)>>>(Wq, Wk, Wv, Wo,
                                                      Swq, Swk, Swv, Swo,
                                                      wqd0, wqd1, wkd0, wkd1,
                                                      wvd0, wvd1, wod0, wod1);
    chunk_meanq_kernel<<<dim3(SS, BB), 256>>>(h);

    // projections: int8 GEMMs -> fp32, then row-quantize
    launch_gemm(hd0, hd1, wqd0, wqd1, Sh, Swq, bq, qf, M, DD, DD, 0,0,0, 0,0, 1, 1.f,
                ncs, 0);
    launch_gemm(ced0, ced1, wkd0, wkd1, Sce, Swk, bk, kf, M, DD, DD, 0,0,0, 0,0, 1, 1.f,
                ncs, 1);                                   // skip all-padding chunk rows
    launch_gemm(ced0, ced1, wvd0, wvd1, Sce, Swv, bv, vf, M, DD, DD, 0,0,0, 0,0, 1, 1.f,
                ncs, 1);
    quant_rows1k_kernel<<<M / 8, 256>>>(qf, qd0, qd1, Sq);
    quant_rows1k_kernel<<<M / 8, 256>>>(kf, kd0, kd1, Sk);
    vtransf_kernel<<<dim3(DD / 32, SS / 32, BB), dim3(32, 8)>>>();
    quant_rows_kernel<<<(BB * DD) / 8, 256>>>(vTf, SS, vTd0, vTd1, SvT);

    // scores[b] = (q[b] @ k[b]^T) / 32 -> fp32 (masked N blocks skipped)
    launch_gemm(qd0, qd1, kd0, kd1, Sq, Sk, nullptr, scb,
                SS, SS, DD, sQ, sQ, sS, SS, SS, BB, 0.03125f, ncs, 2);

    softmax_kernel<<<M, 256>>>();   // -> probs digits + SP (masked cols exactly 0)

    // attended[b] = probs[b] @ vT[b]^T -> fp32 (zero-probs K tail truncated)
    launch_gemm(pd0, pd1, vTd0, vTd1, SP, SvT, nullptr, atf,
                SS, DD, SS, sS, sV, sQ, SS, DD, BB, 1.f, ncs, 4);
    quant_rows1k_kernel<<<M / 8, 256>>>(atf, atd0, atd1, Sat);

    // out = att @ Wo^T + bo -> fp32 d_out
    launch_gemm(atd0, atd1, wod0, wod1, Sat, Swo, bo, out, M, DD, DD, 0,0,0, 0,0, 1, 1.f,
                ncs, 0);
}